// round 8
// baseline (speedup 1.0000x reference)
#include <cuda_runtime.h>
#include <cuda_fp16.h>

#define B_TOT 32768
typedef unsigned int uint;

// ===================== device scratch (tiled+swizzled planes) =====================
// tile = 128 rows x 128 bytes (64 halves), SW128-swizzled, 16KB. B-tiles for N=256 are 256 rows (32KB).
__device__ __half g_spW2T[2*8192],  g_spW3T[2*8192];          // [ch][128x64]
__device__ __half g_vpW1T[8*8192],  g_vpW2T[2*8192];          // [ch][128x64]
__device__ __half g_joinT[(size_t)2*10*16384];                // [nb][ch][256x64]
__device__ __half g_cW1T[(size_t)4*8*16384];                  // [e][ch][256x64]
__device__ __half g_cW2T[(size_t)4*4*16384];                  // [e][ch][256x64]
__device__ __half g_pi_h[(size_t)256*8*8192], g_pi_l[(size_t)256*8*8192];   // [mb][ch][tile]
__device__ __half g_v_h [(size_t)256*2*8192], g_v_l [(size_t)256*2*8192];   // [mb][ch][tile]
__device__ __half g_jo_h[(size_t)256*8*8192], g_jo_l[(size_t)256*8*8192];   // [mb][ch][tile]
__device__ int g_idx[B_TOT + 512];
__device__ int g_cnt[4], g_fill[4], g_seg[5];

// ===================== primitives =====================
__device__ __forceinline__ uint smem_u32(const void* p) {
    uint a;
    asm("{ .reg .u64 t; cvta.to.shared.u64 t, %1; cvt.u32.u64 %0, t; }" : "=r"(a) : "l"(p));
    return a;
}
__device__ __forceinline__ uint swzoff(int r, int cbyte) {   // within-tile byte offset
    return (uint)(r * 128 + (cbyte ^ ((r & 7) << 4)));
}
__device__ __forceinline__ void ldm4(uint f[4], uint a) {
    asm volatile("ldmatrix.sync.aligned.m8n8.x4.shared.b16 {%0,%1,%2,%3}, [%4];"
        : "=r"(f[0]), "=r"(f[1]), "=r"(f[2]), "=r"(f[3]) : "r"(a));
}
__device__ __forceinline__ void mma_fp16(float c[4], const uint a[4], const uint b[2]) {
    asm volatile(
        "mma.sync.aligned.m16n8k16.row.col.f32.f16.f16.f32 "
        "{%0,%1,%2,%3}, {%4,%5,%6,%7}, {%8,%9}, {%0,%1,%2,%3};"
        : "+f"(c[0]), "+f"(c[1]), "+f"(c[2]), "+f"(c[3])
        : "r"(a[0]), "r"(a[1]), "r"(a[2]), "r"(a[3]), "r"(b[0]), "r"(b[1]));
}
__device__ __forceinline__ void split2h(float a, float b, uint& ph, uint& pl) {
    __half h0 = __float2half_rn(a), h1 = __float2half_rn(b);
    float r0 = a - __half2float(h0), r1 = b - __half2float(h1);
    __half l0 = __float2half_rn(r0), l1 = __float2half_rn(r1);
    ph = (uint)__half_as_ushort(h0) | ((uint)__half_as_ushort(h1) << 16);
    pl = (uint)__half_as_ushort(l0) | ((uint)__half_as_ushort(l1) << 16);
}
__device__ __forceinline__ void cpa16(uint d, const void* s) {
    asm volatile("cp.async.cg.shared.global [%0], [%1], 16;" :: "r"(d), "l"(s));
}
#define CPA_COMMIT() asm volatile("cp.async.commit_group;" ::: "memory")
#define CPA_WAIT0()  asm volatile("cp.async.wait_group 0;" ::: "memory")
#define CPA_WAIT1()  asm volatile("cp.async.wait_group 1;" ::: "memory")

__device__ __forceinline__ void bulk_g2s(uint dst, const void* src, uint bytes, uint mbar) {
    asm volatile("cp.async.bulk.shared::cluster.global.mbarrier::complete_tx::bytes [%0], [%1], %2, [%3];"
        :: "r"(dst), "l"(src), "r"(bytes), "r"(mbar) : "memory");
}
#define MBAR_INIT(a, c) asm volatile("mbarrier.init.shared.b64 [%0], %1;" :: "r"(a), "r"(c) : "memory")
#define MBAR_EXPECT(a, tx) asm volatile("mbarrier.arrive.expect_tx.shared.b64 _, [%0], %1;" :: "r"(a), "r"(tx) : "memory")
#define MBAR_WAIT(mbar_a, par) do { \
    uint _m = (mbar_a); uint _p = (uint)(par); uint _d; \
    asm volatile("{ .reg .pred p; mbarrier.try_wait.parity.acquire.cta.shared::cta.b64 p, [%1], %2; selp.b32 %0, 1, 0, p; }" \
        : "=r"(_d) : "r"(_m), "r"(_p) : "memory"); \
    if (!_d) { \
        asm volatile("{ .reg .pred P1;\nWL_%=:\n mbarrier.try_wait.parity.acquire.cta.shared::cta.b64 P1, [%0], %1, 0x989680;\n @P1 bra.uni WD_%=;\n bra.uni WL_%=;\nWD_%=:\n}" \
            :: "r"(_m), "r"(_p) : "memory"); \
    } \
} while (0)

// ===================== gemm: warp tile 16 x (NT*8), 2-pass (A hi/lo fp16) =====================
// A planes: (M/128) x 16KB tiles contiguous; B: single tile (128 or 256 rows), swizzled.
template <int NT>
__device__ __forceinline__ void gemm_swz(float (&acc)[NT][4], uint Ah, uint Al, uint Bs, int wm, int wn)
{
    const int lane = threadIdx.x & 31;
    const int ra = (lane & 15) + wm;
    const uint abase = (uint)(ra >> 7) * 16384u + (uint)(ra & 127) * 128u;
    const uint Ath = Ah + abase, Atl = Al + abase;
    const uint ax = (uint)((ra & 7) << 4);
    const int ua = lane >> 4;
    const int rb = (lane & 7) + ((lane >> 4) << 3) + wn;
    const uint Bt = Bs + (uint)rb * 128u;
    const uint bx2 = (uint)((rb & 7) << 4);
    const int ub = (lane >> 3) & 1;
#pragma unroll
    for (int s = 0; s < 4; s++) {
        uint ca = ((uint)((s * 2 + ua) * 16)) ^ ax;
        uint ah4[4], al4[4];
        ldm4(ah4, Ath + ca);
        ldm4(al4, Atl + ca);
        uint cbb = ((uint)((s * 2 + ub) * 16)) ^ bx2;
#pragma unroll
        for (int p = 0; p < NT / 2; p++) {
            uint b4[4];
            ldm4(b4, Bt + (uint)(p * 2048) + cbb);
            mma_fp16(acc[2*p],   ah4, b4);
            mma_fp16(acc[2*p],   al4, b4);
            mma_fp16(acc[2*p+1], ah4, b4 + 2);
            mma_fp16(acc[2*p+1], al4, b4 + 2);
        }
    }
}
template <int NT>
__device__ __forceinline__ void acc_zero(float (&acc)[NT][4]) {
#pragma unroll
    for (int n = 0; n < NT; n++)
#pragma unroll
    for (int q = 0; q < 4; q++) acc[n][q] = 0.f;
}

// ===================== epilogue: bias(+relu) -> split -> swizzled tiles (smem or global) =====================
template <int NT>
__device__ __forceinline__ void epi_tiled(const float (&acc)[NT][4],
    char* dh, char* dl, const float* bias, int cb,
    size_t tsMb, size_t tsCh, int wm, int wn, bool relu)
{
    int lane = threadIdx.x & 31;
    int rr = wm + (lane >> 2), cc = wn + (lane & 3) * 2;
#pragma unroll
    for (int nt = 0; nt < NT; nt++)
#pragma unroll
    for (int h = 0; h < 2; h++) {
        int r = rr + h * 8, c = cc + nt * 8;
        float v0 = acc[nt][h*2]   + __ldg(bias + cb + c);
        float v1 = acc[nt][h*2+1] + __ldg(bias + cb + c + 1);
        if (relu) { v0 = fmaxf(v0, 0.f); v1 = fmaxf(v1, 0.f); }
        uint ph, pl; split2h(v0, v1, ph, pl);
        size_t off = (size_t)(r >> 7) * tsMb + (size_t)(c >> 6) * tsCh
                   + swzoff(r & 127, (c & 63) * 2);
        *(uint*)(dh + off) = ph;
        *(uint*)(dl + off) = pl;
    }
}

// ===================== weight prep (transpose + fp16 + tile/swizzle) =====================
__global__ void k_prep(const float* spW2, const float* spW3, const float* vpW1, const float* vpW2,
                       const float* jW, const float* cW1, const float* cW2) {
    int i = blockIdx.x * 256 + threadIdx.x;
    float x; char* base; size_t off;
    if (i < 16384) {
        int l = i; int n = l >> 7, k = l & 127; x = spW2[k*128+n];
        base = (char*)g_spW2T; off = (size_t)(k >> 6) * 16384 + swzoff(n, (k & 63) * 2);
    } else if (i < 32768) {
        int l = i - 16384; int n = l >> 7, k = l & 127; x = spW3[k*128+n];
        base = (char*)g_spW3T; off = (size_t)(k >> 6) * 16384 + swzoff(n, (k & 63) * 2);
    } else if (i < 98304) {
        int l = i - 32768; int n = l >> 9, k = l & 511; x = vpW1[k*128+n];
        base = (char*)g_vpW1T; off = (size_t)(k >> 6) * 16384 + swzoff(n, (k & 63) * 2);
    } else if (i < 114688) {
        int l = i - 98304; int n = l >> 7, k = l & 127; x = vpW2[k*128+n];
        base = (char*)g_vpW2T; off = (size_t)(k >> 6) * 16384 + swzoff(n, (k & 63) * 2);
    } else if (i < 442368) {
        int l = i - 114688; int n = l / 640, k = l - n * 640; x = jW[(size_t)k*512+n];
        int nb = n >> 8, nl = n & 255;
        base = (char*)g_joinT; off = ((size_t)nb * 10 + (k >> 6)) * 32768 + swzoff(nl, (k & 63) * 2);
    } else if (i < 966656) {
        int l = i - 442368; int e = l >> 17, rm = l & 131071; int n = rm >> 9, k = rm & 511;
        x = cW1[(size_t)e*131072 + (size_t)k*256 + n];
        base = (char*)g_cW1T; off = ((size_t)e * 8 + (k >> 6)) * 32768 + swzoff(n, (k & 63) * 2);
    } else if (i < 1228800) {
        int l = i - 966656; int e = l >> 16, rm = l & 65535; int n = rm >> 8, k = rm & 255;
        x = cW2[(size_t)e*65536 + (size_t)k*256 + n];
        base = (char*)g_cW2T; off = ((size_t)e * 4 + (k >> 6)) * 32768 + swzoff(n, (k & 63) * 2);
    } else return;
    *(__half*)(base + off) = __float2half_rn(x);
}

// p_i -> tiled swizzled hi/lo planes. One 16B unit per thread.
__global__ void k_pis(const float* __restrict__ p) {
    int idx = blockIdx.x * 256 + threadIdx.x;           // [0, 2097152)
    int m = idx >> 6, u = idx & 63;
    int ch = u >> 3, ui = u & 7;
    const float* s = p + (size_t)m * 512 + u * 8;
    float4 f0 = *(const float4*)s;
    float4 f1 = *(const float4*)(s + 4);
    float xs[8] = {f0.x, f0.y, f0.z, f0.w, f1.x, f1.y, f1.z, f1.w};
    uint wh[4], wl[4];
#pragma unroll
    for (int q = 0; q < 4; q++) split2h(xs[2*q], xs[2*q+1], wh[q], wl[q]);
    size_t off = ((size_t)(m >> 7) * 8 + ch) * 16384 + swzoff(m & 127, ui * 16);
    *(uint4*)((char*)g_pi_h + off) = make_uint4(wh[0], wh[1], wh[2], wh[3]);
    *(uint4*)((char*)g_pi_l + off) = make_uint4(wl[0], wl[1], wl[2], wl[3]);
}

// ===================== routing =====================
__global__ void k_reset() { if (threadIdx.x < 4) { g_cnt[threadIdx.x] = 0; g_fill[threadIdx.x] = 0; } }
__global__ void k_count(const int* __restrict__ cmd) {
    __shared__ int h[4];
    int tid = threadIdx.x;
    if (tid < 4) h[tid] = 0;
    __syncthreads();
    int i = blockIdx.x * 256 + tid;
    if (i < B_TOT) atomicAdd(&h[cmd[i] & 3], 1);
    __syncthreads();
    if (tid < 4) atomicAdd(&g_cnt[tid], h[tid]);
}
__global__ void k_seg() {
    if (threadIdx.x == 0) {
        int off = 0;
        for (int e = 0; e < 4; e++) { g_seg[e] = off; off += (g_cnt[e] + 127) & ~127; }
        g_seg[4] = off;
    }
}
__global__ void k_scatter(const int* __restrict__ cmd) {
    __shared__ int h[4], base[4];
    int tid = threadIdx.x;
    if (tid < 4) h[tid] = 0;
    __syncthreads();
    int i = blockIdx.x * 256 + tid;
    int e = 0, loc = 0;
    if (i < B_TOT) { e = cmd[i] & 3; loc = atomicAdd(&h[e], 1); }
    __syncthreads();
    if (tid < 4) base[tid] = atomicAdd(&g_fill[tid], h[tid]);
    __syncthreads();
    if (i < B_TOT) g_idx[g_seg[e] + base[e] + loc] = i;
}

// ===================== k_sp: 1 -> 128 -> 128 -> 128 (M=128, N=128) =====================
// smem: A1 [2ch x (hi16K+lo16K)] @0, A2 @65536, W @131072 (32KB), ss @163840, mbar @164352
#define SP_SMEM 164384

__global__ void __launch_bounds__(512) k_sp(
    const float* __restrict__ speed,
    const float* __restrict__ W1, const float* __restrict__ b1,
    const float* __restrict__ b2, const float* __restrict__ b3)
{
    extern __shared__ char sm[];
    uint sb = smem_u32(sm);
    int tid = threadIdx.x, wid = tid >> 5;
    int wm = (wid & 7) * 16, wn = (wid >> 3) * 64;
    size_t m0 = (size_t)blockIdx.x * 128;
    uint mbar = sb + 164352;
    float* ss = (float*)(sm + 163840);
    if (tid == 0) MBAR_INIT(mbar, 1);
    if (tid < 128) ss[tid] = speed[m0 + tid];
    __syncthreads();
    if (tid == 0) { MBAR_EXPECT(mbar, 32768); bulk_g2s(sb + 131072, g_spW2T, 32768, mbar); }

    // h1 -> A1 swizzled chunk pairs
    for (int u = tid; u < 8192; u += 512) {
        int r = u >> 6, c = (u & 63) * 2;
        float sv = ss[r];
        float v0 = fmaxf(fmaf(sv, __ldg(W1 + c),     __ldg(b1 + c)),     0.f);
        float v1 = fmaxf(fmaf(sv, __ldg(W1 + c + 1), __ldg(b1 + c + 1)), 0.f);
        uint ph, pl; split2h(v0, v1, ph, pl);
        uint off = (uint)(c >> 6) * 32768 + swzoff(r, (c & 63) * 2);
        *(uint*)(sm + off) = ph;
        *(uint*)(sm + 16384 + off) = pl;
    }
    __syncthreads();
    MBAR_WAIT(mbar, 0);

    float acc[8][4];
    acc_zero(acc);
    gemm_swz<8>(acc, sb + 0,     sb + 16384, sb + 131072,         wm, wn);
    gemm_swz<8>(acc, sb + 32768, sb + 49152, sb + 131072 + 16384, wm, wn);
    __syncthreads();
    if (tid == 0) { MBAR_EXPECT(mbar, 32768); bulk_g2s(sb + 131072, g_spW3T, 32768, mbar); }
    epi_tiled<8>(acc, sm + 65536, sm + 65536 + 16384, b2, 0, 0, 32768, wm, wn, true);
    __syncthreads();
    MBAR_WAIT(mbar, 1);

    acc_zero(acc);
    gemm_swz<8>(acc, sb + 65536,         sb + 65536 + 16384, sb + 131072,         wm, wn);
    gemm_swz<8>(acc, sb + 65536 + 32768, sb + 65536 + 49152, sb + 131072 + 16384, wm, wn);
    epi_tiled<8>(acc, (char*)g_v_h + (size_t)blockIdx.x * 2 * 16384,
                      (char*)g_v_l + (size_t)blockIdx.x * 2 * 16384,
                 b3, 0, 0, 16384, wm, wn, false);
}

// ===================== k_join: M=256, N=256, 1024 threads, 2-stage bulk pipeline =====================
// stage: A_h 2 tiles @0, A_l @32768, B(256x64) @65536; stage size 98304; 2 stages; mbars @196608
#define JSTG 98304u
#define JOIN_SMEM 196640

__global__ void __launch_bounds__(1024) k_join(const float* __restrict__ jb)
{
    extern __shared__ char sm[];
    uint sb = smem_u32(sm);
    int tid = threadIdx.x, wid = tid >> 5;
    int wm = (wid & 15) * 16, wn = (wid >> 4) * 128;
    int bx = blockIdx.x, by = blockIdx.y;
    int N0 = by * 256;
    uint mb[2] = {sb + 196608, sb + 196616};
    if (tid == 0) { MBAR_INIT(mb[0], 1); MBAR_INIT(mb[1], 1); }
    __syncthreads();

#define J_ISSUE(c, s) do { \
    uint d = sb + (uint)(s) * JSTG; uint m_ = mb[s]; \
    MBAR_EXPECT(m_, 98304); \
    if ((c) < 8) { \
        size_t t0 = ((size_t)(2*bx)   * 8 + (c)) * 16384; \
        size_t t1 = ((size_t)(2*bx+1) * 8 + (c)) * 16384; \
        bulk_g2s(d,         (char*)g_pi_h + t0, 16384, m_); \
        bulk_g2s(d + 16384, (char*)g_pi_h + t1, 16384, m_); \
        bulk_g2s(d + 32768, (char*)g_pi_l + t0, 16384, m_); \
        bulk_g2s(d + 49152, (char*)g_pi_l + t1, 16384, m_); \
    } else { \
        size_t t0 = ((size_t)(2*bx)   * 2 + ((c)-8)) * 16384; \
        size_t t1 = ((size_t)(2*bx+1) * 2 + ((c)-8)) * 16384; \
        bulk_g2s(d,         (char*)g_v_h + t0, 16384, m_); \
        bulk_g2s(d + 16384, (char*)g_v_h + t1, 16384, m_); \
        bulk_g2s(d + 32768, (char*)g_v_l + t0, 16384, m_); \
        bulk_g2s(d + 49152, (char*)g_v_l + t1, 16384, m_); \
    } \
    bulk_g2s(d + 65536, (char*)g_joinT + ((size_t)by * 10 + (c)) * 32768, 32768, m_); \
} while (0)

    float acc[16][4];
    acc_zero(acc);
    if (tid == 0) { J_ISSUE(0, 0); J_ISSUE(1, 1); }
    int par[2] = {0, 0};
    for (int c = 0; c < 10; c++) {
        int s = c & 1;
        MBAR_WAIT(mb[s], par[s]); par[s] ^= 1;
        gemm_swz<16>(acc, sb + s*JSTG, sb + s*JSTG + 32768, sb + s*JSTG + 65536, wm, wn);
        __syncthreads();
        if (tid == 0 && c + 2 < 10) J_ISSUE(c + 2, s);
    }
#undef J_ISSUE
    epi_tiled<16>(acc,
        (char*)g_jo_h + ((size_t)(2*bx) * 8 + (N0 >> 6)) * 16384,
        (char*)g_jo_l + ((size_t)(2*bx) * 8 + (N0 >> 6)) * 16384,
        jb, N0, (size_t)8 * 16384, 16384, wm, wn, false);
}

// ===================== k_vp: 512 -> 128 -> 128 -> 1 (M=128, N=128) =====================
// stages: s*49152: A_h@0, A_l@16384, B@32768. A2 @98304 (2ch x 32768). W2 @163840. sv @196608. mbars @197120.
#define VSTG 49152u
#define VP_SMEM 197152

__global__ void __launch_bounds__(512) k_vp(
    const float* __restrict__ b1, const float* __restrict__ b2,
    const float* __restrict__ W3, const float* __restrict__ b3,
    float* __restrict__ out)
{
    extern __shared__ char sm[];
    uint sb = smem_u32(sm);
    int tid = threadIdx.x, wid = tid >> 5;
    int wm = (wid & 7) * 16, wn = (wid >> 3) * 64;
    int bx = blockIdx.x;
    size_t m0 = (size_t)bx * 128;
    float* sv = (float*)(sm + 196608);
    uint mb[2] = {sb + 197120, sb + 197128};
    if (tid == 0) { MBAR_INIT(mb[0], 1); MBAR_INIT(mb[1], 1); }
    if (tid < 128) sv[tid] = 0.f;
    __syncthreads();

#define V_ISSUE(c, s) do { \
    uint d = sb + (uint)(s) * VSTG; uint m_ = mb[s]; \
    MBAR_EXPECT(m_, 49152); \
    size_t t = ((size_t)bx * 8 + (c)) * 16384; \
    bulk_g2s(d,         (char*)g_pi_h + t, 16384, m_); \
    bulk_g2s(d + 16384, (char*)g_pi_l + t, 16384, m_); \
    bulk_g2s(d + 32768, (char*)g_vpW1T + (size_t)(c) * 16384, 16384, m_); \
} while (0)

    float acc[8][4];
    acc_zero(acc);
    if (tid == 0) { V_ISSUE(0, 0); V_ISSUE(1, 1); }
    int par[2] = {0, 0};
    for (int c = 0; c < 8; c++) {
        int s = c & 1;
        MBAR_WAIT(mb[s], par[s]); par[s] ^= 1;
        gemm_swz<8>(acc, sb + s*VSTG, sb + s*VSTG + 16384, sb + s*VSTG + 32768, wm, wn);
        __syncthreads();
        if (tid == 0 && c + 2 < 8) V_ISSUE(c + 2, s);
    }
#undef V_ISSUE
    // layer2: A2 in smem, W2 bulk
    if (tid == 0) { MBAR_EXPECT(mb[0], 32768); bulk_g2s(sb + 163840, g_vpW2T, 32768, mb[0]); }
    epi_tiled<8>(acc, sm + 98304, sm + 98304 + 16384, b1, 0, 0, 32768, wm, wn, true);
    __syncthreads();
    MBAR_WAIT(mb[0], par[0]); par[0] ^= 1;

    acc_zero(acc);
    gemm_swz<8>(acc, sb + 98304,         sb + 98304 + 16384, sb + 163840,         wm, wn);
    gemm_swz<8>(acc, sb + 98304 + 32768, sb + 98304 + 49152, sb + 163840 + 16384, wm, wn);

    // layer3: partial dot, quad-reduce, smem accumulate
    {
        int lane = tid & 31;
#pragma unroll
        for (int h = 0; h < 2; h++) {
            int r = wm + h * 8 + (lane >> 2);
            float s = 0.f;
#pragma unroll
            for (int nt = 0; nt < 8; nt++) {
                int c = wn + nt * 8 + (lane & 3) * 2;
                float v0 = fmaxf(acc[nt][h*2]   + __ldg(b2 + c),     0.f);
                float v1 = fmaxf(acc[nt][h*2+1] + __ldg(b2 + c + 1), 0.f);
                s += v0 * __ldg(W3 + c) + v1 * __ldg(W3 + c + 1);
            }
            s += __shfl_xor_sync(0xFFFFFFFF, s, 1);
            s += __shfl_xor_sync(0xFFFFFFFF, s, 2);
            if ((lane & 3) == 0) atomicAdd(&sv[r], s);
        }
    }
    __syncthreads();
    if (tid < 128) out[m0 + tid] = sv[tid] + __ldg(b3);
}

// ===================== k_ctrl: routed 512 -> 256 -> 256 -> 3 (M=128, N=256) =====================
// L1 stages: s*65536: A_h@0 (cpa gather), A_l@16384, B@32768 (bulk 32KB). A2 reuses @0 (4ch x 32768).
// L2 B stages @131072 + s*32768. ridx @196608, sact @197120, mbars @198656.
#define CTRL_SMEM 198688

__global__ void __launch_bounds__(512) k_ctrl(
    const float* __restrict__ b1, const float* __restrict__ b2,
    const float* __restrict__ W3, const float* __restrict__ b3,
    float* __restrict__ out)
{
    int p0 = blockIdx.x * 128;
    int s1 = g_seg[1], s2 = g_seg[2], s3 = g_seg[3], s4 = g_seg[4];
    if (p0 >= s4) return;
    int e, segb;
    if (p0 < s1)      { e = 0; segb = 0; }
    else if (p0 < s2) { e = 1; segb = s1; }
    else if (p0 < s3) { e = 2; segb = s2; }
    else              { e = 3; segb = s3; }
    int cnt = g_cnt[e];

    extern __shared__ char sm[];
    uint sb = smem_u32(sm);
    int tid = threadIdx.x, wid = tid >> 5;
    int wm = (wid & 7) * 16, wn = (wid >> 3) * 128;
    int* ridx = (int*)(sm + 196608);
    float* sact = (float*)(sm + 197120);
    uint mb[2] = {sb + 198656, sb + 198664};
    if (tid == 0) { MBAR_INIT(mb[0], 1); MBAR_INIT(mb[1], 1); }
    if (tid < 128) {
        int local = p0 - segb + tid;
        ridx[tid] = (local < cnt) ? g_idx[p0 + tid] : -1;
        sact[tid] = 0.f; sact[128 + tid] = 0.f; sact[256 + tid] = 0.f;
    }
    __syncthreads();

    const float* b1e = b1 + e * 256;
    const float* b2e = b2 + e * 256;
    const float* w3e = W3 + e * 768;

    // L1 stage issue: tid0 bulk B + ALL threads gather A via cp.async
#define C1_ISSUE(c, s) do { \
    uint d = sb + (uint)(s) * 65536u; \
    if (tid == 0) { \
        MBAR_EXPECT(mb[s], 32768); \
        bulk_g2s(d + 32768, (char*)g_cW1T + ((size_t)e * 8 + (c)) * 32768, 32768, mb[s]); \
    } \
    for (int u = tid; u < 2048; u += 512) { \
        int pl_ = u >> 10, rem = u & 1023, rl = rem >> 3, un = rem & 7; \
        int src = ridx[rl]; if (src < 0) src = 0; \
        size_t so = ((size_t)(src >> 7) * 8 + (c)) * 16384 \
                  + (size_t)((src & 127) * 128 + ((un * 16) ^ ((src & 7) << 4))); \
        uint dd = d + (uint)pl_ * 16384u + swzoff(rl, un * 16); \
        cpa16(dd, (pl_ ? (char*)g_jo_l : (char*)g_jo_h) + so); \
    } \
    CPA_COMMIT(); \
} while (0)

    float acc[16][4];
    acc_zero(acc);
    C1_ISSUE(0, 0); C1_ISSUE(1, 1);
    int par[2] = {0, 0};
    for (int c = 0; c < 8; c++) {
        int s = c & 1;
        if (c < 7) CPA_WAIT1(); else CPA_WAIT0();
        MBAR_WAIT(mb[s], par[s]); par[s] ^= 1;
        __syncthreads();
        gemm_swz<16>(acc, sb + s*65536u, sb + s*65536u + 16384, sb + s*65536u + 32768, wm, wn);
        __syncthreads();
        if (c + 2 < 8) C1_ISSUE(c + 2, s);
    }
#undef C1_ISSUE

    // h -> A2 smem tiles (L1 stages drained)
    epi_tiled<16>(acc, sm, sm + 16384, b1e, 0, 0, 32768, wm, wn, true);
    __syncthreads();

    // L2: A2 smem, B bulk 2-stage
#define C2_ISSUE(c, s) do { \
    if (tid == 0) { \
        MBAR_EXPECT(mb[s], 32768); \
        bulk_g2s(sb + 131072u + (uint)(s) * 32768u, \
                 (char*)g_cW2T + ((size_t)e * 4 + (c)) * 32768, 32768, mb[s]); \
    } \
} while (0)
    acc_zero(acc);
    C2_ISSUE(0, 0); C2_ISSUE(1, 1);
    for (int c = 0; c < 4; c++) {
        int s = c & 1;
        MBAR_WAIT(mb[s], par[s]); par[s] ^= 1;
        gemm_swz<16>(acc, sb + (uint)c * 32768u, sb + (uint)c * 32768u + 16384,
                     sb + 131072u + (uint)s * 32768u, wm, wn);
        __syncthreads();
        if (c + 2 < 4) C2_ISSUE(c + 2, s);
    }
#undef C2_ISSUE

    // final: relu(h2 + b2) @ W3, quad-reduce, scatter
    {
        int lane = tid & 31;
#pragma unroll
        for (int h = 0; h < 2; h++) {
            int r = wm + h * 8 + (lane >> 2);
            float a0 = 0.f, a1 = 0.f, a2 = 0.f;
#pragma unroll
            for (int nt = 0; nt < 16; nt++) {
                int c = wn + nt * 8 + (lane & 3) * 2;
                float v0 = fmaxf(acc[nt][h*2]   + __ldg(b2e + c),     0.f);
                float v1 = fmaxf(acc[nt][h*2+1] + __ldg(b2e + c + 1), 0.f);
                a0 += v0 * __ldg(w3e + c*3 + 0) + v1 * __ldg(w3e + (c+1)*3 + 0);
                a1 += v0 * __ldg(w3e + c*3 + 1) + v1 * __ldg(w3e + (c+1)*3 + 1);
                a2 += v0 * __ldg(w3e + c*3 + 2) + v1 * __ldg(w3e + (c+1)*3 + 2);
            }
            a0 += __shfl_xor_sync(0xFFFFFFFF, a0, 1);
            a0 += __shfl_xor_sync(0xFFFFFFFF, a0, 2);
            a1 += __shfl_xor_sync(0xFFFFFFFF, a1, 1);
            a1 += __shfl_xor_sync(0xFFFFFFFF, a1, 2);
            a2 += __shfl_xor_sync(0xFFFFFFFF, a2, 1);
            a2 += __shfl_xor_sync(0xFFFFFFFF, a2, 2);
            if ((lane & 3) == 0) {
                atomicAdd(&sact[r * 3 + 0], a0);
                atomicAdd(&sact[r * 3 + 1], a1);
                atomicAdd(&sact[r * 3 + 2], a2);
            }
        }
    }
    __syncthreads();
    if (tid < 128) {
        int src = ridx[tid];
        if (src >= 0) {
            out[(size_t)B_TOT + (size_t)src * 3 + 0] = sact[tid * 3 + 0] + __ldg(b3 + e * 3 + 0);
            out[(size_t)B_TOT + (size_t)src * 3 + 1] = sact[tid * 3 + 1] + __ldg(b3 + e * 3 + 1);
            out[(size_t)B_TOT + (size_t)src * 3 + 2] = sact[tid * 3 + 2] + __ldg(b3 + e * 3 + 2);
        }
    }
}

// ===================== launcher =====================
extern "C" void kernel_launch(void* const* d_in, const int* in_sizes, int n_in,
                              void* d_out, int out_size)
{
    const float* p_i    = (const float*)d_in[0];
    const float* speed  = (const float*)d_in[1];
    const int*   cmd    = (const int*)d_in[2];
    const float* sp_W1  = (const float*)d_in[3];
    const float* sp_b1  = (const float*)d_in[4];
    const float* sp_W2  = (const float*)d_in[5];
    const float* sp_b2  = (const float*)d_in[6];
    const float* sp_W3  = (const float*)d_in[7];
    const float* sp_b3  = (const float*)d_in[8];
    const float* vp_W1  = (const float*)d_in[9];
    const float* vp_b1  = (const float*)d_in[10];
    const float* vp_W2  = (const float*)d_in[11];
    const float* vp_b2  = (const float*)d_in[12];
    const float* vp_W3  = (const float*)d_in[13];
    const float* vp_b3  = (const float*)d_in[14];
    const float* join_W = (const float*)d_in[15];
    const float* join_b = (const float*)d_in[16];
    const float* c_W1   = (const float*)d_in[17];
    const float* c_b1   = (const float*)d_in[18];
    const float* c_W2   = (const float*)d_in[19];
    const float* c_b2   = (const float*)d_in[20];
    const float* c_W3   = (const float*)d_in[21];
    const float* c_b3   = (const float*)d_in[22];
    float* out = (float*)d_out;

    cudaFuncSetAttribute(k_sp,   cudaFuncAttributeMaxDynamicSharedMemorySize, SP_SMEM);
    cudaFuncSetAttribute(k_join, cudaFuncAttributeMaxDynamicSharedMemorySize, JOIN_SMEM);
    cudaFuncSetAttribute(k_vp,   cudaFuncAttributeMaxDynamicSharedMemorySize, VP_SMEM);
    cudaFuncSetAttribute(k_ctrl, cudaFuncAttributeMaxDynamicSharedMemorySize, CTRL_SMEM);

    k_prep<<<4800, 256>>>(sp_W2, sp_W3, vp_W1, vp_W2, join_W, c_W1, c_W2);
    k_pis<<<8192, 256>>>(p_i);
    k_sp<<<B_TOT / 128, 512, SP_SMEM>>>(speed, sp_W1, sp_b1, sp_b2, sp_b3);
    dim3 jg(B_TOT / 256, 2);
    k_join<<<jg, 1024, JOIN_SMEM>>>(join_b);
    k_vp<<<B_TOT / 128, 512, VP_SMEM>>>(vp_b1, vp_b2, vp_W3, vp_b3, out);

    k_reset<<<1, 32>>>();
    k_count<<<B_TOT / 256, 256>>>(cmd);
    k_seg<<<1, 32>>>();
    k_scatter<<<B_TOT / 256, 256>>>(cmd);

    k_ctrl<<<B_TOT / 128 + 4, 512, CTRL_SMEM>>>(c_b1, c_b2, c_W3, c_b3, out);
}

// round 9
// speedup vs baseline: 1.3649x; 1.3649x over previous
#include <cuda_runtime.h>
#include <cuda_fp16.h>

#define B_TOT 32768
typedef unsigned int uint;

// ===================== device scratch (tiled+swizzled planes) =====================
// tile = 128 rows x 128 bytes (64 halves), SW128-swizzled, 16KB. B-tiles for N=256 are 256 rows (32KB).
__device__ __half g_spW2T[2*8192],  g_spW3T[2*8192];          // [ch][128x64]
__device__ __half g_vpW1T[8*8192],  g_vpW2T[2*8192];          // [ch][128x64]
__device__ __half g_joinT[(size_t)2*10*16384];                // [nb][ch][256x64]
__device__ __half g_cW1T[(size_t)4*8*16384];                  // [e][ch][256x64]
__device__ __half g_cW2T[(size_t)4*4*16384];                  // [e][ch][256x64]
__device__ __half g_pi_h[(size_t)256*8*8192], g_pi_l[(size_t)256*8*8192];   // [mb][ch][tile]
__device__ __half g_v_h [(size_t)256*2*8192], g_v_l [(size_t)256*2*8192];   // [mb][ch][tile]
__device__ __half g_jo_h[(size_t)256*8*8192], g_jo_l[(size_t)256*8*8192];   // [mb][ch][tile]
__device__ int g_idx[B_TOT + 512];
__device__ int g_cnt[4], g_fill[4], g_seg[5];

// ===================== primitives =====================
__device__ __forceinline__ uint smem_u32(const void* p) {
    uint a;
    asm("{ .reg .u64 t; cvta.to.shared.u64 t, %1; cvt.u32.u64 %0, t; }" : "=r"(a) : "l"(p));
    return a;
}
__device__ __forceinline__ uint swzoff(int r, int cbyte) {   // within-tile byte offset
    return (uint)(r * 128 + (cbyte ^ ((r & 7) << 4)));
}
__device__ __forceinline__ void ldm4(uint f[4], uint a) {
    asm volatile("ldmatrix.sync.aligned.m8n8.x4.shared.b16 {%0,%1,%2,%3}, [%4];"
        : "=r"(f[0]), "=r"(f[1]), "=r"(f[2]), "=r"(f[3]) : "r"(a));
}
__device__ __forceinline__ void mma_fp16(float c[4], const uint a[4], const uint b[2]) {
    asm volatile(
        "mma.sync.aligned.m16n8k16.row.col.f32.f16.f16.f32 "
        "{%0,%1,%2,%3}, {%4,%5,%6,%7}, {%8,%9}, {%0,%1,%2,%3};"
        : "+f"(c[0]), "+f"(c[1]), "+f"(c[2]), "+f"(c[3])
        : "r"(a[0]), "r"(a[1]), "r"(a[2]), "r"(a[3]), "r"(b[0]), "r"(b[1]));
}
__device__ __forceinline__ void split2h(float a, float b, uint& ph, uint& pl) {
    __half h0 = __float2half_rn(a), h1 = __float2half_rn(b);
    float r0 = a - __half2float(h0), r1 = b - __half2float(h1);
    __half l0 = __float2half_rn(r0), l1 = __float2half_rn(r1);
    ph = (uint)__half_as_ushort(h0) | ((uint)__half_as_ushort(h1) << 16);
    pl = (uint)__half_as_ushort(l0) | ((uint)__half_as_ushort(l1) << 16);
}
__device__ __forceinline__ void cpa16(uint d, const void* s) {
    asm volatile("cp.async.cg.shared.global [%0], [%1], 16;" :: "r"(d), "l"(s));
}
#define CPA_COMMIT() asm volatile("cp.async.commit_group;" ::: "memory")
#define CPA_WAIT0()  asm volatile("cp.async.wait_group 0;" ::: "memory")
#define CPA_WAIT1()  asm volatile("cp.async.wait_group 1;" ::: "memory")

__device__ __forceinline__ void bulk_g2s(uint dst, const void* src, uint bytes, uint mbar) {
    asm volatile("cp.async.bulk.shared::cluster.global.mbarrier::complete_tx::bytes [%0], [%1], %2, [%3];"
        :: "r"(dst), "l"(src), "r"(bytes), "r"(mbar) : "memory");
}
#define MBAR_INIT(a, c) asm volatile("mbarrier.init.shared.b64 [%0], %1;" :: "r"(a), "r"(c) : "memory")
#define MBAR_EXPECT(a, tx) asm volatile("mbarrier.arrive.expect_tx.shared.b64 _, [%0], %1;" :: "r"(a), "r"(tx) : "memory")
#define MBAR_WAIT(mbar_a, par) do { \
    uint _m = (mbar_a); uint _p = (uint)(par); uint _d; \
    asm volatile("{ .reg .pred p; mbarrier.try_wait.parity.acquire.cta.shared::cta.b64 p, [%1], %2; selp.b32 %0, 1, 0, p; }" \
        : "=r"(_d) : "r"(_m), "r"(_p) : "memory"); \
    if (!_d) { \
        asm volatile("{ .reg .pred P1;\nWL_%=:\n mbarrier.try_wait.parity.acquire.cta.shared::cta.b64 P1, [%0], %1, 0x989680;\n @P1 bra.uni WD_%=;\n bra.uni WL_%=;\nWD_%=:\n}" \
            :: "r"(_m), "r"(_p) : "memory"); \
    } \
} while (0)

// ===================== gemm: warp tile 16 x (NT*8), 2-pass (A hi/lo fp16) =====================
template <int NT>
__device__ __forceinline__ void gemm_swz(float (&acc)[NT][4], uint Ah, uint Al, uint Bs, int wm, int wn)
{
    const int lane = threadIdx.x & 31;
    const int ra = (lane & 15) + wm;
    const uint abase = (uint)(ra >> 7) * 16384u + (uint)(ra & 127) * 128u;
    const uint Ath = Ah + abase, Atl = Al + abase;
    const uint ax = (uint)((ra & 7) << 4);
    const int ua = lane >> 4;
    const int rb = (lane & 7) + ((lane >> 4) << 3) + wn;
    const uint Bt = Bs + (uint)rb * 128u;
    const uint bx2 = (uint)((rb & 7) << 4);
    const int ub = (lane >> 3) & 1;
#pragma unroll
    for (int s = 0; s < 4; s++) {
        uint ca = ((uint)((s * 2 + ua) * 16)) ^ ax;
        uint ah4[4], al4[4];
        ldm4(ah4, Ath + ca);
        ldm4(al4, Atl + ca);
        uint cbb = ((uint)((s * 2 + ub) * 16)) ^ bx2;
#pragma unroll
        for (int p = 0; p < NT / 2; p++) {
            uint b4[4];
            ldm4(b4, Bt + (uint)(p * 2048) + cbb);
            mma_fp16(acc[2*p],   ah4, b4);
            mma_fp16(acc[2*p],   al4, b4);
            mma_fp16(acc[2*p+1], ah4, b4 + 2);
            mma_fp16(acc[2*p+1], al4, b4 + 2);
        }
    }
}
template <int NT>
__device__ __forceinline__ void acc_zero(float (&acc)[NT][4]) {
#pragma unroll
    for (int n = 0; n < NT; n++)
#pragma unroll
    for (int q = 0; q < 4; q++) acc[n][q] = 0.f;
}

// ===================== epilogue: bias(+relu) -> split -> swizzled tiles (smem or global) =====================
template <int NT>
__device__ __forceinline__ void epi_tiled(const float (&acc)[NT][4],
    char* dh, char* dl, const float* bias, int cb,
    size_t tsMb, size_t tsCh, int wm, int wn, bool relu)
{
    int lane = threadIdx.x & 31;
    int rr = wm + (lane >> 2), cc = wn + (lane & 3) * 2;
#pragma unroll
    for (int nt = 0; nt < NT; nt++)
#pragma unroll
    for (int h = 0; h < 2; h++) {
        int r = rr + h * 8, c = cc + nt * 8;
        float v0 = acc[nt][h*2]   + __ldg(bias + cb + c);
        float v1 = acc[nt][h*2+1] + __ldg(bias + cb + c + 1);
        if (relu) { v0 = fmaxf(v0, 0.f); v1 = fmaxf(v1, 0.f); }
        uint ph, pl; split2h(v0, v1, ph, pl);
        size_t off = (size_t)(r >> 7) * tsMb + (size_t)(c >> 6) * tsCh
                   + swzoff(r & 127, (c & 63) * 2);
        *(uint*)(dh + off) = ph;
        *(uint*)(dl + off) = pl;
    }
}

// ===================== weight prep (transpose + fp16 + tile/swizzle) =====================
__global__ void k_prep(const float* spW2, const float* spW3, const float* vpW1, const float* vpW2,
                       const float* jW, const float* cW1, const float* cW2) {
    int i = blockIdx.x * 256 + threadIdx.x;
    float x; char* base; size_t off;
    if (i < 16384) {
        int l = i; int n = l >> 7, k = l & 127; x = spW2[k*128+n];
        base = (char*)g_spW2T; off = (size_t)(k >> 6) * 16384 + swzoff(n, (k & 63) * 2);
    } else if (i < 32768) {
        int l = i - 16384; int n = l >> 7, k = l & 127; x = spW3[k*128+n];
        base = (char*)g_spW3T; off = (size_t)(k >> 6) * 16384 + swzoff(n, (k & 63) * 2);
    } else if (i < 98304) {
        int l = i - 32768; int n = l >> 9, k = l & 511; x = vpW1[k*128+n];
        base = (char*)g_vpW1T; off = (size_t)(k >> 6) * 16384 + swzoff(n, (k & 63) * 2);
    } else if (i < 114688) {
        int l = i - 98304; int n = l >> 7, k = l & 127; x = vpW2[k*128+n];
        base = (char*)g_vpW2T; off = (size_t)(k >> 6) * 16384 + swzoff(n, (k & 63) * 2);
    } else if (i < 442368) {
        int l = i - 114688; int n = l / 640, k = l - n * 640; x = jW[(size_t)k*512+n];
        int nb = n >> 8, nl = n & 255;
        base = (char*)g_joinT; off = ((size_t)nb * 10 + (k >> 6)) * 32768 + swzoff(nl, (k & 63) * 2);
    } else if (i < 966656) {
        int l = i - 442368; int e = l >> 17, rm = l & 131071; int n = rm >> 9, k = rm & 511;
        x = cW1[(size_t)e*131072 + (size_t)k*256 + n];
        base = (char*)g_cW1T; off = ((size_t)e * 8 + (k >> 6)) * 32768 + swzoff(n, (k & 63) * 2);
    } else if (i < 1228800) {
        int l = i - 966656; int e = l >> 16, rm = l & 65535; int n = rm >> 8, k = rm & 255;
        x = cW2[(size_t)e*65536 + (size_t)k*256 + n];
        base = (char*)g_cW2T; off = ((size_t)e * 4 + (k >> 6)) * 32768 + swzoff(n, (k & 63) * 2);
    } else return;
    *(__half*)(base + off) = __float2half_rn(x);
}

// p_i -> tiled swizzled hi/lo planes. One 16B unit per thread.
__global__ void k_pis(const float* __restrict__ p) {
    int idx = blockIdx.x * 256 + threadIdx.x;           // [0, 2097152)
    int m = idx >> 6, u = idx & 63;
    int ch = u >> 3, ui = u & 7;
    const float* s = p + (size_t)m * 512 + u * 8;
    float4 f0 = *(const float4*)s;
    float4 f1 = *(const float4*)(s + 4);
    float xs[8] = {f0.x, f0.y, f0.z, f0.w, f1.x, f1.y, f1.z, f1.w};
    uint wh[4], wl[4];
#pragma unroll
    for (int q = 0; q < 4; q++) split2h(xs[2*q], xs[2*q+1], wh[q], wl[q]);
    size_t off = ((size_t)(m >> 7) * 8 + ch) * 16384 + swzoff(m & 127, ui * 16);
    *(uint4*)((char*)g_pi_h + off) = make_uint4(wh[0], wh[1], wh[2], wh[3]);
    *(uint4*)((char*)g_pi_l + off) = make_uint4(wl[0], wl[1], wl[2], wl[3]);
}

// ===================== routing =====================
__global__ void k_reset() { if (threadIdx.x < 4) { g_cnt[threadIdx.x] = 0; g_fill[threadIdx.x] = 0; } }
__global__ void k_count(const int* __restrict__ cmd) {
    __shared__ int h[4];
    int tid = threadIdx.x;
    if (tid < 4) h[tid] = 0;
    __syncthreads();
    int i = blockIdx.x * 256 + tid;
    if (i < B_TOT) atomicAdd(&h[cmd[i] & 3], 1);
    __syncthreads();
    if (tid < 4) atomicAdd(&g_cnt[tid], h[tid]);
}
__global__ void k_seg() {
    if (threadIdx.x == 0) {
        int off = 0;
        for (int e = 0; e < 4; e++) { g_seg[e] = off; off += (g_cnt[e] + 127) & ~127; }
        g_seg[4] = off;
    }
}
__global__ void k_scatter(const int* __restrict__ cmd) {
    __shared__ int h[4], base[4];
    int tid = threadIdx.x;
    if (tid < 4) h[tid] = 0;
    __syncthreads();
    int i = blockIdx.x * 256 + tid;
    int e = 0, loc = 0;
    if (i < B_TOT) { e = cmd[i] & 3; loc = atomicAdd(&h[e], 1); }
    __syncthreads();
    if (tid < 4) base[tid] = atomicAdd(&g_fill[tid], h[tid]);
    __syncthreads();
    if (i < B_TOT) g_idx[g_seg[e] + base[e] + loc] = i;
}

// ===================== k_sp: 1 -> 128 -> 128 -> 128 (M=128, N=128) =====================
#define SP_SMEM 164384

__global__ void __launch_bounds__(512) k_sp(
    const float* __restrict__ speed,
    const float* __restrict__ W1, const float* __restrict__ b1,
    const float* __restrict__ b2, const float* __restrict__ b3)
{
    extern __shared__ char sm[];
    uint sb = smem_u32(sm);
    int tid = threadIdx.x, wid = tid >> 5;
    int wm = (wid & 7) * 16, wn = (wid >> 3) * 64;
    size_t m0 = (size_t)blockIdx.x * 128;
    uint mbar = sb + 164352;
    float* ss = (float*)(sm + 163840);
    if (tid == 0) MBAR_INIT(mbar, 1);
    if (tid < 128) ss[tid] = speed[m0 + tid];
    __syncthreads();
    if (tid == 0) { MBAR_EXPECT(mbar, 32768); bulk_g2s(sb + 131072, g_spW2T, 32768, mbar); }

    for (int u = tid; u < 8192; u += 512) {
        int r = u >> 6, c = (u & 63) * 2;
        float sv = ss[r];
        float v0 = fmaxf(fmaf(sv, __ldg(W1 + c),     __ldg(b1 + c)),     0.f);
        float v1 = fmaxf(fmaf(sv, __ldg(W1 + c + 1), __ldg(b1 + c + 1)), 0.f);
        uint ph, pl; split2h(v0, v1, ph, pl);
        uint off = (uint)(c >> 6) * 32768 + swzoff(r, (c & 63) * 2);
        *(uint*)(sm + off) = ph;
        *(uint*)(sm + 16384 + off) = pl;
    }
    __syncthreads();
    MBAR_WAIT(mbar, 0);

    float acc[8][4];
    acc_zero(acc);
    gemm_swz<8>(acc, sb + 0,     sb + 16384, sb + 131072,         wm, wn);
    gemm_swz<8>(acc, sb + 32768, sb + 49152, sb + 131072 + 16384, wm, wn);
    __syncthreads();
    if (tid == 0) { MBAR_EXPECT(mbar, 32768); bulk_g2s(sb + 131072, g_spW3T, 32768, mbar); }
    epi_tiled<8>(acc, sm + 65536, sm + 65536 + 16384, b2, 0, 0, 32768, wm, wn, true);
    __syncthreads();
    MBAR_WAIT(mbar, 1);

    acc_zero(acc);
    gemm_swz<8>(acc, sb + 65536,         sb + 65536 + 16384, sb + 131072,         wm, wn);
    gemm_swz<8>(acc, sb + 65536 + 32768, sb + 65536 + 49152, sb + 131072 + 16384, wm, wn);
    epi_tiled<8>(acc, (char*)g_v_h + (size_t)blockIdx.x * 2 * 16384,
                      (char*)g_v_l + (size_t)blockIdx.x * 2 * 16384,
                 b3, 0, 0, 16384, wm, wn, false);
}

// ===================== k_join: M=128, N=256, 512 threads, 3-stage bulk pipeline =====================
// stage: A_h @0 (16KB), A_l @16384, B(256x64) @32768 (32KB); 64KB/stage; 3 stages; mbars @196608
#define JSTG 65536u
#define JOIN_SMEM 196640

__global__ void __launch_bounds__(512) k_join(const float* __restrict__ jb)
{
    extern __shared__ char sm[];
    uint sb = smem_u32(sm);
    int tid = threadIdx.x, wid = tid >> 5;
    int wm = (wid & 7) * 16, wn = (wid >> 3) * 128;
    int bx = blockIdx.x, by = blockIdx.y;
    int N0 = by * 256;
    uint mb[3] = {sb + 196608, sb + 196616, sb + 196624};
    if (tid == 0) { MBAR_INIT(mb[0], 1); MBAR_INIT(mb[1], 1); MBAR_INIT(mb[2], 1); }
    __syncthreads();

#define J_ISSUE(c, s) do { \
    uint d = sb + (uint)(s) * JSTG; uint m_ = mb[s]; \
    MBAR_EXPECT(m_, 65536); \
    if ((c) < 8) { \
        size_t t = ((size_t)bx * 8 + (c)) * 16384; \
        bulk_g2s(d,         (char*)g_pi_h + t, 16384, m_); \
        bulk_g2s(d + 16384, (char*)g_pi_l + t, 16384, m_); \
    } else { \
        size_t t = ((size_t)bx * 2 + ((c)-8)) * 16384; \
        bulk_g2s(d,         (char*)g_v_h + t, 16384, m_); \
        bulk_g2s(d + 16384, (char*)g_v_l + t, 16384, m_); \
    } \
    bulk_g2s(d + 32768, (char*)g_joinT + ((size_t)by * 10 + (c)) * 32768, 32768, m_); \
} while (0)

    float acc[16][4];
    acc_zero(acc);
    if (tid == 0) { J_ISSUE(0, 0); J_ISSUE(1, 1); }
    int par[3] = {0, 0, 0};
    for (int c = 0; c < 10; c++) {
        int s = c % 3;
        MBAR_WAIT(mb[s], par[s]); par[s] ^= 1;
        gemm_swz<16>(acc, sb + s*JSTG, sb + s*JSTG + 16384, sb + s*JSTG + 32768, wm, wn);
        __syncthreads();
        if (tid == 0 && c + 2 < 10) J_ISSUE(c + 2, (c + 2) % 3);
    }
#undef J_ISSUE
    epi_tiled<16>(acc,
        (char*)g_jo_h + ((size_t)bx * 8 + (N0 >> 6)) * 16384,
        (char*)g_jo_l + ((size_t)bx * 8 + (N0 >> 6)) * 16384,
        jb, N0, 0, 16384, wm, wn, false);
}

// ===================== k_vp: 512 -> 128 -> 128 -> 1 (M=128, N=128) =====================
#define VSTG 49152u
#define VP_SMEM 197152

__global__ void __launch_bounds__(512) k_vp(
    const float* __restrict__ b1, const float* __restrict__ b2,
    const float* __restrict__ W3, const float* __restrict__ b3,
    float* __restrict__ out)
{
    extern __shared__ char sm[];
    uint sb = smem_u32(sm);
    int tid = threadIdx.x, wid = tid >> 5;
    int wm = (wid & 7) * 16, wn = (wid >> 3) * 64;
    int bx = blockIdx.x;
    size_t m0 = (size_t)bx * 128;
    float* sv = (float*)(sm + 196608);
    uint mb[2] = {sb + 197120, sb + 197128};
    if (tid == 0) { MBAR_INIT(mb[0], 1); MBAR_INIT(mb[1], 1); }
    if (tid < 128) sv[tid] = 0.f;
    __syncthreads();

#define V_ISSUE(c, s) do { \
    uint d = sb + (uint)(s) * VSTG; uint m_ = mb[s]; \
    MBAR_EXPECT(m_, 49152); \
    size_t t = ((size_t)bx * 8 + (c)) * 16384; \
    bulk_g2s(d,         (char*)g_pi_h + t, 16384, m_); \
    bulk_g2s(d + 16384, (char*)g_pi_l + t, 16384, m_); \
    bulk_g2s(d + 32768, (char*)g_vpW1T + (size_t)(c) * 16384, 16384, m_); \
} while (0)

    float acc[8][4];
    acc_zero(acc);
    if (tid == 0) { V_ISSUE(0, 0); V_ISSUE(1, 1); }
    int par[2] = {0, 0};
    for (int c = 0; c < 8; c++) {
        int s = c & 1;
        MBAR_WAIT(mb[s], par[s]); par[s] ^= 1;
        gemm_swz<8>(acc, sb + s*VSTG, sb + s*VSTG + 16384, sb + s*VSTG + 32768, wm, wn);
        __syncthreads();
        if (tid == 0 && c + 2 < 8) V_ISSUE(c + 2, s);
    }
#undef V_ISSUE
    if (tid == 0) { MBAR_EXPECT(mb[0], 32768); bulk_g2s(sb + 163840, g_vpW2T, 32768, mb[0]); }
    epi_tiled<8>(acc, sm + 98304, sm + 98304 + 16384, b1, 0, 0, 32768, wm, wn, true);
    __syncthreads();
    MBAR_WAIT(mb[0], par[0]); par[0] ^= 1;

    acc_zero(acc);
    gemm_swz<8>(acc, sb + 98304,         sb + 98304 + 16384, sb + 163840,         wm, wn);
    gemm_swz<8>(acc, sb + 98304 + 32768, sb + 98304 + 49152, sb + 163840 + 16384, wm, wn);

    {
        int lane = tid & 31;
#pragma unroll
        for (int h = 0; h < 2; h++) {
            int r = wm + h * 8 + (lane >> 2);
            float s = 0.f;
#pragma unroll
            for (int nt = 0; nt < 8; nt++) {
                int c = wn + nt * 8 + (lane & 3) * 2;
                float v0 = fmaxf(acc[nt][h*2]   + __ldg(b2 + c),     0.f);
                float v1 = fmaxf(acc[nt][h*2+1] + __ldg(b2 + c + 1), 0.f);
                s += v0 * __ldg(W3 + c) + v1 * __ldg(W3 + c + 1);
            }
            s += __shfl_xor_sync(0xFFFFFFFF, s, 1);
            s += __shfl_xor_sync(0xFFFFFFFF, s, 2);
            if ((lane & 3) == 0) atomicAdd(&sv[r], s);
        }
    }
    __syncthreads();
    if (tid < 128) out[m0 + tid] = sv[tid] + __ldg(b3);
}

// ===================== k_ctrl: routed 512 -> 256 -> 256 -> 3 (M=128, N=256) =====================
#define CTRL_SMEM 198688

__global__ void __launch_bounds__(512) k_ctrl(
    const float* __restrict__ b1, const float* __restrict__ b2,
    const float* __restrict__ W3, const float* __restrict__ b3,
    float* __restrict__ out)
{
    int p0 = blockIdx.x * 128;
    int s1 = g_seg[1], s2 = g_seg[2], s3 = g_seg[3], s4 = g_seg[4];
    if (p0 >= s4) return;
    int e, segb;
    if (p0 < s1)      { e = 0; segb = 0; }
    else if (p0 < s2) { e = 1; segb = s1; }
    else if (p0 < s3) { e = 2; segb = s2; }
    else              { e = 3; segb = s3; }
    int cnt = g_cnt[e];

    extern __shared__ char sm[];
    uint sb = smem_u32(sm);
    int tid = threadIdx.x, wid = tid >> 5;
    int wm = (wid & 7) * 16, wn = (wid >> 3) * 128;
    int* ridx = (int*)(sm + 196608);
    float* sact = (float*)(sm + 197120);
    uint mb[2] = {sb + 198656, sb + 198664};
    if (tid == 0) { MBAR_INIT(mb[0], 1); MBAR_INIT(mb[1], 1); }
    if (tid < 128) {
        int local = p0 - segb + tid;
        ridx[tid] = (local < cnt) ? g_idx[p0 + tid] : -1;
        sact[tid] = 0.f; sact[128 + tid] = 0.f; sact[256 + tid] = 0.f;
    }
    __syncthreads();

    const float* b1e = b1 + e * 256;
    const float* b2e = b2 + e * 256;
    const float* w3e = W3 + e * 768;

#define C1_ISSUE(c, s) do { \
    uint d = sb + (uint)(s) * 65536u; \
    if (tid == 0) { \
        MBAR_EXPECT(mb[s], 32768); \
        bulk_g2s(d + 32768, (char*)g_cW1T + ((size_t)e * 8 + (c)) * 32768, 32768, mb[s]); \
    } \
    for (int u = tid; u < 2048; u += 512) { \
        int pl_ = u >> 10, rem = u & 1023, rl = rem >> 3, un = rem & 7; \
        int src = ridx[rl]; if (src < 0) src = 0; \
        size_t so = ((size_t)(src >> 7) * 8 + (c)) * 16384 \
                  + (size_t)((src & 127) * 128 + ((un * 16) ^ ((src & 7) << 4))); \
        uint dd = d + (uint)pl_ * 16384u + swzoff(rl, un * 16); \
        cpa16(dd, (pl_ ? (char*)g_jo_l : (char*)g_jo_h) + so); \
    } \
    CPA_COMMIT(); \
} while (0)

    float acc[16][4];
    acc_zero(acc);
    C1_ISSUE(0, 0); C1_ISSUE(1, 1);
    int par[2] = {0, 0};
    for (int c = 0; c < 8; c++) {
        int s = c & 1;
        if (c < 7) CPA_WAIT1(); else CPA_WAIT0();
        MBAR_WAIT(mb[s], par[s]); par[s] ^= 1;
        __syncthreads();
        gemm_swz<16>(acc, sb + s*65536u, sb + s*65536u + 16384, sb + s*65536u + 32768, wm, wn);
        __syncthreads();
        if (c + 2 < 8) C1_ISSUE(c + 2, s);
    }
#undef C1_ISSUE

    epi_tiled<16>(acc, sm, sm + 16384, b1e, 0, 0, 32768, wm, wn, true);
    __syncthreads();

#define C2_ISSUE(c, s) do { \
    if (tid == 0) { \
        MBAR_EXPECT(mb[s], 32768); \
        bulk_g2s(sb + 131072u + (uint)(s) * 32768u, \
                 (char*)g_cW2T + ((size_t)e * 4 + (c)) * 32768, 32768, mb[s]); \
    } \
} while (0)
    acc_zero(acc);
    C2_ISSUE(0, 0); C2_ISSUE(1, 1);
    for (int c = 0; c < 4; c++) {
        int s = c & 1;
        MBAR_WAIT(mb[s], par[s]); par[s] ^= 1;
        gemm_swz<16>(acc, sb + (uint)c * 32768u, sb + (uint)c * 32768u + 16384,
                     sb + 131072u + (uint)s * 32768u, wm, wn);
        __syncthreads();
        if (c + 2 < 4) C2_ISSUE(c + 2, s);
    }
#undef C2_ISSUE

    {
        int lane = tid & 31;
#pragma unroll
        for (int h = 0; h < 2; h++) {
            int r = wm + h * 8 + (lane >> 2);
            float a0 = 0.f, a1 = 0.f, a2 = 0.f;
#pragma unroll
            for (int nt = 0; nt < 16; nt++) {
                int c = wn + nt * 8 + (lane & 3) * 2;
                float v0 = fmaxf(acc[nt][h*2]   + __ldg(b2e + c),     0.f);
                float v1 = fmaxf(acc[nt][h*2+1] + __ldg(b2e + c + 1), 0.f);
                a0 += v0 * __ldg(w3e + c*3 + 0) + v1 * __ldg(w3e + (c+1)*3 + 0);
                a1 += v0 * __ldg(w3e + c*3 + 1) + v1 * __ldg(w3e + (c+1)*3 + 1);
                a2 += v0 * __ldg(w3e + c*3 + 2) + v1 * __ldg(w3e + (c+1)*3 + 2);
            }
            a0 += __shfl_xor_sync(0xFFFFFFFF, a0, 1);
            a0 += __shfl_xor_sync(0xFFFFFFFF, a0, 2);
            a1 += __shfl_xor_sync(0xFFFFFFFF, a1, 1);
            a1 += __shfl_xor_sync(0xFFFFFFFF, a1, 2);
            a2 += __shfl_xor_sync(0xFFFFFFFF, a2, 1);
            a2 += __shfl_xor_sync(0xFFFFFFFF, a2, 2);
            if ((lane & 3) == 0) {
                atomicAdd(&sact[r * 3 + 0], a0);
                atomicAdd(&sact[r * 3 + 1], a1);
                atomicAdd(&sact[r * 3 + 2], a2);
            }
        }
    }
    __syncthreads();
    if (tid < 128) {
        int src = ridx[tid];
        if (src >= 0) {
            out[(size_t)B_TOT + (size_t)src * 3 + 0] = sact[tid * 3 + 0] + __ldg(b3 + e * 3 + 0);
            out[(size_t)B_TOT + (size_t)src * 3 + 1] = sact[tid * 3 + 1] + __ldg(b3 + e * 3 + 1);
            out[(size_t)B_TOT + (size_t)src * 3 + 2] = sact[tid * 3 + 2] + __ldg(b3 + e * 3 + 2);
        }
    }
}

// ===================== launcher =====================
extern "C" void kernel_launch(void* const* d_in, const int* in_sizes, int n_in,
                              void* d_out, int out_size)
{
    const float* p_i    = (const float*)d_in[0];
    const float* speed  = (const float*)d_in[1];
    const int*   cmd    = (const int*)d_in[2];
    const float* sp_W1  = (const float*)d_in[3];
    const float* sp_b1  = (const float*)d_in[4];
    const float* sp_W2  = (const float*)d_in[5];
    const float* sp_b2  = (const float*)d_in[6];
    const float* sp_W3  = (const float*)d_in[7];
    const float* sp_b3  = (const float*)d_in[8];
    const float* vp_W1  = (const float*)d_in[9];
    const float* vp_b1  = (const float*)d_in[10];
    const float* vp_W2  = (const float*)d_in[11];
    const float* vp_b2  = (const float*)d_in[12];
    const float* vp_W3  = (const float*)d_in[13];
    const float* vp_b3  = (const float*)d_in[14];
    const float* join_W = (const float*)d_in[15];
    const float* join_b = (const float*)d_in[16];
    const float* c_W1   = (const float*)d_in[17];
    const float* c_b1   = (const float*)d_in[18];
    const float* c_W2   = (const float*)d_in[19];
    const float* c_b2   = (const float*)d_in[20];
    const float* c_W3   = (const float*)d_in[21];
    const float* c_b3   = (const float*)d_in[22];
    float* out = (float*)d_out;

    cudaFuncSetAttribute(k_sp,   cudaFuncAttributeMaxDynamicSharedMemorySize, SP_SMEM);
    cudaFuncSetAttribute(k_join, cudaFuncAttributeMaxDynamicSharedMemorySize, JOIN_SMEM);
    cudaFuncSetAttribute(k_vp,   cudaFuncAttributeMaxDynamicSharedMemorySize, VP_SMEM);
    cudaFuncSetAttribute(k_ctrl, cudaFuncAttributeMaxDynamicSharedMemorySize, CTRL_SMEM);

    k_prep<<<4800, 256>>>(sp_W2, sp_W3, vp_W1, vp_W2, join_W, c_W1, c_W2);
    k_pis<<<8192, 256>>>(p_i);
    k_sp<<<B_TOT / 128, 512, SP_SMEM>>>(speed, sp_W1, sp_b1, sp_b2, sp_b3);
    dim3 jg(B_TOT / 128, 2);
    k_join<<<jg, 512, JOIN_SMEM>>>(join_b);
    k_vp<<<B_TOT / 128, 512, VP_SMEM>>>(vp_b1, vp_b2, vp_W3, vp_b3, out);

    k_reset<<<1, 32>>>();
    k_count<<<B_TOT / 256, 256>>>(cmd);
    k_seg<<<1, 32>>>();
    k_scatter<<<B_TOT / 256, 256>>>(cmd);

    k_ctrl<<<B_TOT / 128 + 4, 512, CTRL_SMEM>>>(c_b1, c_b2, c_W3, c_b3, out);
}

// round 10
// speedup vs baseline: 1.4342x; 1.0508x over previous
#include <cuda_runtime.h>
#include <cuda_fp16.h>

#define B_TOT 32768
typedef unsigned int uint;

// ===================== device scratch (tiled+swizzled planes) =====================
__device__ __half g_spW2T[2*8192],  g_spW3T[2*8192];          // [ch][128x64]
__device__ __half g_vpW1T[8*8192],  g_vpW2T[2*8192];          // [ch][128x64]
__device__ __half g_joinT[(size_t)2*10*16384];                // [nb][ch][256x64]
__device__ __half g_cW1T[(size_t)4*8*16384];                  // [e][ch][256x64]
__device__ __half g_cW2T[(size_t)4*4*16384];                  // [e][ch][256x64]
__device__ __half g_pi_h[(size_t)256*8*8192], g_pi_l[(size_t)256*8*8192];   // [mb][ch][tile]
__device__ __half g_v_h [(size_t)256*2*8192], g_v_l [(size_t)256*2*8192];   // [mb][ch][tile]
__device__ __half g_jo_h[(size_t)256*8*8192], g_jo_l[(size_t)256*8*8192];   // [mb][ch][tile]
__device__ int g_idx[B_TOT + 512];
__device__ int g_cnt[4], g_fill[4], g_seg[5];

// ===================== primitives =====================
__device__ __forceinline__ uint smem_u32(const void* p) {
    uint a;
    asm("{ .reg .u64 t; cvta.to.shared.u64 t, %1; cvt.u32.u64 %0, t; }" : "=r"(a) : "l"(p));
    return a;
}
__device__ __forceinline__ uint swzoff(int r, int cbyte) {
    return (uint)(r * 128 + (cbyte ^ ((r & 7) << 4)));
}
__device__ __forceinline__ void ldm4(uint f[4], uint a) {
    asm volatile("ldmatrix.sync.aligned.m8n8.x4.shared.b16 {%0,%1,%2,%3}, [%4];"
        : "=r"(f[0]), "=r"(f[1]), "=r"(f[2]), "=r"(f[3]) : "r"(a));
}
__device__ __forceinline__ void mma_fp16(float c[4], const uint a[4], const uint b[2]) {
    asm volatile(
        "mma.sync.aligned.m16n8k16.row.col.f32.f16.f16.f32 "
        "{%0,%1,%2,%3}, {%4,%5,%6,%7}, {%8,%9}, {%0,%1,%2,%3};"
        : "+f"(c[0]), "+f"(c[1]), "+f"(c[2]), "+f"(c[3])
        : "r"(a[0]), "r"(a[1]), "r"(a[2]), "r"(a[3]), "r"(b[0]), "r"(b[1]));
}
__device__ __forceinline__ void split2h(float a, float b, uint& ph, uint& pl) {
    __half h0 = __float2half_rn(a), h1 = __float2half_rn(b);
    float r0 = a - __half2float(h0), r1 = b - __half2float(h1);
    __half l0 = __float2half_rn(r0), l1 = __float2half_rn(r1);
    ph = (uint)__half_as_ushort(h0) | ((uint)__half_as_ushort(h1) << 16);
    pl = (uint)__half_as_ushort(l0) | ((uint)__half_as_ushort(l1) << 16);
}
__device__ __forceinline__ void cpa16(uint d, const void* s) {
    asm volatile("cp.async.cg.shared.global [%0], [%1], 16;" :: "r"(d), "l"(s));
}
#define CPA_COMMIT() asm volatile("cp.async.commit_group;" ::: "memory")
#define CPA_WAIT0()  asm volatile("cp.async.wait_group 0;" ::: "memory")
#define CPA_WAIT1()  asm volatile("cp.async.wait_group 1;" ::: "memory")

__device__ __forceinline__ void bulk_g2s(uint dst, const void* src, uint bytes, uint mbar) {
    asm volatile("cp.async.bulk.shared::cluster.global.mbarrier::complete_tx::bytes [%0], [%1], %2, [%3];"
        :: "r"(dst), "l"(src), "r"(bytes), "r"(mbar) : "memory");
}
#define MBAR_INIT(a, c) asm volatile("mbarrier.init.shared.b64 [%0], %1;" :: "r"(a), "r"(c) : "memory")
#define MBAR_EXPECT(a, tx) asm volatile("mbarrier.arrive.expect_tx.shared.b64 _, [%0], %1;" :: "r"(a), "r"(tx) : "memory")
#define MBAR_ARRIVE(a) asm volatile("mbarrier.arrive.shared.b64 _, [%0];" :: "r"(a) : "memory")
#define MBAR_WAIT(mbar_a, par) do { \
    uint _m = (mbar_a); uint _p = (uint)(par); uint _d; \
    asm volatile("{ .reg .pred p; mbarrier.try_wait.parity.acquire.cta.shared::cta.b64 p, [%1], %2; selp.b32 %0, 1, 0, p; }" \
        : "=r"(_d) : "r"(_m), "r"(_p) : "memory"); \
    if (!_d) { \
        asm volatile("{ .reg .pred P1;\nWL_%=:\n mbarrier.try_wait.parity.acquire.cta.shared::cta.b64 P1, [%0], %1, 0x989680;\n @P1 bra.uni WD_%=;\n bra.uni WL_%=;\nWD_%=:\n}" \
            :: "r"(_m), "r"(_p) : "memory"); \
    } \
} while (0)

// ===================== gemm: warp tile 16 x (NT*8), 2-pass (A hi/lo fp16) =====================
template <int NT>
__device__ __forceinline__ void gemm_swz(float (&acc)[NT][4], uint Ah, uint Al, uint Bs, int wm, int wn)
{
    const int lane = threadIdx.x & 31;
    const int ra = (lane & 15) + wm;
    const uint abase = (uint)(ra >> 7) * 16384u + (uint)(ra & 127) * 128u;
    const uint Ath = Ah + abase, Atl = Al + abase;
    const uint ax = (uint)((ra & 7) << 4);
    const int ua = lane >> 4;
    const int rb = (lane & 7) + ((lane >> 4) << 3) + wn;
    const uint Bt = Bs + (uint)rb * 128u;
    const uint bx2 = (uint)((rb & 7) << 4);
    const int ub = (lane >> 3) & 1;
#pragma unroll
    for (int s = 0; s < 4; s++) {
        uint ca = ((uint)((s * 2 + ua) * 16)) ^ ax;
        uint ah4[4], al4[4];
        ldm4(ah4, Ath + ca);
        ldm4(al4, Atl + ca);
        uint cbb = ((uint)((s * 2 + ub) * 16)) ^ bx2;
#pragma unroll
        for (int p = 0; p < NT / 2; p++) {
            uint b4[4];
            ldm4(b4, Bt + (uint)(p * 2048) + cbb);
            mma_fp16(acc[2*p],   ah4, b4);
            mma_fp16(acc[2*p],   al4, b4);
            mma_fp16(acc[2*p+1], ah4, b4 + 2);
            mma_fp16(acc[2*p+1], al4, b4 + 2);
        }
    }
}
template <int NT>
__device__ __forceinline__ void acc_zero(float (&acc)[NT][4]) {
#pragma unroll
    for (int n = 0; n < NT; n++)
#pragma unroll
    for (int q = 0; q < 4; q++) acc[n][q] = 0.f;
}

// ===================== epilogue =====================
template <int NT>
__device__ __forceinline__ void epi_tiled(const float (&acc)[NT][4],
    char* dh, char* dl, const float* bias, int cb,
    size_t tsMb, size_t tsCh, int wm, int wn, bool relu)
{
    int lane = threadIdx.x & 31;
    int rr = wm + (lane >> 2), cc = wn + (lane & 3) * 2;
#pragma unroll
    for (int nt = 0; nt < NT; nt++)
#pragma unroll
    for (int h = 0; h < 2; h++) {
        int r = rr + h * 8, c = cc + nt * 8;
        float v0 = acc[nt][h*2]   + __ldg(bias + cb + c);
        float v1 = acc[nt][h*2+1] + __ldg(bias + cb + c + 1);
        if (relu) { v0 = fmaxf(v0, 0.f); v1 = fmaxf(v1, 0.f); }
        uint ph, pl; split2h(v0, v1, ph, pl);
        size_t off = (size_t)(r >> 7) * tsMb + (size_t)(c >> 6) * tsCh
                   + swzoff(r & 127, (c & 63) * 2);
        *(uint*)(dh + off) = ph;
        *(uint*)(dl + off) = pl;
    }
}

// ===================== weight prep =====================
__global__ void k_prep(const float* spW2, const float* spW3, const float* vpW1, const float* vpW2,
                       const float* jW, const float* cW1, const float* cW2) {
    int i = blockIdx.x * 256 + threadIdx.x;
    float x; char* base; size_t off;
    if (i < 16384) {
        int l = i; int n = l >> 7, k = l & 127; x = spW2[k*128+n];
        base = (char*)g_spW2T; off = (size_t)(k >> 6) * 16384 + swzoff(n, (k & 63) * 2);
    } else if (i < 32768) {
        int l = i - 16384; int n = l >> 7, k = l & 127; x = spW3[k*128+n];
        base = (char*)g_spW3T; off = (size_t)(k >> 6) * 16384 + swzoff(n, (k & 63) * 2);
    } else if (i < 98304) {
        int l = i - 32768; int n = l >> 9, k = l & 511; x = vpW1[k*128+n];
        base = (char*)g_vpW1T; off = (size_t)(k >> 6) * 16384 + swzoff(n, (k & 63) * 2);
    } else if (i < 114688) {
        int l = i - 98304; int n = l >> 7, k = l & 127; x = vpW2[k*128+n];
        base = (char*)g_vpW2T; off = (size_t)(k >> 6) * 16384 + swzoff(n, (k & 63) * 2);
    } else if (i < 442368) {
        int l = i - 114688; int n = l / 640, k = l - n * 640; x = jW[(size_t)k*512+n];
        int nb = n >> 8, nl = n & 255;
        base = (char*)g_joinT; off = ((size_t)nb * 10 + (k >> 6)) * 32768 + swzoff(nl, (k & 63) * 2);
    } else if (i < 966656) {
        int l = i - 442368; int e = l >> 17, rm = l & 131071; int n = rm >> 9, k = rm & 511;
        x = cW1[(size_t)e*131072 + (size_t)k*256 + n];
        base = (char*)g_cW1T; off = ((size_t)e * 8 + (k >> 6)) * 32768 + swzoff(n, (k & 63) * 2);
    } else if (i < 1228800) {
        int l = i - 966656; int e = l >> 16, rm = l & 65535; int n = rm >> 8, k = rm & 255;
        x = cW2[(size_t)e*65536 + (size_t)k*256 + n];
        base = (char*)g_cW2T; off = ((size_t)e * 4 + (k >> 6)) * 32768 + swzoff(n, (k & 63) * 2);
    } else return;
    *(__half*)(base + off) = __float2half_rn(x);
}

__global__ void k_pis(const float* __restrict__ p) {
    int idx = blockIdx.x * 256 + threadIdx.x;
    int m = idx >> 6, u = idx & 63;
    int ch = u >> 3, ui = u & 7;
    const float* s = p + (size_t)m * 512 + u * 8;
    float4 f0 = *(const float4*)s;
    float4 f1 = *(const float4*)(s + 4);
    float xs[8] = {f0.x, f0.y, f0.z, f0.w, f1.x, f1.y, f1.z, f1.w};
    uint wh[4], wl[4];
#pragma unroll
    for (int q = 0; q < 4; q++) split2h(xs[2*q], xs[2*q+1], wh[q], wl[q]);
    size_t off = ((size_t)(m >> 7) * 8 + ch) * 16384 + swzoff(m & 127, ui * 16);
    *(uint4*)((char*)g_pi_h + off) = make_uint4(wh[0], wh[1], wh[2], wh[3]);
    *(uint4*)((char*)g_pi_l + off) = make_uint4(wl[0], wl[1], wl[2], wl[3]);
}

// ===================== routing =====================
__global__ void k_reset() { if (threadIdx.x < 4) { g_cnt[threadIdx.x] = 0; g_fill[threadIdx.x] = 0; } }
__global__ void k_count(const int* __restrict__ cmd) {
    __shared__ int h[4];
    int tid = threadIdx.x;
    if (tid < 4) h[tid] = 0;
    __syncthreads();
    int i = blockIdx.x * 256 + tid;
    if (i < B_TOT) atomicAdd(&h[cmd[i] & 3], 1);
    __syncthreads();
    if (tid < 4) atomicAdd(&g_cnt[tid], h[tid]);
}
__global__ void k_seg() {
    if (threadIdx.x == 0) {
        int off = 0;
        for (int e = 0; e < 4; e++) { g_seg[e] = off; off += (g_cnt[e] + 127) & ~127; }
        g_seg[4] = off;
    }
}
__global__ void k_scatter(const int* __restrict__ cmd) {
    __shared__ int h[4], base[4];
    int tid = threadIdx.x;
    if (tid < 4) h[tid] = 0;
    __syncthreads();
    int i = blockIdx.x * 256 + tid;
    int e = 0, loc = 0;
    if (i < B_TOT) { e = cmd[i] & 3; loc = atomicAdd(&h[e], 1); }
    __syncthreads();
    if (tid < 4) base[tid] = atomicAdd(&g_fill[tid], h[tid]);
    __syncthreads();
    if (i < B_TOT) g_idx[g_seg[e] + base[e] + loc] = i;
}

// ===================== k_sp: 1 -> 128 -> 128 -> 128 =====================
#define SP_SMEM 164384

__global__ void __launch_bounds__(512) k_sp(
    const float* __restrict__ speed,
    const float* __restrict__ W1, const float* __restrict__ b1,
    const float* __restrict__ b2, const float* __restrict__ b3)
{
    extern __shared__ char sm[];
    uint sb = smem_u32(sm);
    int tid = threadIdx.x, wid = tid >> 5;
    int wm = (wid & 7) * 16, wn = (wid >> 3) * 64;
    size_t m0 = (size_t)blockIdx.x * 128;
    uint mbar = sb + 164352;
    float* ss = (float*)(sm + 163840);
    if (tid == 0) MBAR_INIT(mbar, 1);
    if (tid < 128) ss[tid] = speed[m0 + tid];
    __syncthreads();
    if (tid == 0) { MBAR_EXPECT(mbar, 32768); bulk_g2s(sb + 131072, g_spW2T, 32768, mbar); }

    for (int u = tid; u < 8192; u += 512) {
        int r = u >> 6, c = (u & 63) * 2;
        float sv = ss[r];
        float v0 = fmaxf(fmaf(sv, __ldg(W1 + c),     __ldg(b1 + c)),     0.f);
        float v1 = fmaxf(fmaf(sv, __ldg(W1 + c + 1), __ldg(b1 + c + 1)), 0.f);
        uint ph, pl; split2h(v0, v1, ph, pl);
        uint off = (uint)(c >> 6) * 32768 + swzoff(r, (c & 63) * 2);
        *(uint*)(sm + off) = ph;
        *(uint*)(sm + 16384 + off) = pl;
    }
    __syncthreads();
    MBAR_WAIT(mbar, 0);

    float acc[8][4];
    acc_zero(acc);
    gemm_swz<8>(acc, sb + 0,     sb + 16384, sb + 131072,         wm, wn);
    gemm_swz<8>(acc, sb + 32768, sb + 49152, sb + 131072 + 16384, wm, wn);
    __syncthreads();
    if (tid == 0) { MBAR_EXPECT(mbar, 32768); bulk_g2s(sb + 131072, g_spW3T, 32768, mbar); }
    epi_tiled<8>(acc, sm + 65536, sm + 65536 + 16384, b2, 0, 0, 32768, wm, wn, true);
    __syncthreads();
    MBAR_WAIT(mbar, 1);

    acc_zero(acc);
    gemm_swz<8>(acc, sb + 65536,         sb + 65536 + 16384, sb + 131072,         wm, wn);
    gemm_swz<8>(acc, sb + 65536 + 32768, sb + 65536 + 49152, sb + 131072 + 16384, wm, wn);
    epi_tiled<8>(acc, (char*)g_v_h + (size_t)blockIdx.x * 2 * 16384,
                      (char*)g_v_l + (size_t)blockIdx.x * 2 * 16384,
                 b3, 0, 0, 16384, wm, wn, false);
}

// ===================== k_join: M=128, N=256, 3-stage bulk pipeline with empty-barriers =====================
// stage: A_h @0, A_l @16384, B @32768 (32KB); 64KB/stage; full mbars @196608, empty @196632
#define JSTG 65536u
#define JOIN_SMEM 196672

__global__ void __launch_bounds__(512) k_join(const float* __restrict__ jb)
{
    extern __shared__ char sm[];
    uint sb = smem_u32(sm);
    int tid = threadIdx.x, wid = tid >> 5;
    int wm = (wid & 7) * 16, wn = (wid >> 3) * 128;
    int bx = blockIdx.x, by = blockIdx.y;
    int N0 = by * 256;
    if (tid == 0) {
#pragma unroll
        for (int s = 0; s < 3; s++) {
            MBAR_INIT(sb + 196608 + s * 8, 1);    // full
            MBAR_INIT(sb + 196632 + s * 8, 16);   // empty (one arrive per warp)
        }
    }
    __syncthreads();

#define J_ISSUE(c, s) do { \
    uint d = sb + (uint)(s) * JSTG; uint m_ = sb + 196608 + (uint)(s) * 8; \
    MBAR_EXPECT(m_, 65536); \
    if ((c) < 8) { \
        size_t t = ((size_t)bx * 8 + (c)) * 16384; \
        bulk_g2s(d,         (char*)g_pi_h + t, 16384, m_); \
        bulk_g2s(d + 16384, (char*)g_pi_l + t, 16384, m_); \
    } else { \
        size_t t = ((size_t)bx * 2 + ((c)-8)) * 16384; \
        bulk_g2s(d,         (char*)g_v_h + t, 16384, m_); \
        bulk_g2s(d + 16384, (char*)g_v_l + t, 16384, m_); \
    } \
    bulk_g2s(d + 32768, (char*)g_joinT + ((size_t)by * 10 + (c)) * 32768, 32768, m_); \
} while (0)

    float acc[16][4];
    acc_zero(acc);
    if (tid == 0) { J_ISSUE(0, 0); J_ISSUE(1, 1); J_ISSUE(2, 2); }
#pragma unroll
    for (int c = 0; c < 10; c++) {
        const int s = c % 3;
        MBAR_WAIT(sb + 196608 + s * 8, (c / 3) & 1);
        gemm_swz<16>(acc, sb + s*JSTG, sb + s*JSTG + 16384, sb + s*JSTG + 32768, wm, wn);
        if ((tid & 31) == 0) MBAR_ARRIVE(sb + 196632 + s * 8);
        if (tid == 0 && c + 3 < 10) {
            MBAR_WAIT(sb + 196632 + s * 8, (c / 3) & 1);
            J_ISSUE(c + 3, s);
        }
    }
#undef J_ISSUE
    epi_tiled<16>(acc,
        (char*)g_jo_h + ((size_t)bx * 8 + (N0 >> 6)) * 16384,
        (char*)g_jo_l + ((size_t)bx * 8 + (N0 >> 6)) * 16384,
        jb, N0, 0, 16384, wm, wn, false);
}

// ===================== k_vp: 512 -> 128 -> 128 -> 1 (3-stage, empty-barriers) =====================
// stages @ s*49152 (A_h, A_l@+16384, B@+32768). After L1: A2 @0 (64KB), W2 @65536 (32KB).
// sv @147456, full mbars @147968, empty @147992
#define VSTG 49152u
#define VP_SMEM 148032

__global__ void __launch_bounds__(512) k_vp(
    const float* __restrict__ b1, const float* __restrict__ b2,
    const float* __restrict__ W3, const float* __restrict__ b3,
    float* __restrict__ out)
{
    extern __shared__ char sm[];
    uint sb = smem_u32(sm);
    int tid = threadIdx.x, wid = tid >> 5;
    int wm = (wid & 7) * 16, wn = (wid >> 3) * 64;
    int bx = blockIdx.x;
    size_t m0 = (size_t)bx * 128;
    float* sv = (float*)(sm + 147456);
    if (tid == 0) {
#pragma unroll
        for (int s = 0; s < 3; s++) {
            MBAR_INIT(sb + 147968 + s * 8, 1);
            MBAR_INIT(sb + 147992 + s * 8, 16);
        }
    }
    if (tid < 128) sv[tid] = 0.f;
    __syncthreads();

#define V_ISSUE(c, s) do { \
    uint d = sb + (uint)(s) * VSTG; uint m_ = sb + 147968 + (uint)(s) * 8; \
    MBAR_EXPECT(m_, 49152); \
    size_t t = ((size_t)bx * 8 + (c)) * 16384; \
    bulk_g2s(d,         (char*)g_pi_h + t, 16384, m_); \
    bulk_g2s(d + 16384, (char*)g_pi_l + t, 16384, m_); \
    bulk_g2s(d + 32768, (char*)g_vpW1T + (size_t)(c) * 16384, 16384, m_); \
} while (0)

    float acc[8][4];
    acc_zero(acc);
    if (tid == 0) { V_ISSUE(0, 0); V_ISSUE(1, 1); V_ISSUE(2, 2); }
#pragma unroll
    for (int c = 0; c < 8; c++) {
        const int s = c % 3;
        MBAR_WAIT(sb + 147968 + s * 8, (c / 3) & 1);
        gemm_swz<8>(acc, sb + s*VSTG, sb + s*VSTG + 16384, sb + s*VSTG + 32768, wm, wn);
        if ((tid & 31) == 0) MBAR_ARRIVE(sb + 147992 + s * 8);
        if (tid == 0 && c + 3 < 8) {
            MBAR_WAIT(sb + 147992 + s * 8, (c / 3) & 1);
            V_ISSUE(c + 3, s);
        }
    }
#undef V_ISSUE
    __syncthreads();   // all warps done with stage buffers before A2 overlay
    // W2 bulk into @65536 (stage region, drained). full[0] next phase idx = 3 -> parity 1.
    if (tid == 0) { MBAR_EXPECT(sb + 147968, 32768); bulk_g2s(sb + 65536, g_vpW2T, 32768, sb + 147968); }
    epi_tiled<8>(acc, sm, sm + 16384, b1, 0, 0, 32768, wm, wn, true);
    __syncthreads();
    MBAR_WAIT(sb + 147968, 1);

    acc_zero(acc);
    gemm_swz<8>(acc, sb + 0,     sb + 16384, sb + 65536,         wm, wn);
    gemm_swz<8>(acc, sb + 32768, sb + 49152, sb + 65536 + 16384, wm, wn);

    {
        int lane = tid & 31;
#pragma unroll
        for (int h = 0; h < 2; h++) {
            int r = wm + h * 8 + (lane >> 2);
            float s = 0.f;
#pragma unroll
            for (int nt = 0; nt < 8; nt++) {
                int c = wn + nt * 8 + (lane & 3) * 2;
                float v0 = fmaxf(acc[nt][h*2]   + __ldg(b2 + c),     0.f);
                float v1 = fmaxf(acc[nt][h*2+1] + __ldg(b2 + c + 1), 0.f);
                s += v0 * __ldg(W3 + c) + v1 * __ldg(W3 + c + 1);
            }
            s += __shfl_xor_sync(0xFFFFFFFF, s, 1);
            s += __shfl_xor_sync(0xFFFFFFFF, s, 2);
            if ((lane & 3) == 0) atomicAdd(&sv[r], s);
        }
    }
    __syncthreads();
    if (tid < 128) out[m0 + tid] = sv[tid] + __ldg(b3);
}

// ===================== k_ctrl: routed 512 -> 256 -> 256 -> 3 (M=128, N=256) =====================
// L1 stages: s*65536 (A gather + bulk B). A2 overlay @0. L2 B stages @131072+s*32768.
// ridx @196608, sact @197120, full mbars @198656, L2-empty @198672
#define CTRL_SMEM 198720

__global__ void __launch_bounds__(512) k_ctrl(
    const float* __restrict__ b1, const float* __restrict__ b2,
    const float* __restrict__ W3, const float* __restrict__ b3,
    float* __restrict__ out)
{
    int p0 = blockIdx.x * 128;
    int s1 = g_seg[1], s2 = g_seg[2], s3 = g_seg[3], s4 = g_seg[4];
    if (p0 >= s4) return;
    int e, segb;
    if (p0 < s1)      { e = 0; segb = 0; }
    else if (p0 < s2) { e = 1; segb = s1; }
    else if (p0 < s3) { e = 2; segb = s2; }
    else              { e = 3; segb = s3; }
    int cnt = g_cnt[e];

    extern __shared__ char sm[];
    uint sb = smem_u32(sm);
    int tid = threadIdx.x, wid = tid >> 5;
    int wm = (wid & 7) * 16, wn = (wid >> 3) * 128;
    int* ridx = (int*)(sm + 196608);
    float* sact = (float*)(sm + 197120);
    uint mb[2] = {sb + 198656, sb + 198664};
    uint me[2] = {sb + 198672, sb + 198680};
    if (tid == 0) {
        MBAR_INIT(mb[0], 1); MBAR_INIT(mb[1], 1);
        MBAR_INIT(me[0], 16); MBAR_INIT(me[1], 16);
    }
    if (tid < 128) {
        int local = p0 - segb + tid;
        ridx[tid] = (local < cnt) ? g_idx[p0 + tid] : -1;
        sact[tid] = 0.f; sact[128 + tid] = 0.f; sact[256 + tid] = 0.f;
    }
    __syncthreads();

    const float* b1e = b1 + e * 256;
    const float* b2e = b2 + e * 256;
    const float* w3e = W3 + e * 768;

#define C1_ISSUE(c, s) do { \
    uint d = sb + (uint)(s) * 65536u; \
    if (tid == 0) { \
        MBAR_EXPECT(mb[s], 32768); \
        bulk_g2s(d + 32768, (char*)g_cW1T + ((size_t)e * 8 + (c)) * 32768, 32768, mb[s]); \
    } \
    for (int u = tid; u < 2048; u += 512) { \
        int pl_ = u >> 10, rem = u & 1023, rl = rem >> 3, un = rem & 7; \
        int src = ridx[rl]; if (src < 0) src = 0; \
        size_t so = ((size_t)(src >> 7) * 8 + (c)) * 16384 \
                  + (size_t)((src & 127) * 128 + ((un * 16) ^ ((src & 7) << 4))); \
        uint dd = d + (uint)pl_ * 16384u + swzoff(rl, un * 16); \
        cpa16(dd, (pl_ ? (char*)g_jo_l : (char*)g_jo_h) + so); \
    } \
    CPA_COMMIT(); \
} while (0)

    float acc[16][4];
    acc_zero(acc);
    C1_ISSUE(0, 0); C1_ISSUE(1, 1);
    int par[2] = {0, 0};
    for (int c = 0; c < 8; c++) {
        int s = c & 1;
        if (c < 7) CPA_WAIT1(); else CPA_WAIT0();
        MBAR_WAIT(mb[s], par[s]); par[s] ^= 1;
        __syncthreads();
        gemm_swz<16>(acc, sb + s*65536u, sb + s*65536u + 16384, sb + s*65536u + 32768, wm, wn);
        __syncthreads();
        if (c + 2 < 8) C1_ISSUE(c + 2, s);
    }
#undef C1_ISSUE

    epi_tiled<16>(acc, sm, sm + 16384, b1e, 0, 0, 32768, wm, wn, true);
    __syncthreads();

    // L2: A2 smem, B bulk 2-stage with empty barriers (no per-chunk CTA sync)
#define C2_ISSUE(c, s) do { \
    MBAR_EXPECT(mb[s], 32768); \
    bulk_g2s(sb + 131072u + (uint)(s) * 32768u, \
             (char*)g_cW2T + ((size_t)e * 4 + (c)) * 32768, 32768, mb[s]); \
} while (0)
    acc_zero(acc);
    if (tid == 0) { C2_ISSUE(0, 0); C2_ISSUE(1, 1); }
#pragma unroll
    for (int c = 0; c < 4; c++) {
        const int s = c & 1;
        MBAR_WAIT(mb[s], par[s]); par[s] ^= 1;
        gemm_swz<16>(acc, sb + (uint)c * 32768u, sb + (uint)c * 32768u + 16384,
                     sb + 131072u + (uint)s * 32768u, wm, wn);
        if ((tid & 31) == 0) MBAR_ARRIVE(me[s]);
        if (tid == 0 && c + 2 < 4) {
            MBAR_WAIT(me[s], (c / 2) & 1);
            C2_ISSUE(c + 2, s);
        }
    }
#undef C2_ISSUE

    {
        int lane = tid & 31;
#pragma unroll
        for (int h = 0; h < 2; h++) {
            int r = wm + h * 8 + (lane >> 2);
            float a0 = 0.f, a1 = 0.f, a2 = 0.f;
#pragma unroll
            for (int nt = 0; nt < 16; nt++) {
                int c = wn + nt * 8 + (lane & 3) * 2;
                float v0 = fmaxf(acc[nt][h*2]   + __ldg(b2e + c),     0.f);
                float v1 = fmaxf(acc[nt][h*2+1] + __ldg(b2e + c + 1), 0.f);
                a0 += v0 * __ldg(w3e + c*3 + 0) + v1 * __ldg(w3e + (c+1)*3 + 0);
                a1 += v0 * __ldg(w3e + c*3 + 1) + v1 * __ldg(w3e + (c+1)*3 + 1);
                a2 += v0 * __ldg(w3e + c*3 + 2) + v1 * __ldg(w3e + (c+1)*3 + 2);
            }
            a0 += __shfl_xor_sync(0xFFFFFFFF, a0, 1);
            a0 += __shfl_xor_sync(0xFFFFFFFF, a0, 2);
            a1 += __shfl_xor_sync(0xFFFFFFFF, a1, 1);
            a1 += __shfl_xor_sync(0xFFFFFFFF, a1, 2);
            a2 += __shfl_xor_sync(0xFFFFFFFF, a2, 1);
            a2 += __shfl_xor_sync(0xFFFFFFFF, a2, 2);
            if ((lane & 3) == 0) {
                atomicAdd(&sact[r * 3 + 0], a0);
                atomicAdd(&sact[r * 3 + 1], a1);
                atomicAdd(&sact[r * 3 + 2], a2);
            }
        }
    }
    __syncthreads();
    if (tid < 128) {
        int src = ridx[tid];
        if (src >= 0) {
            out[(size_t)B_TOT + (size_t)src * 3 + 0] = sact[tid * 3 + 0] + __ldg(b3 + e * 3 + 0);
            out[(size_t)B_TOT + (size_t)src * 3 + 1] = sact[tid * 3 + 1] + __ldg(b3 + e * 3 + 1);
            out[(size_t)B_TOT + (size_t)src * 3 + 2] = sact[tid * 3 + 2] + __ldg(b3 + e * 3 + 2);
        }
    }
}

// ===================== launcher =====================
extern "C" void kernel_launch(void* const* d_in, const int* in_sizes, int n_in,
                              void* d_out, int out_size)
{
    const float* p_i    = (const float*)d_in[0];
    const float* speed  = (const float*)d_in[1];
    const int*   cmd    = (const int*)d_in[2];
    const float* sp_W1  = (const float*)d_in[3];
    const float* sp_b1  = (const float*)d_in[4];
    const float* sp_W2  = (const float*)d_in[5];
    const float* sp_b2  = (const float*)d_in[6];
    const float* sp_W3  = (const float*)d_in[7];
    const float* sp_b3  = (const float*)d_in[8];
    const float* vp_W1  = (const float*)d_in[9];
    const float* vp_b1  = (const float*)d_in[10];
    const float* vp_W2  = (const float*)d_in[11];
    const float* vp_b2  = (const float*)d_in[12];
    const float* vp_W3  = (const float*)d_in[13];
    const float* vp_b3  = (const float*)d_in[14];
    const float* join_W = (const float*)d_in[15];
    const float* join_b = (const float*)d_in[16];
    const float* c_W1   = (const float*)d_in[17];
    const float* c_b1   = (const float*)d_in[18];
    const float* c_W2   = (const float*)d_in[19];
    const float* c_b2   = (const float*)d_in[20];
    const float* c_W3   = (const float*)d_in[21];
    const float* c_b3   = (const float*)d_in[22];
    float* out = (float*)d_out;

    cudaFuncSetAttribute(k_sp,   cudaFuncAttributeMaxDynamicSharedMemorySize, SP_SMEM);
    cudaFuncSetAttribute(k_join, cudaFuncAttributeMaxDynamicSharedMemorySize, JOIN_SMEM);
    cudaFuncSetAttribute(k_vp,   cudaFuncAttributeMaxDynamicSharedMemorySize, VP_SMEM);
    cudaFuncSetAttribute(k_ctrl, cudaFuncAttributeMaxDynamicSharedMemorySize, CTRL_SMEM);

    k_prep<<<4800, 256>>>(sp_W2, sp_W3, vp_W1, vp_W2, join_W, c_W1, c_W2);
    k_pis<<<8192, 256>>>(p_i);
    k_sp<<<B_TOT / 128, 512, SP_SMEM>>>(speed, sp_W1, sp_b1, sp_b2, sp_b3);
    dim3 jg(B_TOT / 128, 2);
    k_join<<<jg, 512, JOIN_SMEM>>>(join_b);
    k_vp<<<B_TOT / 128, 512, VP_SMEM>>>(vp_b1, vp_b2, vp_W3, vp_b3, out);

    k_reset<<<1, 32>>>();
    k_count<<<B_TOT / 256, 256>>>(cmd);
    k_seg<<<1, 32>>>();
    k_scatter<<<B_TOT / 256, 256>>>(cmd);

    k_ctrl<<<B_TOT / 128 + 4, 512, CTRL_SMEM>>>(c_b1, c_b2, c_W3, c_b3, out);
}

// round 11
// speedup vs baseline: 1.5388x; 1.0729x over previous
#include <cuda_runtime.h>
#include <cuda_fp16.h>

#define B_TOT 32768
typedef unsigned int uint;

// ===================== device scratch (tiled+swizzled planes) =====================
__device__ __half g_spW2T[2*8192],  g_spW3T[2*8192];          // [ch][128x64]
__device__ __half g_vpW1T[8*8192],  g_vpW2T[2*8192];          // [ch][128x64]
__device__ __half g_joinT[(size_t)2*10*16384];                // [nb][ch][256x64]
__device__ __half g_cW1T[(size_t)4*8*16384];                  // [e][ch][256x64]
__device__ __half g_cW2T[(size_t)4*4*16384];                  // [e][ch][256x64]
__device__ __half g_pi_h[(size_t)256*8*8192], g_pi_l[(size_t)256*8*8192];   // [mb][ch][tile]
__device__ __half g_v_h [(size_t)256*2*8192], g_v_l [(size_t)256*2*8192];   // [mb][ch][tile]
__device__ __half g_jo_h[(size_t)256*8*8192], g_jo_l[(size_t)256*8*8192];   // [mb][ch][tile]
__device__ int g_idx[B_TOT + 512];
__device__ int g_cnt[4], g_fill[4], g_seg[5];

// ===================== primitives =====================
__device__ __forceinline__ uint smem_u32(const void* p) {
    uint a;
    asm("{ .reg .u64 t; cvta.to.shared.u64 t, %1; cvt.u32.u64 %0, t; }" : "=r"(a) : "l"(p));
    return a;
}
__device__ __forceinline__ uint swzoff(int r, int cbyte) {
    return (uint)(r * 128 + (cbyte ^ ((r & 7) << 4)));
}
__device__ __forceinline__ void ldm4(uint f[4], uint a) {
    asm volatile("ldmatrix.sync.aligned.m8n8.x4.shared.b16 {%0,%1,%2,%3}, [%4];"
        : "=r"(f[0]), "=r"(f[1]), "=r"(f[2]), "=r"(f[3]) : "r"(a));
}
__device__ __forceinline__ void mma_fp16(float c[4], const uint a[4], const uint b[2]) {
    asm volatile(
        "mma.sync.aligned.m16n8k16.row.col.f32.f16.f16.f32 "
        "{%0,%1,%2,%3}, {%4,%5,%6,%7}, {%8,%9}, {%0,%1,%2,%3};"
        : "+f"(c[0]), "+f"(c[1]), "+f"(c[2]), "+f"(c[3])
        : "r"(a[0]), "r"(a[1]), "r"(a[2]), "r"(a[3]), "r"(b[0]), "r"(b[1]));
}
__device__ __forceinline__ void split2h(float a, float b, uint& ph, uint& pl) {
    __half h0 = __float2half_rn(a), h1 = __float2half_rn(b);
    float r0 = a - __half2float(h0), r1 = b - __half2float(h1);
    __half l0 = __float2half_rn(r0), l1 = __float2half_rn(r1);
    ph = (uint)__half_as_ushort(h0) | ((uint)__half_as_ushort(h1) << 16);
    pl = (uint)__half_as_ushort(l0) | ((uint)__half_as_ushort(l1) << 16);
}
__device__ __forceinline__ void cpa16(uint d, const void* s) {
    asm volatile("cp.async.cg.shared.global [%0], [%1], 16;" :: "r"(d), "l"(s));
}
#define CPA_COMMIT() asm volatile("cp.async.commit_group;" ::: "memory")
#define CPA_WAIT0()  asm volatile("cp.async.wait_group 0;" ::: "memory")
#define CPA_WAIT1()  asm volatile("cp.async.wait_group 1;" ::: "memory")

__device__ __forceinline__ void bulk_g2s(uint dst, const void* src, uint bytes, uint mbar) {
    asm volatile("cp.async.bulk.shared::cluster.global.mbarrier::complete_tx::bytes [%0], [%1], %2, [%3];"
        :: "r"(dst), "l"(src), "r"(bytes), "r"(mbar) : "memory");
}
#define MBAR_INIT(a, c) asm volatile("mbarrier.init.shared.b64 [%0], %1;" :: "r"(a), "r"(c) : "memory")
#define MBAR_EXPECT(a, tx) asm volatile("mbarrier.arrive.expect_tx.shared.b64 _, [%0], %1;" :: "r"(a), "r"(tx) : "memory")
#define MBAR_ARRIVE(a) asm volatile("mbarrier.arrive.shared.b64 _, [%0];" :: "r"(a) : "memory")
#define MBAR_WAIT(mbar_a, par) do { \
    uint _m = (mbar_a); uint _p = (uint)(par); uint _d; \
    asm volatile("{ .reg .pred p; mbarrier.try_wait.parity.acquire.cta.shared::cta.b64 p, [%1], %2; selp.b32 %0, 1, 0, p; }" \
        : "=r"(_d) : "r"(_m), "r"(_p) : "memory"); \
    if (!_d) { \
        asm volatile("{ .reg .pred P1;\nWL_%=:\n mbarrier.try_wait.parity.acquire.cta.shared::cta.b64 P1, [%0], %1, 0x989680;\n @P1 bra.uni WD_%=;\n bra.uni WL_%=;\nWD_%=:\n}" \
            :: "r"(_m), "r"(_p) : "memory"); \
    } \
} while (0)

// ===================== gemm: warp tile 16 x (NT*8), 2-pass (A hi/lo fp16) =====================
template <int NT>
__device__ __forceinline__ void gemm_swz(float (&acc)[NT][4], uint Ah, uint Al, uint Bs, int wm, int wn)
{
    const int lane = threadIdx.x & 31;
    const int ra = (lane & 15) + wm;
    const uint abase = (uint)(ra >> 7) * 16384u + (uint)(ra & 127) * 128u;
    const uint Ath = Ah + abase, Atl = Al + abase;
    const uint ax = (uint)((ra & 7) << 4);
    const int ua = lane >> 4;
    const int rb = (lane & 7) + ((lane >> 4) << 3) + wn;
    const uint Bt = Bs + (uint)rb * 128u;
    const uint bx2 = (uint)((rb & 7) << 4);
    const int ub = (lane >> 3) & 1;
#pragma unroll
    for (int s = 0; s < 4; s++) {
        uint ca = ((uint)((s * 2 + ua) * 16)) ^ ax;
        uint ah4[4], al4[4];
        ldm4(ah4, Ath + ca);
        ldm4(al4, Atl + ca);
        uint cbb = ((uint)((s * 2 + ub) * 16)) ^ bx2;
#pragma unroll
        for (int p = 0; p < NT / 2; p++) {
            uint b4[4];
            ldm4(b4, Bt + (uint)(p * 2048) + cbb);
            mma_fp16(acc[2*p],   ah4, b4);
            mma_fp16(acc[2*p],   al4, b4);
            mma_fp16(acc[2*p+1], ah4, b4 + 2);
            mma_fp16(acc[2*p+1], al4, b4 + 2);
        }
    }
}
template <int NT>
__device__ __forceinline__ void acc_zero(float (&acc)[NT][4]) {
#pragma unroll
    for (int n = 0; n < NT; n++)
#pragma unroll
    for (int q = 0; q < 4; q++) acc[n][q] = 0.f;
}

// ===================== epilogue =====================
template <int NT>
__device__ __forceinline__ void epi_tiled(const float (&acc)[NT][4],
    char* dh, char* dl, const float* bias, int cb,
    size_t tsMb, size_t tsCh, int wm, int wn, bool relu)
{
    int lane = threadIdx.x & 31;
    int rr = wm + (lane >> 2), cc = wn + (lane & 3) * 2;
#pragma unroll
    for (int nt = 0; nt < NT; nt++)
#pragma unroll
    for (int h = 0; h < 2; h++) {
        int r = rr + h * 8, c = cc + nt * 8;
        float v0 = acc[nt][h*2]   + __ldg(bias + cb + c);
        float v1 = acc[nt][h*2+1] + __ldg(bias + cb + c + 1);
        if (relu) { v0 = fmaxf(v0, 0.f); v1 = fmaxf(v1, 0.f); }
        uint ph, pl; split2h(v0, v1, ph, pl);
        size_t off = (size_t)(r >> 7) * tsMb + (size_t)(c >> 6) * tsCh
                   + swzoff(r & 127, (c & 63) * 2);
        *(uint*)(dh + off) = ph;
        *(uint*)(dl + off) = pl;
    }
}

// ===================== weight prep =====================
__global__ void k_prep(const float* spW2, const float* spW3, const float* vpW1, const float* vpW2,
                       const float* jW, const float* cW1, const float* cW2) {
    int i = blockIdx.x * 256 + threadIdx.x;
    float x; char* base; size_t off;
    if (i < 16384) {
        int l = i; int n = l >> 7, k = l & 127; x = spW2[k*128+n];
        base = (char*)g_spW2T; off = (size_t)(k >> 6) * 16384 + swzoff(n, (k & 63) * 2);
    } else if (i < 32768) {
        int l = i - 16384; int n = l >> 7, k = l & 127; x = spW3[k*128+n];
        base = (char*)g_spW3T; off = (size_t)(k >> 6) * 16384 + swzoff(n, (k & 63) * 2);
    } else if (i < 98304) {
        int l = i - 32768; int n = l >> 9, k = l & 511; x = vpW1[k*128+n];
        base = (char*)g_vpW1T; off = (size_t)(k >> 6) * 16384 + swzoff(n, (k & 63) * 2);
    } else if (i < 114688) {
        int l = i - 98304; int n = l >> 7, k = l & 127; x = vpW2[k*128+n];
        base = (char*)g_vpW2T; off = (size_t)(k >> 6) * 16384 + swzoff(n, (k & 63) * 2);
    } else if (i < 442368) {
        int l = i - 114688; int n = l / 640, k = l - n * 640; x = jW[(size_t)k*512+n];
        int nb = n >> 8, nl = n & 255;
        base = (char*)g_joinT; off = ((size_t)nb * 10 + (k >> 6)) * 32768 + swzoff(nl, (k & 63) * 2);
    } else if (i < 966656) {
        int l = i - 442368; int e = l >> 17, rm = l & 131071; int n = rm >> 9, k = rm & 511;
        x = cW1[(size_t)e*131072 + (size_t)k*256 + n];
        base = (char*)g_cW1T; off = ((size_t)e * 8 + (k >> 6)) * 32768 + swzoff(n, (k & 63) * 2);
    } else if (i < 1228800) {
        int l = i - 966656; int e = l >> 16, rm = l & 65535; int n = rm >> 8, k = rm & 255;
        x = cW2[(size_t)e*65536 + (size_t)k*256 + n];
        base = (char*)g_cW2T; off = ((size_t)e * 4 + (k >> 6)) * 32768 + swzoff(n, (k & 63) * 2);
    } else return;
    *(__half*)(base + off) = __float2half_rn(x);
}

__global__ void k_pis(const float* __restrict__ p) {
    int idx = blockIdx.x * 256 + threadIdx.x;
    int m = idx >> 6, u = idx & 63;
    int ch = u >> 3, ui = u & 7;
    const float* s = p + (size_t)m * 512 + u * 8;
    float4 f0 = *(const float4*)s;
    float4 f1 = *(const float4*)(s + 4);
    float xs[8] = {f0.x, f0.y, f0.z, f0.w, f1.x, f1.y, f1.z, f1.w};
    uint wh[4], wl[4];
#pragma unroll
    for (int q = 0; q < 4; q++) split2h(xs[2*q], xs[2*q+1], wh[q], wl[q]);
    size_t off = ((size_t)(m >> 7) * 8 + ch) * 16384 + swzoff(m & 127, ui * 16);
    *(uint4*)((char*)g_pi_h + off) = make_uint4(wh[0], wh[1], wh[2], wh[3]);
    *(uint4*)((char*)g_pi_l + off) = make_uint4(wl[0], wl[1], wl[2], wl[3]);
}

// ===================== routing =====================
__global__ void k_reset() { if (threadIdx.x < 4) { g_cnt[threadIdx.x] = 0; g_fill[threadIdx.x] = 0; } }
__global__ void k_count(const int* __restrict__ cmd) {
    __shared__ int h[4];
    int tid = threadIdx.x;
    if (tid < 4) h[tid] = 0;
    __syncthreads();
    int i = blockIdx.x * 256 + tid;
    if (i < B_TOT) atomicAdd(&h[cmd[i] & 3], 1);
    __syncthreads();
    if (tid < 4) atomicAdd(&g_cnt[tid], h[tid]);
}
__global__ void k_seg() {
    if (threadIdx.x == 0) {
        int off = 0;
        for (int e = 0; e < 4; e++) { g_seg[e] = off; off += (g_cnt[e] + 127) & ~127; }
        g_seg[4] = off;
    }
}
__global__ void k_scatter(const int* __restrict__ cmd) {
    __shared__ int h[4], base[4];
    int tid = threadIdx.x;
    if (tid < 4) h[tid] = 0;
    __syncthreads();
    int i = blockIdx.x * 256 + tid;
    int e = 0, loc = 0;
    if (i < B_TOT) { e = cmd[i] & 3; loc = atomicAdd(&h[e], 1); }
    __syncthreads();
    if (tid < 4) base[tid] = atomicAdd(&g_fill[tid], h[tid]);
    __syncthreads();
    if (i < B_TOT) g_idx[g_seg[e] + base[e] + loc] = i;
}

// ===================== k_sp: 1 -> 128 -> 128 -> 128 =====================
#define SP_SMEM 164384

__global__ void __launch_bounds__(512) k_sp(
    const float* __restrict__ speed,
    const float* __restrict__ W1, const float* __restrict__ b1,
    const float* __restrict__ b2, const float* __restrict__ b3)
{
    extern __shared__ char sm[];
    uint sb = smem_u32(sm);
    int tid = threadIdx.x, wid = tid >> 5;
    int wm = (wid & 7) * 16, wn = (wid >> 3) * 64;
    size_t m0 = (size_t)blockIdx.x * 128;
    uint mbar = sb + 164352;
    float* ss = (float*)(sm + 163840);
    if (tid == 0) MBAR_INIT(mbar, 1);
    if (tid < 128) ss[tid] = speed[m0 + tid];
    __syncthreads();
    if (tid == 0) { MBAR_EXPECT(mbar, 32768); bulk_g2s(sb + 131072, g_spW2T, 32768, mbar); }

    for (int u = tid; u < 8192; u += 512) {
        int r = u >> 6, c = (u & 63) * 2;
        float sv = ss[r];
        float v0 = fmaxf(fmaf(sv, __ldg(W1 + c),     __ldg(b1 + c)),     0.f);
        float v1 = fmaxf(fmaf(sv, __ldg(W1 + c + 1), __ldg(b1 + c + 1)), 0.f);
        uint ph, pl; split2h(v0, v1, ph, pl);
        uint off = (uint)(c >> 6) * 32768 + swzoff(r, (c & 63) * 2);
        *(uint*)(sm + off) = ph;
        *(uint*)(sm + 16384 + off) = pl;
    }
    __syncthreads();
    MBAR_WAIT(mbar, 0);

    float acc[8][4];
    acc_zero(acc);
    gemm_swz<8>(acc, sb + 0,     sb + 16384, sb + 131072,         wm, wn);
    gemm_swz<8>(acc, sb + 32768, sb + 49152, sb + 131072 + 16384, wm, wn);
    __syncthreads();
    if (tid == 0) { MBAR_EXPECT(mbar, 32768); bulk_g2s(sb + 131072, g_spW3T, 32768, mbar); }
    epi_tiled<8>(acc, sm + 65536, sm + 65536 + 16384, b2, 0, 0, 32768, wm, wn, true);
    __syncthreads();
    MBAR_WAIT(mbar, 1);

    acc_zero(acc);
    gemm_swz<8>(acc, sb + 65536,         sb + 65536 + 16384, sb + 131072,         wm, wn);
    gemm_swz<8>(acc, sb + 65536 + 32768, sb + 65536 + 49152, sb + 131072 + 16384, wm, wn);
    epi_tiled<8>(acc, (char*)g_v_h + (size_t)blockIdx.x * 2 * 16384,
                      (char*)g_v_l + (size_t)blockIdx.x * 2 * 16384,
                 b3, 0, 0, 16384, wm, wn, false);
}

// ===================== k_join: M=128, N=128, 2 CTAs/SM, 2-stage bulk pipeline =====================
// stage: A_h @0 (16KB), A_l @16384, B(128x64) @32768 (16KB); 48KB/stage; 2 stages
// full mbars @98304, empty @98320
#define JSTG 49152u
#define JOIN_SMEM 98368

__global__ void __launch_bounds__(512, 2) k_join(const float* __restrict__ jb)
{
    extern __shared__ char sm[];
    uint sb = smem_u32(sm);
    int tid = threadIdx.x, wid = tid >> 5;
    int wm = (wid & 7) * 16, wn = (wid >> 3) * 64;
    int nb = blockIdx.x;           // N-block 0..3 (fast dim -> co-resident share A)
    int bm = blockIdx.y;           // M-tile  0..255
    int N0 = nb * 128;
    if (tid == 0) {
#pragma unroll
        for (int s = 0; s < 2; s++) {
            MBAR_INIT(sb + 98304 + s * 8, 1);    // full
            MBAR_INIT(sb + 98320 + s * 8, 16);   // empty
        }
    }
    __syncthreads();

#define J_ISSUE(c, s) do { \
    uint d = sb + (uint)(s) * JSTG; uint m_ = sb + 98304 + (uint)(s) * 8; \
    MBAR_EXPECT(m_, 49152); \
    if ((c) < 8) { \
        size_t t = ((size_t)bm * 8 + (c)) * 16384; \
        bulk_g2s(d,         (char*)g_pi_h + t, 16384, m_); \
        bulk_g2s(d + 16384, (char*)g_pi_l + t, 16384, m_); \
    } else { \
        size_t t = ((size_t)bm * 2 + ((c)-8)) * 16384; \
        bulk_g2s(d,         (char*)g_v_h + t, 16384, m_); \
        bulk_g2s(d + 16384, (char*)g_v_l + t, 16384, m_); \
    } \
    bulk_g2s(d + 32768, \
             (char*)g_joinT + ((size_t)(N0 >> 8) * 10 + (c)) * 32768 + (size_t)(N0 & 255) * 128, \
             16384, m_); \
} while (0)

    float acc[8][4];
    acc_zero(acc);
    if (tid == 0) { J_ISSUE(0, 0); J_ISSUE(1, 1); }
#pragma unroll
    for (int c = 0; c < 10; c++) {
        const int s = c & 1;
        MBAR_WAIT(sb + 98304 + s * 8, (c >> 1) & 1);
        gemm_swz<8>(acc, sb + s*JSTG, sb + s*JSTG + 16384, sb + s*JSTG + 32768, wm, wn);
        if ((tid & 31) == 0) MBAR_ARRIVE(sb + 98320 + s * 8);
        if (tid == 0 && c + 2 < 10) {
            MBAR_WAIT(sb + 98320 + s * 8, (c >> 1) & 1);
            J_ISSUE(c + 2, s);
        }
    }
#undef J_ISSUE
    epi_tiled<8>(acc,
        (char*)g_jo_h + ((size_t)bm * 8 + (N0 >> 6)) * 16384,
        (char*)g_jo_l + ((size_t)bm * 8 + (N0 >> 6)) * 16384,
        jb, N0, 0, 16384, wm, wn, false);
}

// ===================== k_vp: 512 -> 128 -> 128 -> 1 (3-stage, empty-barriers) =====================
#define VSTG 49152u
#define VP_SMEM 148032

__global__ void __launch_bounds__(512) k_vp(
    const float* __restrict__ b1, const float* __restrict__ b2,
    const float* __restrict__ W3, const float* __restrict__ b3,
    float* __restrict__ out)
{
    extern __shared__ char sm[];
    uint sb = smem_u32(sm);
    int tid = threadIdx.x, wid = tid >> 5;
    int wm = (wid & 7) * 16, wn = (wid >> 3) * 64;
    int bx = blockIdx.x;
    size_t m0 = (size_t)bx * 128;
    float* sv = (float*)(sm + 147456);
    if (tid == 0) {
#pragma unroll
        for (int s = 0; s < 3; s++) {
            MBAR_INIT(sb + 147968 + s * 8, 1);
            MBAR_INIT(sb + 147992 + s * 8, 16);
        }
    }
    if (tid < 128) sv[tid] = 0.f;
    __syncthreads();

#define V_ISSUE(c, s) do { \
    uint d = sb + (uint)(s) * VSTG; uint m_ = sb + 147968 + (uint)(s) * 8; \
    MBAR_EXPECT(m_, 49152); \
    size_t t = ((size_t)bx * 8 + (c)) * 16384; \
    bulk_g2s(d,         (char*)g_pi_h + t, 16384, m_); \
    bulk_g2s(d + 16384, (char*)g_pi_l + t, 16384, m_); \
    bulk_g2s(d + 32768, (char*)g_vpW1T + (size_t)(c) * 16384, 16384, m_); \
} while (0)

    float acc[8][4];
    acc_zero(acc);
    if (tid == 0) { V_ISSUE(0, 0); V_ISSUE(1, 1); V_ISSUE(2, 2); }
#pragma unroll
    for (int c = 0; c < 8; c++) {
        const int s = c % 3;
        MBAR_WAIT(sb + 147968 + s * 8, (c / 3) & 1);
        gemm_swz<8>(acc, sb + s*VSTG, sb + s*VSTG + 16384, sb + s*VSTG + 32768, wm, wn);
        if ((tid & 31) == 0) MBAR_ARRIVE(sb + 147992 + s * 8);
        if (tid == 0 && c + 3 < 8) {
            MBAR_WAIT(sb + 147992 + s * 8, (c / 3) & 1);
            V_ISSUE(c + 3, s);
        }
    }
#undef V_ISSUE
    __syncthreads();
    if (tid == 0) { MBAR_EXPECT(sb + 147968, 32768); bulk_g2s(sb + 65536, g_vpW2T, 32768, sb + 147968); }
    epi_tiled<8>(acc, sm, sm + 16384, b1, 0, 0, 32768, wm, wn, true);
    __syncthreads();
    MBAR_WAIT(sb + 147968, 1);

    acc_zero(acc);
    gemm_swz<8>(acc, sb + 0,     sb + 16384, sb + 65536,         wm, wn);
    gemm_swz<8>(acc, sb + 32768, sb + 49152, sb + 65536 + 16384, wm, wn);

    {
        int lane = tid & 31;
#pragma unroll
        for (int h = 0; h < 2; h++) {
            int r = wm + h * 8 + (lane >> 2);
            float s = 0.f;
#pragma unroll
            for (int nt = 0; nt < 8; nt++) {
                int c = wn + nt * 8 + (lane & 3) * 2;
                float v0 = fmaxf(acc[nt][h*2]   + __ldg(b2 + c),     0.f);
                float v1 = fmaxf(acc[nt][h*2+1] + __ldg(b2 + c + 1), 0.f);
                s += v0 * __ldg(W3 + c) + v1 * __ldg(W3 + c + 1);
            }
            s += __shfl_xor_sync(0xFFFFFFFF, s, 1);
            s += __shfl_xor_sync(0xFFFFFFFF, s, 2);
            if ((lane & 3) == 0) atomicAdd(&sv[r], s);
        }
    }
    __syncthreads();
    if (tid < 128) out[m0 + tid] = sv[tid] + __ldg(b3);
}

// ===================== k_ctrl: routed 512 -> 256 -> 256 -> 3 (M=128, N=256) =====================
#define CTRL_SMEM 198720

__global__ void __launch_bounds__(512) k_ctrl(
    const float* __restrict__ b1, const float* __restrict__ b2,
    const float* __restrict__ W3, const float* __restrict__ b3,
    float* __restrict__ out)
{
    int p0 = blockIdx.x * 128;
    int s1 = g_seg[1], s2 = g_seg[2], s3 = g_seg[3], s4 = g_seg[4];
    if (p0 >= s4) return;
    int e, segb;
    if (p0 < s1)      { e = 0; segb = 0; }
    else if (p0 < s2) { e = 1; segb = s1; }
    else if (p0 < s3) { e = 2; segb = s2; }
    else              { e = 3; segb = s3; }
    int cnt = g_cnt[e];

    extern __shared__ char sm[];
    uint sb = smem_u32(sm);
    int tid = threadIdx.x, wid = tid >> 5;
    int wm = (wid & 7) * 16, wn = (wid >> 3) * 128;
    int* ridx = (int*)(sm + 196608);
    float* sact = (float*)(sm + 197120);
    uint mb[2] = {sb + 198656, sb + 198664};
    uint me[2] = {sb + 198672, sb + 198680};
    if (tid == 0) {
        MBAR_INIT(mb[0], 1); MBAR_INIT(mb[1], 1);
        MBAR_INIT(me[0], 16); MBAR_INIT(me[1], 16);
    }
    if (tid < 128) {
        int local = p0 - segb + tid;
        ridx[tid] = (local < cnt) ? g_idx[p0 + tid] : -1;
        sact[tid] = 0.f; sact[128 + tid] = 0.f; sact[256 + tid] = 0.f;
    }
    __syncthreads();

    const float* b1e = b1 + e * 256;
    const float* b2e = b2 + e * 256;
    const float* w3e = W3 + e * 768;

#define C1_ISSUE(c, s) do { \
    uint d = sb + (uint)(s) * 65536u; \
    if (tid == 0) { \
        MBAR_EXPECT(mb[s], 32768); \
        bulk_g2s(d + 32768, (char*)g_cW1T + ((size_t)e * 8 + (c)) * 32768, 32768, mb[s]); \
    } \
    for (int u = tid; u < 2048; u += 512) { \
        int pl_ = u >> 10, rem = u & 1023, rl = rem >> 3, un = rem & 7; \
        int src = ridx[rl]; if (src < 0) src = 0; \
        size_t so = ((size_t)(src >> 7) * 8 + (c)) * 16384 \
                  + (size_t)((src & 127) * 128 + ((un * 16) ^ ((src & 7) << 4))); \
        uint dd = d + (uint)pl_ * 16384u + swzoff(rl, un * 16); \
        cpa16(dd, (pl_ ? (char*)g_jo_l : (char*)g_jo_h) + so); \
    } \
    CPA_COMMIT(); \
} while (0)

    float acc[16][4];
    acc_zero(acc);
    C1_ISSUE(0, 0); C1_ISSUE(1, 1);
    int par[2] = {0, 0};
    for (int c = 0; c < 8; c++) {
        int s = c & 1;
        if (c < 7) CPA_WAIT1(); else CPA_WAIT0();
        MBAR_WAIT(mb[s], par[s]); par[s] ^= 1;
        __syncthreads();
        gemm_swz<16>(acc, sb + s*65536u, sb + s*65536u + 16384, sb + s*65536u + 32768, wm, wn);
        __syncthreads();
        if (c + 2 < 8) C1_ISSUE(c + 2, s);
    }
#undef C1_ISSUE

    epi_tiled<16>(acc, sm, sm + 16384, b1e, 0, 0, 32768, wm, wn, true);
    __syncthreads();

#define C2_ISSUE(c, s) do { \
    MBAR_EXPECT(mb[s], 32768); \
    bulk_g2s(sb + 131072u + (uint)(s) * 32768u, \
             (char*)g_cW2T + ((size_t)e * 4 + (c)) * 32768, 32768, mb[s]); \
} while (0)
    acc_zero(acc);
    if (tid == 0) { C2_ISSUE(0, 0); C2_ISSUE(1, 1); }
#pragma unroll
    for (int c = 0; c < 4; c++) {
        const int s = c & 1;
        MBAR_WAIT(mb[s], par[s]); par[s] ^= 1;
        gemm_swz<16>(acc, sb + (uint)c * 32768u, sb + (uint)c * 32768u + 16384,
                     sb + 131072u + (uint)s * 32768u, wm, wn);
        if ((tid & 31) == 0) MBAR_ARRIVE(me[s]);
        if (tid == 0 && c + 2 < 4) {
            MBAR_WAIT(me[s], (c / 2) & 1);
            C2_ISSUE(c + 2, s);
        }
    }
#undef C2_ISSUE

    {
        int lane = tid & 31;
#pragma unroll
        for (int h = 0; h < 2; h++) {
            int r = wm + h * 8 + (lane >> 2);
            float a0 = 0.f, a1 = 0.f, a2 = 0.f;
#pragma unroll
            for (int nt = 0; nt < 16; nt++) {
                int c = wn + nt * 8 + (lane & 3) * 2;
                float v0 = fmaxf(acc[nt][h*2]   + __ldg(b2e + c),     0.f);
                float v1 = fmaxf(acc[nt][h*2+1] + __ldg(b2e + c + 1), 0.f);
                a0 += v0 * __ldg(w3e + c*3 + 0) + v1 * __ldg(w3e + (c+1)*3 + 0);
                a1 += v0 * __ldg(w3e + c*3 + 1) + v1 * __ldg(w3e + (c+1)*3 + 1);
                a2 += v0 * __ldg(w3e + c*3 + 2) + v1 * __ldg(w3e + (c+1)*3 + 2);
            }
            a0 += __shfl_xor_sync(0xFFFFFFFF, a0, 1);
            a0 += __shfl_xor_sync(0xFFFFFFFF, a0, 2);
            a1 += __shfl_xor_sync(0xFFFFFFFF, a1, 1);
            a1 += __shfl_xor_sync(0xFFFFFFFF, a1, 2);
            a2 += __shfl_xor_sync(0xFFFFFFFF, a2, 1);
            a2 += __shfl_xor_sync(0xFFFFFFFF, a2, 2);
            if ((lane & 3) == 0) {
                atomicAdd(&sact[r * 3 + 0], a0);
                atomicAdd(&sact[r * 3 + 1], a1);
                atomicAdd(&sact[r * 3 + 2], a2);
            }
        }
    }
    __syncthreads();
    if (tid < 128) {
        int src = ridx[tid];
        if (src >= 0) {
            out[(size_t)B_TOT + (size_t)src * 3 + 0] = sact[tid * 3 + 0] + __ldg(b3 + e * 3 + 0);
            out[(size_t)B_TOT + (size_t)src * 3 + 1] = sact[tid * 3 + 1] + __ldg(b3 + e * 3 + 1);
            out[(size_t)B_TOT + (size_t)src * 3 + 2] = sact[tid * 3 + 2] + __ldg(b3 + e * 3 + 2);
        }
    }
}

// ===================== launcher =====================
extern "C" void kernel_launch(void* const* d_in, const int* in_sizes, int n_in,
                              void* d_out, int out_size)
{
    const float* p_i    = (const float*)d_in[0];
    const float* speed  = (const float*)d_in[1];
    const int*   cmd    = (const int*)d_in[2];
    const float* sp_W1  = (const float*)d_in[3];
    const float* sp_b1  = (const float*)d_in[4];
    const float* sp_W2  = (const float*)d_in[5];
    const float* sp_b2  = (const float*)d_in[6];
    const float* sp_W3  = (const float*)d_in[7];
    const float* sp_b3  = (const float*)d_in[8];
    const float* vp_W1  = (const float*)d_in[9];
    const float* vp_b1  = (const float*)d_in[10];
    const float* vp_W2  = (const float*)d_in[11];
    const float* vp_b2  = (const float*)d_in[12];
    const float* vp_W3  = (const float*)d_in[13];
    const float* vp_b3  = (const float*)d_in[14];
    const float* join_W = (const float*)d_in[15];
    const float* join_b = (const float*)d_in[16];
    const float* c_W1   = (const float*)d_in[17];
    const float* c_b1   = (const float*)d_in[18];
    const float* c_W2   = (const float*)d_in[19];
    const float* c_b2   = (const float*)d_in[20];
    const float* c_W3   = (const float*)d_in[21];
    const float* c_b3   = (const float*)d_in[22];
    float* out = (float*)d_out;

    cudaFuncSetAttribute(k_sp,   cudaFuncAttributeMaxDynamicSharedMemorySize, SP_SMEM);
    cudaFuncSetAttribute(k_join, cudaFuncAttributeMaxDynamicSharedMemorySize, JOIN_SMEM);
    cudaFuncSetAttribute(k_vp,   cudaFuncAttributeMaxDynamicSharedMemorySize, VP_SMEM);
    cudaFuncSetAttribute(k_ctrl, cudaFuncAttributeMaxDynamicSharedMemorySize, CTRL_SMEM);

    k_prep<<<4800, 256>>>(sp_W2, sp_W3, vp_W1, vp_W2, join_W, c_W1, c_W2);
    k_pis<<<8192, 256>>>(p_i);
    k_sp<<<B_TOT / 128, 512, SP_SMEM>>>(speed, sp_W1, sp_b1, sp_b2, sp_b3);
    dim3 jg(4, B_TOT / 128);
    k_join<<<jg, 512, JOIN_SMEM>>>(join_b);
    k_vp<<<B_TOT / 128, 512, VP_SMEM>>>(vp_b1, vp_b2, vp_W3, vp_b3, out);

    k_reset<<<1, 32>>>();
    k_count<<<B_TOT / 256, 256>>>(cmd);
    k_seg<<<1, 32>>>();
    k_scatter<<<B_TOT / 256, 256>>>(cmd);

    k_ctrl<<<B_TOT / 128 + 4, 512, CTRL_SMEM>>>(c_b1, c_b2, c_W3, c_b3, out);
}

// round 12
// speedup vs baseline: 1.5613x; 1.0146x over previous
#include <cuda_runtime.h>
#include <cuda_fp16.h>

#define B_TOT 32768
typedef unsigned int uint;

// ===================== device scratch (tiled+swizzled planes) =====================
__device__ __half g_spW2T[2*8192],  g_spW3T[2*8192];          // [ch][128x64]
__device__ __half g_vpW1T[8*8192],  g_vpW2T[2*8192];          // [ch][128x64]
__device__ __half g_joinT[(size_t)2*10*16384];                // [nb][ch][256x64]
__device__ __half g_cW1T[(size_t)4*8*16384];                  // [e][ch][256x64]
__device__ __half g_cW2T[(size_t)4*4*16384];                  // [e][ch][256x64]
__device__ __half g_pi_h[(size_t)256*8*8192], g_pi_l[(size_t)256*8*8192];   // [mb][ch][tile]
__device__ __half g_v_h [(size_t)256*2*8192], g_v_l [(size_t)256*2*8192];   // [mb][ch][tile]
__device__ __half g_jo_h[(size_t)256*8*8192], g_jo_l[(size_t)256*8*8192];   // [mb][ch][tile]
__device__ int g_idx[B_TOT + 512];
__device__ int g_cnt[4], g_fill[4], g_seg[5];

// ===================== primitives =====================
__device__ __forceinline__ uint smem_u32(const void* p) {
    uint a;
    asm("{ .reg .u64 t; cvta.to.shared.u64 t, %1; cvt.u32.u64 %0, t; }" : "=r"(a) : "l"(p));
    return a;
}
__device__ __forceinline__ uint swzoff(int r, int cbyte) {
    return (uint)(r * 128 + (cbyte ^ ((r & 7) << 4)));
}
__device__ __forceinline__ void ldm4(uint f[4], uint a) {
    asm volatile("ldmatrix.sync.aligned.m8n8.x4.shared.b16 {%0,%1,%2,%3}, [%4];"
        : "=r"(f[0]), "=r"(f[1]), "=r"(f[2]), "=r"(f[3]) : "r"(a));
}
__device__ __forceinline__ void mma_fp16(float c[4], const uint a[4], const uint b[2]) {
    asm volatile(
        "mma.sync.aligned.m16n8k16.row.col.f32.f16.f16.f32 "
        "{%0,%1,%2,%3}, {%4,%5,%6,%7}, {%8,%9}, {%0,%1,%2,%3};"
        : "+f"(c[0]), "+f"(c[1]), "+f"(c[2]), "+f"(c[3])
        : "r"(a[0]), "r"(a[1]), "r"(a[2]), "r"(a[3]), "r"(b[0]), "r"(b[1]));
}
__device__ __forceinline__ void split2h(float a, float b, uint& ph, uint& pl) {
    __half h0 = __float2half_rn(a), h1 = __float2half_rn(b);
    float r0 = a - __half2float(h0), r1 = b - __half2float(h1);
    __half l0 = __float2half_rn(r0), l1 = __float2half_rn(r1);
    ph = (uint)__half_as_ushort(h0) | ((uint)__half_as_ushort(h1) << 16);
    pl = (uint)__half_as_ushort(l0) | ((uint)__half_as_ushort(l1) << 16);
}
__device__ __forceinline__ void cpa16(uint d, const void* s) {
    asm volatile("cp.async.cg.shared.global [%0], [%1], 16;" :: "r"(d), "l"(s));
}
#define CPA_COMMIT() asm volatile("cp.async.commit_group;" ::: "memory")
#define CPA_WAIT0()  asm volatile("cp.async.wait_group 0;" ::: "memory")
#define CPA_WAIT1()  asm volatile("cp.async.wait_group 1;" ::: "memory")

__device__ __forceinline__ void bulk_g2s(uint dst, const void* src, uint bytes, uint mbar) {
    asm volatile("cp.async.bulk.shared::cluster.global.mbarrier::complete_tx::bytes [%0], [%1], %2, [%3];"
        :: "r"(dst), "l"(src), "r"(bytes), "r"(mbar) : "memory");
}
#define MBAR_INIT(a, c) asm volatile("mbarrier.init.shared.b64 [%0], %1;" :: "r"(a), "r"(c) : "memory")
#define MBAR_EXPECT(a, tx) asm volatile("mbarrier.arrive.expect_tx.shared.b64 _, [%0], %1;" :: "r"(a), "r"(tx) : "memory")
#define MBAR_ARRIVE(a) asm volatile("mbarrier.arrive.shared.b64 _, [%0];" :: "r"(a) : "memory")
#define MBAR_WAIT(mbar_a, par) do { \
    uint _m = (mbar_a); uint _p = (uint)(par); uint _d; \
    asm volatile("{ .reg .pred p; mbarrier.try_wait.parity.acquire.cta.shared::cta.b64 p, [%1], %2; selp.b32 %0, 1, 0, p; }" \
        : "=r"(_d) : "r"(_m), "r"(_p) : "memory"); \
    if (!_d) { \
        asm volatile("{ .reg .pred P1;\nWL_%=:\n mbarrier.try_wait.parity.acquire.cta.shared::cta.b64 P1, [%0], %1, 0x989680;\n @P1 bra.uni WD_%=;\n bra.uni WL_%=;\nWD_%=:\n}" \
            :: "r"(_m), "r"(_p) : "memory"); \
    } \
} while (0)

// ===================== gemm: warp tile 16 x (NT*8), 2-pass (A hi/lo fp16) =====================
template <int NT>
__device__ __forceinline__ void gemm_swz(float (&acc)[NT][4], uint Ah, uint Al, uint Bs, int wm, int wn)
{
    const int lane = threadIdx.x & 31;
    const int ra = (lane & 15) + wm;
    const uint abase = (uint)(ra >> 7) * 16384u + (uint)(ra & 127) * 128u;
    const uint Ath = Ah + abase, Atl = Al + abase;
    const uint ax = (uint)((ra & 7) << 4);
    const int ua = lane >> 4;
    const int rb = (lane & 7) + ((lane >> 4) << 3) + wn;
    const uint Bt = Bs + (uint)rb * 128u;
    const uint bx2 = (uint)((rb & 7) << 4);
    const int ub = (lane >> 3) & 1;
#pragma unroll
    for (int s = 0; s < 4; s++) {
        uint ca = ((uint)((s * 2 + ua) * 16)) ^ ax;
        uint ah4[4], al4[4];
        ldm4(ah4, Ath + ca);
        ldm4(al4, Atl + ca);
        uint cbb = ((uint)((s * 2 + ub) * 16)) ^ bx2;
#pragma unroll
        for (int p = 0; p < NT / 2; p++) {
            uint b4[4];
            ldm4(b4, Bt + (uint)(p * 2048) + cbb);
            mma_fp16(acc[2*p],   ah4, b4);
            mma_fp16(acc[2*p],   al4, b4);
            mma_fp16(acc[2*p+1], ah4, b4 + 2);
            mma_fp16(acc[2*p+1], al4, b4 + 2);
        }
    }
}
template <int NT>
__device__ __forceinline__ void acc_zero(float (&acc)[NT][4]) {
#pragma unroll
    for (int n = 0; n < NT; n++)
#pragma unroll
    for (int q = 0; q < 4; q++) acc[n][q] = 0.f;
}

// ===================== epilogue =====================
template <int NT>
__device__ __forceinline__ void epi_tiled(const float (&acc)[NT][4],
    char* dh, char* dl, const float* bias, int cb,
    size_t tsMb, size_t tsCh, int wm, int wn, bool relu)
{
    int lane = threadIdx.x & 31;
    int rr = wm + (lane >> 2), cc = wn + (lane & 3) * 2;
#pragma unroll
    for (int nt = 0; nt < NT; nt++)
#pragma unroll
    for (int h = 0; h < 2; h++) {
        int r = rr + h * 8, c = cc + nt * 8;
        float v0 = acc[nt][h*2]   + __ldg(bias + cb + c);
        float v1 = acc[nt][h*2+1] + __ldg(bias + cb + c + 1);
        if (relu) { v0 = fmaxf(v0, 0.f); v1 = fmaxf(v1, 0.f); }
        uint ph, pl; split2h(v0, v1, ph, pl);
        size_t off = (size_t)(r >> 7) * tsMb + (size_t)(c >> 6) * tsCh
                   + swzoff(r & 127, (c & 63) * 2);
        *(uint*)(dh + off) = ph;
        *(uint*)(dl + off) = pl;
    }
}

// ===================== weight prep =====================
__global__ void k_prep(const float* spW2, const float* spW3, const float* vpW1, const float* vpW2,
                       const float* jW, const float* cW1, const float* cW2) {
    int i = blockIdx.x * 256 + threadIdx.x;
    float x; char* base; size_t off;
    if (i < 16384) {
        int l = i; int n = l >> 7, k = l & 127; x = spW2[k*128+n];
        base = (char*)g_spW2T; off = (size_t)(k >> 6) * 16384 + swzoff(n, (k & 63) * 2);
    } else if (i < 32768) {
        int l = i - 16384; int n = l >> 7, k = l & 127; x = spW3[k*128+n];
        base = (char*)g_spW3T; off = (size_t)(k >> 6) * 16384 + swzoff(n, (k & 63) * 2);
    } else if (i < 98304) {
        int l = i - 32768; int n = l >> 9, k = l & 511; x = vpW1[k*128+n];
        base = (char*)g_vpW1T; off = (size_t)(k >> 6) * 16384 + swzoff(n, (k & 63) * 2);
    } else if (i < 114688) {
        int l = i - 98304; int n = l >> 7, k = l & 127; x = vpW2[k*128+n];
        base = (char*)g_vpW2T; off = (size_t)(k >> 6) * 16384 + swzoff(n, (k & 63) * 2);
    } else if (i < 442368) {
        int l = i - 114688; int n = l / 640, k = l - n * 640; x = jW[(size_t)k*512+n];
        int nb = n >> 8, nl = n & 255;
        base = (char*)g_joinT; off = ((size_t)nb * 10 + (k >> 6)) * 32768 + swzoff(nl, (k & 63) * 2);
    } else if (i < 966656) {
        int l = i - 442368; int e = l >> 17, rm = l & 131071; int n = rm >> 9, k = rm & 511;
        x = cW1[(size_t)e*131072 + (size_t)k*256 + n];
        base = (char*)g_cW1T; off = ((size_t)e * 8 + (k >> 6)) * 32768 + swzoff(n, (k & 63) * 2);
    } else if (i < 1228800) {
        int l = i - 966656; int e = l >> 16, rm = l & 65535; int n = rm >> 8, k = rm & 255;
        x = cW2[(size_t)e*65536 + (size_t)k*256 + n];
        base = (char*)g_cW2T; off = ((size_t)e * 4 + (k >> 6)) * 32768 + swzoff(n, (k & 63) * 2);
    } else return;
    *(__half*)(base + off) = __float2half_rn(x);
}

__global__ void k_pis(const float* __restrict__ p) {
    int idx = blockIdx.x * 256 + threadIdx.x;
    int m = idx >> 6, u = idx & 63;
    int ch = u >> 3, ui = u & 7;
    const float* s = p + (size_t)m * 512 + u * 8;
    float4 f0 = *(const float4*)s;
    float4 f1 = *(const float4*)(s + 4);
    float xs[8] = {f0.x, f0.y, f0.z, f0.w, f1.x, f1.y, f1.z, f1.w};
    uint wh[4], wl[4];
#pragma unroll
    for (int q = 0; q < 4; q++) split2h(xs[2*q], xs[2*q+1], wh[q], wl[q]);
    size_t off = ((size_t)(m >> 7) * 8 + ch) * 16384 + swzoff(m & 127, ui * 16);
    *(uint4*)((char*)g_pi_h + off) = make_uint4(wh[0], wh[1], wh[2], wh[3]);
    *(uint4*)((char*)g_pi_l + off) = make_uint4(wl[0], wl[1], wl[2], wl[3]);
}

// ===================== routing =====================
__global__ void k_reset() { if (threadIdx.x < 4) { g_cnt[threadIdx.x] = 0; g_fill[threadIdx.x] = 0; } }
__global__ void k_count(const int* __restrict__ cmd) {
    __shared__ int h[4];
    int tid = threadIdx.x;
    if (tid < 4) h[tid] = 0;
    __syncthreads();
    int i = blockIdx.x * 256 + tid;
    if (i < B_TOT) atomicAdd(&h[cmd[i] & 3], 1);
    __syncthreads();
    if (tid < 4) atomicAdd(&g_cnt[tid], h[tid]);
}
__global__ void k_seg() {
    if (threadIdx.x == 0) {
        int off = 0;
        for (int e = 0; e < 4; e++) { g_seg[e] = off; off += (g_cnt[e] + 127) & ~127; }
        g_seg[4] = off;
    }
}
__global__ void k_scatter(const int* __restrict__ cmd) {
    __shared__ int h[4], base[4];
    int tid = threadIdx.x;
    if (tid < 4) h[tid] = 0;
    __syncthreads();
    int i = blockIdx.x * 256 + tid;
    int e = 0, loc = 0;
    if (i < B_TOT) { e = cmd[i] & 3; loc = atomicAdd(&h[e], 1); }
    __syncthreads();
    if (tid < 4) base[tid] = atomicAdd(&g_fill[tid], h[tid]);
    __syncthreads();
    if (i < B_TOT) g_idx[g_seg[e] + base[e] + loc] = i;
}

// ===================== k_sp: 1 -> 128 -> 128 -> 128 =====================
#define SP_SMEM 164384

__global__ void __launch_bounds__(512) k_sp(
    const float* __restrict__ speed,
    const float* __restrict__ W1, const float* __restrict__ b1,
    const float* __restrict__ b2, const float* __restrict__ b3)
{
    extern __shared__ char sm[];
    uint sb = smem_u32(sm);
    int tid = threadIdx.x, wid = tid >> 5;
    int wm = (wid & 7) * 16, wn = (wid >> 3) * 64;
    size_t m0 = (size_t)blockIdx.x * 128;
    uint mbar = sb + 164352;
    float* ss = (float*)(sm + 163840);
    if (tid == 0) MBAR_INIT(mbar, 1);
    if (tid < 128) ss[tid] = speed[m0 + tid];
    __syncthreads();
    if (tid == 0) { MBAR_EXPECT(mbar, 32768); bulk_g2s(sb + 131072, g_spW2T, 32768, mbar); }

    for (int u = tid; u < 8192; u += 512) {
        int r = u >> 6, c = (u & 63) * 2;
        float sv = ss[r];
        float v0 = fmaxf(fmaf(sv, __ldg(W1 + c),     __ldg(b1 + c)),     0.f);
        float v1 = fmaxf(fmaf(sv, __ldg(W1 + c + 1), __ldg(b1 + c + 1)), 0.f);
        uint ph, pl; split2h(v0, v1, ph, pl);
        uint off = (uint)(c >> 6) * 32768 + swzoff(r, (c & 63) * 2);
        *(uint*)(sm + off) = ph;
        *(uint*)(sm + 16384 + off) = pl;
    }
    __syncthreads();
    MBAR_WAIT(mbar, 0);

    float acc[8][4];
    acc_zero(acc);
    gemm_swz<8>(acc, sb + 0,     sb + 16384, sb + 131072,         wm, wn);
    gemm_swz<8>(acc, sb + 32768, sb + 49152, sb + 131072 + 16384, wm, wn);
    __syncthreads();
    if (tid == 0) { MBAR_EXPECT(mbar, 32768); bulk_g2s(sb + 131072, g_spW3T, 32768, mbar); }
    epi_tiled<8>(acc, sm + 65536, sm + 65536 + 16384, b2, 0, 0, 32768, wm, wn, true);
    __syncthreads();
    MBAR_WAIT(mbar, 1);

    acc_zero(acc);
    gemm_swz<8>(acc, sb + 65536,         sb + 65536 + 16384, sb + 131072,         wm, wn);
    gemm_swz<8>(acc, sb + 65536 + 32768, sb + 65536 + 49152, sb + 131072 + 16384, wm, wn);
    epi_tiled<8>(acc, (char*)g_v_h + (size_t)blockIdx.x * 2 * 16384,
                      (char*)g_v_l + (size_t)blockIdx.x * 2 * 16384,
                 b3, 0, 0, 16384, wm, wn, false);
}

// ===================== k_join: M=128, N=128, 2 CTAs/SM, 2-stage bulk pipeline =====================
#define JSTG 49152u
#define JOIN_SMEM 98368

__global__ void __launch_bounds__(512, 2) k_join(const float* __restrict__ jb)
{
    extern __shared__ char sm[];
    uint sb = smem_u32(sm);
    int tid = threadIdx.x, wid = tid >> 5;
    int wm = (wid & 7) * 16, wn = (wid >> 3) * 64;
    int nb = blockIdx.x;
    int bm = blockIdx.y;
    int N0 = nb * 128;
    if (tid == 0) {
#pragma unroll
        for (int s = 0; s < 2; s++) {
            MBAR_INIT(sb + 98304 + s * 8, 1);
            MBAR_INIT(sb + 98320 + s * 8, 16);
        }
    }
    __syncthreads();

#define J_ISSUE(c, s) do { \
    uint d = sb + (uint)(s) * JSTG; uint m_ = sb + 98304 + (uint)(s) * 8; \
    MBAR_EXPECT(m_, 49152); \
    if ((c) < 8) { \
        size_t t = ((size_t)bm * 8 + (c)) * 16384; \
        bulk_g2s(d,         (char*)g_pi_h + t, 16384, m_); \
        bulk_g2s(d + 16384, (char*)g_pi_l + t, 16384, m_); \
    } else { \
        size_t t = ((size_t)bm * 2 + ((c)-8)) * 16384; \
        bulk_g2s(d,         (char*)g_v_h + t, 16384, m_); \
        bulk_g2s(d + 16384, (char*)g_v_l + t, 16384, m_); \
    } \
    bulk_g2s(d + 32768, \
             (char*)g_joinT + ((size_t)(N0 >> 8) * 10 + (c)) * 32768 + (size_t)(N0 & 255) * 128, \
             16384, m_); \
} while (0)

    float acc[8][4];
    acc_zero(acc);
    if (tid == 0) { J_ISSUE(0, 0); J_ISSUE(1, 1); }
#pragma unroll
    for (int c = 0; c < 10; c++) {
        const int s = c & 1;
        MBAR_WAIT(sb + 98304 + s * 8, (c >> 1) & 1);
        gemm_swz<8>(acc, sb + s*JSTG, sb + s*JSTG + 16384, sb + s*JSTG + 32768, wm, wn);
        if ((tid & 31) == 0) MBAR_ARRIVE(sb + 98320 + s * 8);
        if (tid == 0 && c + 2 < 10) {
            MBAR_WAIT(sb + 98320 + s * 8, (c >> 1) & 1);
            J_ISSUE(c + 2, s);
        }
    }
#undef J_ISSUE
    epi_tiled<8>(acc,
        (char*)g_jo_h + ((size_t)bm * 8 + (N0 >> 6)) * 16384,
        (char*)g_jo_l + ((size_t)bm * 8 + (N0 >> 6)) * 16384,
        jb, N0, 0, 16384, wm, wn, false);
}

// ===================== k_vp: 512 -> 128 -> 128 -> 1 (2-stage, 2 CTAs/SM) =====================
// stages @ s*49152 (A_h, A_l@+16384, B@+32768). After L1: A2 @0 (64KB), W2 @65536 (32KB).
// sv @98304, full mbars @98816, empty @98832
#define VSTG 49152u
#define VP_SMEM 98880

__global__ void __launch_bounds__(512, 2) k_vp(
    const float* __restrict__ b1, const float* __restrict__ b2,
    const float* __restrict__ W3, const float* __restrict__ b3,
    float* __restrict__ out)
{
    extern __shared__ char sm[];
    uint sb = smem_u32(sm);
    int tid = threadIdx.x, wid = tid >> 5;
    int wm = (wid & 7) * 16, wn = (wid >> 3) * 64;
    int bx = blockIdx.x;
    size_t m0 = (size_t)bx * 128;
    float* sv = (float*)(sm + 98304);
    if (tid == 0) {
#pragma unroll
        for (int s = 0; s < 2; s++) {
            MBAR_INIT(sb + 98816 + s * 8, 1);
            MBAR_INIT(sb + 98832 + s * 8, 16);
        }
    }
    if (tid < 128) sv[tid] = 0.f;
    __syncthreads();

#define V_ISSUE(c, s) do { \
    uint d = sb + (uint)(s) * VSTG; uint m_ = sb + 98816 + (uint)(s) * 8; \
    MBAR_EXPECT(m_, 49152); \
    size_t t = ((size_t)bx * 8 + (c)) * 16384; \
    bulk_g2s(d,         (char*)g_pi_h + t, 16384, m_); \
    bulk_g2s(d + 16384, (char*)g_pi_l + t, 16384, m_); \
    bulk_g2s(d + 32768, (char*)g_vpW1T + (size_t)(c) * 16384, 16384, m_); \
} while (0)

    float acc[8][4];
    acc_zero(acc);
    if (tid == 0) { V_ISSUE(0, 0); V_ISSUE(1, 1); }
#pragma unroll
    for (int c = 0; c < 8; c++) {
        const int s = c & 1;
        MBAR_WAIT(sb + 98816 + s * 8, (c >> 1) & 1);
        gemm_swz<8>(acc, sb + s*VSTG, sb + s*VSTG + 16384, sb + s*VSTG + 32768, wm, wn);
        if ((tid & 31) == 0) MBAR_ARRIVE(sb + 98832 + s * 8);
        if (tid == 0 && c + 2 < 8) {
            MBAR_WAIT(sb + 98832 + s * 8, (c >> 1) & 1);
            V_ISSUE(c + 2, s);
        }
    }
#undef V_ISSUE
    __syncthreads();   // drain: all warps done with stage buffers
    // full[0] completed 4 times (c=0,2,4,6) -> next wait parity 0
    if (tid == 0) { MBAR_EXPECT(sb + 98816, 32768); bulk_g2s(sb + 65536, g_vpW2T, 32768, sb + 98816); }
    epi_tiled<8>(acc, sm, sm + 16384, b1, 0, 0, 32768, wm, wn, true);
    __syncthreads();
    MBAR_WAIT(sb + 98816, 0);

    acc_zero(acc);
    gemm_swz<8>(acc, sb + 0,     sb + 16384, sb + 65536,         wm, wn);
    gemm_swz<8>(acc, sb + 32768, sb + 49152, sb + 65536 + 16384, wm, wn);

    {
        int lane = tid & 31;
#pragma unroll
        for (int h = 0; h < 2; h++) {
            int r = wm + h * 8 + (lane >> 2);
            float s = 0.f;
#pragma unroll
            for (int nt = 0; nt < 8; nt++) {
                int c = wn + nt * 8 + (lane & 3) * 2;
                float v0 = fmaxf(acc[nt][h*2]   + __ldg(b2 + c),     0.f);
                float v1 = fmaxf(acc[nt][h*2+1] + __ldg(b2 + c + 1), 0.f);
                s += v0 * __ldg(W3 + c) + v1 * __ldg(W3 + c + 1);
            }
            s += __shfl_xor_sync(0xFFFFFFFF, s, 1);
            s += __shfl_xor_sync(0xFFFFFFFF, s, 2);
            if ((lane & 3) == 0) atomicAdd(&sv[r], s);
        }
    }
    __syncthreads();
    if (tid < 128) out[m0 + tid] = sv[tid] + __ldg(b3);
}

// ===================== k_ctrl: routed 512 -> 256 -> 256 -> 3 (M=64, N=256, 2 CTAs/SM) =====================
// L1 stages: s*49152: A_h@0 (8KB gather), A_l@8192, B@16384 (32KB bulk). 2 stages = 96KB.
// A2 overlay @0: 4 chunks x (hi 8KB + lo 8KB) = 64KB. L2 B single buf @65536 (32KB).
// ridx @98304 (256B), sact @98560 (768B), full mbars @99328, empty @99344
#define CSTG 49152u
#define CTRL_SMEM 99392

__global__ void __launch_bounds__(512, 2) k_ctrl(
    const float* __restrict__ b1, const float* __restrict__ b2,
    const float* __restrict__ W3, const float* __restrict__ b3,
    float* __restrict__ out)
{
    int p0 = blockIdx.x * 64;
    int s1 = g_seg[1], s2 = g_seg[2], s3 = g_seg[3], s4 = g_seg[4];
    if (p0 >= s4) return;
    int e, segb;
    if (p0 < s1)      { e = 0; segb = 0; }
    else if (p0 < s2) { e = 1; segb = s1; }
    else if (p0 < s3) { e = 2; segb = s2; }
    else              { e = 3; segb = s3; }
    int cnt = g_cnt[e];

    extern __shared__ char sm[];
    uint sb = smem_u32(sm);
    int tid = threadIdx.x, wid = tid >> 5;
    int wm = (wid & 3) * 16, wn = (wid >> 2) * 64;
    int* ridx = (int*)(sm + 98304);
    float* sact = (float*)(sm + 98560);
    uint mb[2] = {sb + 99328, sb + 99336};
    uint me[2] = {sb + 99344, sb + 99352};
    if (tid == 0) {
        MBAR_INIT(mb[0], 1); MBAR_INIT(mb[1], 1);
        MBAR_INIT(me[0], 16); MBAR_INIT(me[1], 16);
    }
    if (tid < 64) {
        int local = p0 - segb + tid;
        ridx[tid] = (local < cnt) ? g_idx[p0 + tid] : -1;
    }
    if (tid < 192) sact[tid] = 0.f;
    __syncthreads();

    const float* b1e = b1 + e * 256;
    const float* b2e = b2 + e * 256;
    const float* w3e = W3 + e * 768;

    // L1: tid0 bulk B (32KB) + all threads gather A (64 rows x 2 planes)
#define C1_ISSUE(c, s) do { \
    uint d = sb + (uint)(s) * CSTG; \
    if (tid == 0) { \
        MBAR_EXPECT(mb[s], 32768); \
        bulk_g2s(d + 16384, (char*)g_cW1T + ((size_t)e * 8 + (c)) * 32768, 32768, mb[s]); \
    } \
    for (int u = tid; u < 1024; u += 512) { \
        int pl_ = u >> 9, rem = u & 511, rl = rem >> 3, un = rem & 7; \
        int src = ridx[rl]; if (src < 0) src = 0; \
        size_t so = ((size_t)(src >> 7) * 8 + (c)) * 16384 \
                  + (size_t)((src & 127) * 128 + ((un * 16) ^ ((src & 7) << 4))); \
        uint dd = d + (uint)pl_ * 8192u + swzoff(rl, un * 16); \
        cpa16(dd, (pl_ ? (char*)g_jo_l : (char*)g_jo_h) + so); \
    } \
    CPA_COMMIT(); \
} while (0)

    float acc[8][4];
    acc_zero(acc);
    C1_ISSUE(0, 0); C1_ISSUE(1, 1);
    int par[2] = {0, 0};
    for (int c = 0; c < 8; c++) {
        int s = c & 1;
        if (c < 7) CPA_WAIT1(); else CPA_WAIT0();
        MBAR_WAIT(mb[s], par[s]); par[s] ^= 1;
        __syncthreads();
        gemm_swz<8>(acc, sb + s*CSTG, sb + s*CSTG + 8192, sb + s*CSTG + 16384, wm, wn);
        __syncthreads();
        if (c + 2 < 8) C1_ISSUE(c + 2, s);
    }
#undef C1_ISSUE

    // h1 -> A2 smem tiles (4 k-chunks x (hi 8KB + lo 8KB))
    epi_tiled<8>(acc, sm, sm + 8192, b1e, 0, 0, 16384, wm, wn, true);
    __syncthreads();

    // L2: A2 smem, B single-buffered bulk @65536
#define C2_ISSUE(c, s) do { \
    MBAR_EXPECT(mb[s], 32768); \
    bulk_g2s(sb + 65536u, (char*)g_cW2T + ((size_t)e * 4 + (c)) * 32768, 32768, mb[s]); \
} while (0)
    acc_zero(acc);
    if (tid == 0) C2_ISSUE(0, 0);
#pragma unroll
    for (int c = 0; c < 4; c++) {
        const int s = c & 1;
        MBAR_WAIT(mb[s], par[s]); par[s] ^= 1;
        gemm_swz<8>(acc, sb + (uint)c * 16384u, sb + (uint)c * 16384u + 8192,
                    sb + 65536u, wm, wn);
        if ((tid & 31) == 0) MBAR_ARRIVE(me[0]);
        if (tid == 0 && c + 1 < 4) {
            MBAR_WAIT(me[0], c & 1);
            C2_ISSUE(c + 1, (c + 1) & 1);
        }
    }
#undef C2_ISSUE

    // final: relu(h2 + b2) @ W3, quad-reduce, scatter
    {
        int lane = tid & 31;
#pragma unroll
        for (int h = 0; h < 2; h++) {
            int r = wm + h * 8 + (lane >> 2);
            float a0 = 0.f, a1 = 0.f, a2 = 0.f;
#pragma unroll
            for (int nt = 0; nt < 8; nt++) {
                int c = wn + nt * 8 + (lane & 3) * 2;
                float v0 = fmaxf(acc[nt][h*2]   + __ldg(b2e + c),     0.f);
                float v1 = fmaxf(acc[nt][h*2+1] + __ldg(b2e + c + 1), 0.f);
                a0 += v0 * __ldg(w3e + c*3 + 0) + v1 * __ldg(w3e + (c+1)*3 + 0);
                a1 += v0 * __ldg(w3e + c*3 + 1) + v1 * __ldg(w3e + (c+1)*3 + 1);
                a2 += v0 * __ldg(w3e + c*3 + 2) + v1 * __ldg(w3e + (c+1)*3 + 2);
            }
            a0 += __shfl_xor_sync(0xFFFFFFFF, a0, 1);
            a0 += __shfl_xor_sync(0xFFFFFFFF, a0, 2);
            a1 += __shfl_xor_sync(0xFFFFFFFF, a1, 1);
            a1 += __shfl_xor_sync(0xFFFFFFFF, a1, 2);
            a2 += __shfl_xor_sync(0xFFFFFFFF, a2, 1);
            a2 += __shfl_xor_sync(0xFFFFFFFF, a2, 2);
            if ((lane & 3) == 0) {
                atomicAdd(&sact[r * 3 + 0], a0);
                atomicAdd(&sact[r * 3 + 1], a1);
                atomicAdd(&sact[r * 3 + 2], a2);
            }
        }
    }
    __syncthreads();
    if (tid < 64) {
        int src = ridx[tid];
        if (src >= 0) {
            out[(size_t)B_TOT + (size_t)src * 3 + 0] = sact[tid * 3 + 0] + __ldg(b3 + e * 3 + 0);
            out[(size_t)B_TOT + (size_t)src * 3 + 1] = sact[tid * 3 + 1] + __ldg(b3 + e * 3 + 1);
            out[(size_t)B_TOT + (size_t)src * 3 + 2] = sact[tid * 3 + 2] + __ldg(b3 + e * 3 + 2);
        }
    }
}

// ===================== launcher =====================
extern "C" void kernel_launch(void* const* d_in, const int* in_sizes, int n_in,
                              void* d_out, int out_size)
{
    const float* p_i    = (const float*)d_in[0];
    const float* speed  = (const float*)d_in[1];
    const int*   cmd    = (const int*)d_in[2];
    const float* sp_W1  = (const float*)d_in[3];
    const float* sp_b1  = (const float*)d_in[4];
    const float* sp_W2  = (const float*)d_in[5];
    const float* sp_b2  = (const float*)d_in[6];
    const float* sp_W3  = (const float*)d_in[7];
    const float* sp_b3  = (const float*)d_in[8];
    const float* vp_W1  = (const float*)d_in[9];
    const float* vp_b1  = (const float*)d_in[10];
    const float* vp_W2  = (const float*)d_in[11];
    const float* vp_b2  = (const float*)d_in[12];
    const float* vp_W3  = (const float*)d_in[13];
    const float* vp_b3  = (const float*)d_in[14];
    const float* join_W = (const float*)d_in[15];
    const float* join_b = (const float*)d_in[16];
    const float* c_W1   = (const float*)d_in[17];
    const float* c_b1   = (const float*)d_in[18];
    const float* c_W2   = (const float*)d_in[19];
    const float* c_b2   = (const float*)d_in[20];
    const float* c_W3   = (const float*)d_in[21];
    const float* c_b3   = (const float*)d_in[22];
    float* out = (float*)d_out;

    cudaFuncSetAttribute(k_sp,   cudaFuncAttributeMaxDynamicSharedMemorySize, SP_SMEM);
    cudaFuncSetAttribute(k_join, cudaFuncAttributeMaxDynamicSharedMemorySize, JOIN_SMEM);
    cudaFuncSetAttribute(k_vp,   cudaFuncAttributeMaxDynamicSharedMemorySize, VP_SMEM);
    cudaFuncSetAttribute(k_ctrl, cudaFuncAttributeMaxDynamicSharedMemorySize, CTRL_SMEM);

    k_prep<<<4800, 256>>>(sp_W2, sp_W3, vp_W1, vp_W2, join_W, c_W1, c_W2);
    k_pis<<<8192, 256>>>(p_i);
    k_sp<<<B_TOT / 128, 512, SP_SMEM>>>(speed, sp_W1, sp_b1, sp_b2, sp_b3);
    dim3 jg(4, B_TOT / 128);
    k_join<<<jg, 512, JOIN_SMEM>>>(join_b);
    k_vp<<<B_TOT / 128, 512, VP_SMEM>>>(vp_b1, vp_b2, vp_W3, vp_b3, out);

    k_reset<<<1, 32>>>();
    k_count<<<B_TOT / 256, 256>>>(cmd);
    k_seg<<<1, 32>>>();
    k_scatter<<<B_TOT / 256, 256>>>(cmd);

    k_ctrl<<<B_TOT / 64 + 8, 512, CTRL_SMEM>>>(c_b1, c_b2, c_W3, c_b3, out);
}

// round 13
// speedup vs baseline: 1.6622x; 1.0647x over previous
#include <cuda_runtime.h>
#include <cuda_fp16.h>

#define B_TOT 32768
typedef unsigned int uint;

// ===================== device scratch (tiled+swizzled planes) =====================
__device__ __half g_spW2T[2*8192],  g_spW3T[2*8192];
__device__ __half g_vpW1T[8*8192],  g_vpW2T[2*8192];
__device__ __half g_joinT[(size_t)2*10*16384];
__device__ __half g_cW1T[(size_t)4*8*16384];
__device__ __half g_cW2T[(size_t)4*4*16384];
__device__ __half g_pi_h[(size_t)256*8*8192], g_pi_l[(size_t)256*8*8192];
__device__ __half g_v_h [(size_t)256*2*8192], g_v_l [(size_t)256*2*8192];
__device__ __half g_jo_h[(size_t)256*8*8192], g_jo_l[(size_t)256*8*8192];
__device__ int g_idx[B_TOT + 512];
__device__ int g_cnt[4], g_fill[4], g_seg[5];

// ===================== primitives =====================
__device__ __forceinline__ uint smem_u32(const void* p) {
    uint a;
    asm("{ .reg .u64 t; cvta.to.shared.u64 t, %1; cvt.u32.u64 %0, t; }" : "=r"(a) : "l"(p));
    return a;
}
__device__ __forceinline__ uint swzoff(int r, int cbyte) {
    return (uint)(r * 128 + (cbyte ^ ((r & 7) << 4)));
}
__device__ __forceinline__ void ldm4(uint f[4], uint a) {
    asm volatile("ldmatrix.sync.aligned.m8n8.x4.shared.b16 {%0,%1,%2,%3}, [%4];"
        : "=r"(f[0]), "=r"(f[1]), "=r"(f[2]), "=r"(f[3]) : "r"(a));
}
__device__ __forceinline__ void mma_fp16(float c[4], const uint a[4], const uint b[2]) {
    asm volatile(
        "mma.sync.aligned.m16n8k16.row.col.f32.f16.f16.f32 "
        "{%0,%1,%2,%3}, {%4,%5,%6,%7}, {%8,%9}, {%0,%1,%2,%3};"
        : "+f"(c[0]), "+f"(c[1]), "+f"(c[2]), "+f"(c[3])
        : "r"(a[0]), "r"(a[1]), "r"(a[2]), "r"(a[3]), "r"(b[0]), "r"(b[1]));
}
__device__ __forceinline__ void split2h(float a, float b, uint& ph, uint& pl) {
    __half h0 = __float2half_rn(a), h1 = __float2half_rn(b);
    float r0 = a - __half2float(h0), r1 = b - __half2float(h1);
    __half l0 = __float2half_rn(r0), l1 = __float2half_rn(r1);
    ph = (uint)__half_as_ushort(h0) | ((uint)__half_as_ushort(h1) << 16);
    pl = (uint)__half_as_ushort(l0) | ((uint)__half_as_ushort(l1) << 16);
}
__device__ __forceinline__ void cpa16(uint d, const void* s) {
    asm volatile("cp.async.cg.shared.global [%0], [%1], 16;" :: "r"(d), "l"(s));
}
#define CPA_COMMIT() asm volatile("cp.async.commit_group;" ::: "memory")
#define CPA_WAIT0()  asm volatile("cp.async.wait_group 0;" ::: "memory")
#define CPA_WAIT1()  asm volatile("cp.async.wait_group 1;" ::: "memory")

__device__ __forceinline__ void bulk_g2s(uint dst, const void* src, uint bytes, uint mbar) {
    asm volatile("cp.async.bulk.shared::cluster.global.mbarrier::complete_tx::bytes [%0], [%1], %2, [%3];"
        :: "r"(dst), "l"(src), "r"(bytes), "r"(mbar) : "memory");
}
#define MBAR_INIT(a, c) asm volatile("mbarrier.init.shared.b64 [%0], %1;" :: "r"(a), "r"(c) : "memory")
#define MBAR_EXPECT(a, tx) asm volatile("mbarrier.arrive.expect_tx.shared.b64 _, [%0], %1;" :: "r"(a), "r"(tx) : "memory")
#define MBAR_ARRIVE(a) asm volatile("mbarrier.arrive.shared.b64 _, [%0];" :: "r"(a) : "memory")
#define MBAR_WAIT(mbar_a, par) do { \
    uint _m = (mbar_a); uint _p = (uint)(par); uint _d; \
    asm volatile("{ .reg .pred p; mbarrier.try_wait.parity.acquire.cta.shared::cta.b64 p, [%1], %2; selp.b32 %0, 1, 0, p; }" \
        : "=r"(_d) : "r"(_m), "r"(_p) : "memory"); \
    if (!_d) { \
        asm volatile("{ .reg .pred P1;\nWL_%=:\n mbarrier.try_wait.parity.acquire.cta.shared::cta.b64 P1, [%0], %1, 0x989680;\n @P1 bra.uni WD_%=;\n bra.uni WL_%=;\nWD_%=:\n}" \
            :: "r"(_m), "r"(_p) : "memory"); \
    } \
} while (0)

// ===================== gemm: warp tile 16 x (NT*8), 2-pass (A hi/lo fp16) =====================
template <int NT>
__device__ __forceinline__ void gemm_swz(float (&acc)[NT][4], uint Ah, uint Al, uint Bs, int wm, int wn)
{
    const int lane = threadIdx.x & 31;
    const int ra = (lane & 15) + wm;
    const uint abase = (uint)(ra >> 7) * 16384u + (uint)(ra & 127) * 128u;
    const uint Ath = Ah + abase, Atl = Al + abase;
    const uint ax = (uint)((ra & 7) << 4);
    const int ua = lane >> 4;
    const int rb = (lane & 7) + ((lane >> 4) << 3) + wn;
    const uint Bt = Bs + (uint)rb * 128u;
    const uint bx2 = (uint)((rb & 7) << 4);
    const int ub = (lane >> 3) & 1;
#pragma unroll
    for (int s = 0; s < 4; s++) {
        uint ca = ((uint)((s * 2 + ua) * 16)) ^ ax;
        uint ah4[4], al4[4];
        ldm4(ah4, Ath + ca);
        ldm4(al4, Atl + ca);
        uint cbb = ((uint)((s * 2 + ub) * 16)) ^ bx2;
#pragma unroll
        for (int p = 0; p < NT / 2; p++) {
            uint b4[4];
            ldm4(b4, Bt + (uint)(p * 2048) + cbb);
            mma_fp16(acc[2*p],   ah4, b4);
            mma_fp16(acc[2*p],   al4, b4);
            mma_fp16(acc[2*p+1], ah4, b4 + 2);
            mma_fp16(acc[2*p+1], al4, b4 + 2);
        }
    }
}
template <int NT>
__device__ __forceinline__ void acc_zero(float (&acc)[NT][4]) {
#pragma unroll
    for (int n = 0; n < NT; n++)
#pragma unroll
    for (int q = 0; q < 4; q++) acc[n][q] = 0.f;
}

// ===================== epilogue =====================
template <int NT>
__device__ __forceinline__ void epi_tiled(const float (&acc)[NT][4],
    char* dh, char* dl, const float* bias, int cb,
    size_t tsMb, size_t tsCh, int wm, int wn, bool relu)
{
    int lane = threadIdx.x & 31;
    int rr = wm + (lane >> 2), cc = wn + (lane & 3) * 2;
#pragma unroll
    for (int nt = 0; nt < NT; nt++)
#pragma unroll
    for (int h = 0; h < 2; h++) {
        int r = rr + h * 8, c = cc + nt * 8;
        float v0 = acc[nt][h*2]   + __ldg(bias + cb + c);
        float v1 = acc[nt][h*2+1] + __ldg(bias + cb + c + 1);
        if (relu) { v0 = fmaxf(v0, 0.f); v1 = fmaxf(v1, 0.f); }
        uint ph, pl; split2h(v0, v1, ph, pl);
        size_t off = (size_t)(r >> 7) * tsMb + (size_t)(c >> 6) * tsCh
                   + swzoff(r & 127, (c & 63) * 2);
        *(uint*)(dh + off) = ph;
        *(uint*)(dl + off) = pl;
    }
}

// ===================== weight prep =====================
__global__ void k_prep(const float* spW2, const float* spW3, const float* vpW1, const float* vpW2,
                       const float* jW, const float* cW1, const float* cW2) {
    int i = blockIdx.x * 256 + threadIdx.x;
    float x; char* base; size_t off;
    if (i < 16384) {
        int l = i; int n = l >> 7, k = l & 127; x = spW2[k*128+n];
        base = (char*)g_spW2T; off = (size_t)(k >> 6) * 16384 + swzoff(n, (k & 63) * 2);
    } else if (i < 32768) {
        int l = i - 16384; int n = l >> 7, k = l & 127; x = spW3[k*128+n];
        base = (char*)g_spW3T; off = (size_t)(k >> 6) * 16384 + swzoff(n, (k & 63) * 2);
    } else if (i < 98304) {
        int l = i - 32768; int n = l >> 9, k = l & 511; x = vpW1[k*128+n];
        base = (char*)g_vpW1T; off = (size_t)(k >> 6) * 16384 + swzoff(n, (k & 63) * 2);
    } else if (i < 114688) {
        int l = i - 98304; int n = l >> 7, k = l & 127; x = vpW2[k*128+n];
        base = (char*)g_vpW2T; off = (size_t)(k >> 6) * 16384 + swzoff(n, (k & 63) * 2);
    } else if (i < 442368) {
        int l = i - 114688; int n = l / 640, k = l - n * 640; x = jW[(size_t)k*512+n];
        int nb = n >> 8, nl = n & 255;
        base = (char*)g_joinT; off = ((size_t)nb * 10 + (k >> 6)) * 32768 + swzoff(nl, (k & 63) * 2);
    } else if (i < 966656) {
        int l = i - 442368; int e = l >> 17, rm = l & 131071; int n = rm >> 9, k = rm & 511;
        x = cW1[(size_t)e*131072 + (size_t)k*256 + n];
        base = (char*)g_cW1T; off = ((size_t)e * 8 + (k >> 6)) * 32768 + swzoff(n, (k & 63) * 2);
    } else if (i < 1228800) {
        int l = i - 966656; int e = l >> 16, rm = l & 65535; int n = rm >> 8, k = rm & 255;
        x = cW2[(size_t)e*65536 + (size_t)k*256 + n];
        base = (char*)g_cW2T; off = ((size_t)e * 4 + (k >> 6)) * 32768 + swzoff(n, (k & 63) * 2);
    } else return;
    *(__half*)(base + off) = __float2half_rn(x);
}

__global__ void k_pis(const float* __restrict__ p) {
    int idx = blockIdx.x * 256 + threadIdx.x;
    int m = idx >> 6, u = idx & 63;
    int ch = u >> 3, ui = u & 7;
    const float* s = p + (size_t)m * 512 + u * 8;
    float4 f0 = *(const float4*)s;
    float4 f1 = *(const float4*)(s + 4);
    float xs[8] = {f0.x, f0.y, f0.z, f0.w, f1.x, f1.y, f1.z, f1.w};
    uint wh[4], wl[4];
#pragma unroll
    for (int q = 0; q < 4; q++) split2h(xs[2*q], xs[2*q+1], wh[q], wl[q]);
    size_t off = ((size_t)(m >> 7) * 8 + ch) * 16384 + swzoff(m & 127, ui * 16);
    *(uint4*)((char*)g_pi_h + off) = make_uint4(wh[0], wh[1], wh[2], wh[3]);
    *(uint4*)((char*)g_pi_l + off) = make_uint4(wl[0], wl[1], wl[2], wl[3]);
}

// ===================== routing =====================
__global__ void k_reset() { if (threadIdx.x < 4) { g_cnt[threadIdx.x] = 0; g_fill[threadIdx.x] = 0; } }
__global__ void k_count(const int* __restrict__ cmd) {
    __shared__ int h[4];
    int tid = threadIdx.x;
    if (tid < 4) h[tid] = 0;
    __syncthreads();
    int i = blockIdx.x * 256 + tid;
    if (i < B_TOT) atomicAdd(&h[cmd[i] & 3], 1);
    __syncthreads();
    if (tid < 4) atomicAdd(&g_cnt[tid], h[tid]);
}
__global__ void k_seg() {
    if (threadIdx.x == 0) {
        int off = 0;
        for (int e = 0; e < 4; e++) { g_seg[e] = off; off += (g_cnt[e] + 127) & ~127; }
        g_seg[4] = off;
    }
}
__global__ void k_scatter(const int* __restrict__ cmd) {
    __shared__ int h[4], base[4];
    int tid = threadIdx.x;
    if (tid < 4) h[tid] = 0;
    __syncthreads();
    int i = blockIdx.x * 256 + tid;
    int e = 0, loc = 0;
    if (i < B_TOT) { e = cmd[i] & 3; loc = atomicAdd(&h[e], 1); }
    __syncthreads();
    if (tid < 4) base[tid] = atomicAdd(&g_fill[tid], h[tid]);
    __syncthreads();
    if (i < B_TOT) g_idx[g_seg[e] + base[e] + loc] = i;
}

// ===================== k_sp =====================
#define SP_SMEM 164384

__global__ void __launch_bounds__(512) k_sp(
    const float* __restrict__ speed,
    const float* __restrict__ W1, const float* __restrict__ b1,
    const float* __restrict__ b2, const float* __restrict__ b3)
{
    extern __shared__ char sm[];
    uint sb = smem_u32(sm);
    int tid = threadIdx.x, wid = tid >> 5;
    int wm = (wid & 7) * 16, wn = (wid >> 3) * 64;
    size_t m0 = (size_t)blockIdx.x * 128;
    uint mbar = sb + 164352;
    float* ss = (float*)(sm + 163840);
    if (tid == 0) MBAR_INIT(mbar, 1);
    if (tid < 128) ss[tid] = speed[m0 + tid];
    __syncthreads();
    if (tid == 0) { MBAR_EXPECT(mbar, 32768); bulk_g2s(sb + 131072, g_spW2T, 32768, mbar); }

    for (int u = tid; u < 8192; u += 512) {
        int r = u >> 6, c = (u & 63) * 2;
        float sv = ss[r];
        float v0 = fmaxf(fmaf(sv, __ldg(W1 + c),     __ldg(b1 + c)),     0.f);
        float v1 = fmaxf(fmaf(sv, __ldg(W1 + c + 1), __ldg(b1 + c + 1)), 0.f);
        uint ph, pl; split2h(v0, v1, ph, pl);
        uint off = (uint)(c >> 6) * 32768 + swzoff(r, (c & 63) * 2);
        *(uint*)(sm + off) = ph;
        *(uint*)(sm + 16384 + off) = pl;
    }
    __syncthreads();
    MBAR_WAIT(mbar, 0);

    float acc[8][4];
    acc_zero(acc);
    gemm_swz<8>(acc, sb + 0,     sb + 16384, sb + 131072,         wm, wn);
    gemm_swz<8>(acc, sb + 32768, sb + 49152, sb + 131072 + 16384, wm, wn);
    __syncthreads();
    if (tid == 0) { MBAR_EXPECT(mbar, 32768); bulk_g2s(sb + 131072, g_spW3T, 32768, mbar); }
    epi_tiled<8>(acc, sm + 65536, sm + 65536 + 16384, b2, 0, 0, 32768, wm, wn, true);
    __syncthreads();
    MBAR_WAIT(mbar, 1);

    acc_zero(acc);
    gemm_swz<8>(acc, sb + 65536,         sb + 65536 + 16384, sb + 131072,         wm, wn);
    gemm_swz<8>(acc, sb + 65536 + 32768, sb + 65536 + 49152, sb + 131072 + 16384, wm, wn);
    epi_tiled<8>(acc, (char*)g_v_h + (size_t)blockIdx.x * 2 * 16384,
                      (char*)g_v_l + (size_t)blockIdx.x * 2 * 16384,
                 b3, 0, 0, 16384, wm, wn, false);
}

// ===================== k_join =====================
#define JSTG 49152u
#define JOIN_SMEM 98368

__global__ void __launch_bounds__(512, 2) k_join(const float* __restrict__ jb)
{
    extern __shared__ char sm[];
    uint sb = smem_u32(sm);
    int tid = threadIdx.x, wid = tid >> 5;
    int wm = (wid & 7) * 16, wn = (wid >> 3) * 64;
    int nb = blockIdx.x;
    int bm = blockIdx.y;
    int N0 = nb * 128;
    if (tid == 0) {
#pragma unroll
        for (int s = 0; s < 2; s++) {
            MBAR_INIT(sb + 98304 + s * 8, 1);
            MBAR_INIT(sb + 98320 + s * 8, 16);
        }
    }
    __syncthreads();

#define J_ISSUE(c, s) do { \
    uint d = sb + (uint)(s) * JSTG; uint m_ = sb + 98304 + (uint)(s) * 8; \
    MBAR_EXPECT(m_, 49152); \
    if ((c) < 8) { \
        size_t t = ((size_t)bm * 8 + (c)) * 16384; \
        bulk_g2s(d,         (char*)g_pi_h + t, 16384, m_); \
        bulk_g2s(d + 16384, (char*)g_pi_l + t, 16384, m_); \
    } else { \
        size_t t = ((size_t)bm * 2 + ((c)-8)) * 16384; \
        bulk_g2s(d,         (char*)g_v_h + t, 16384, m_); \
        bulk_g2s(d + 16384, (char*)g_v_l + t, 16384, m_); \
    } \
    bulk_g2s(d + 32768, \
             (char*)g_joinT + ((size_t)(N0 >> 8) * 10 + (c)) * 32768 + (size_t)(N0 & 255) * 128, \
             16384, m_); \
} while (0)

    float acc[8][4];
    acc_zero(acc);
    if (tid == 0) { J_ISSUE(0, 0); J_ISSUE(1, 1); }
#pragma unroll
    for (int c = 0; c < 10; c++) {
        const int s = c & 1;
        MBAR_WAIT(sb + 98304 + s * 8, (c >> 1) & 1);
        gemm_swz<8>(acc, sb + s*JSTG, sb + s*JSTG + 16384, sb + s*JSTG + 32768, wm, wn);
        if ((tid & 31) == 0) MBAR_ARRIVE(sb + 98320 + s * 8);
        if (tid == 0 && c + 2 < 10) {
            MBAR_WAIT(sb + 98320 + s * 8, (c >> 1) & 1);
            J_ISSUE(c + 2, s);
        }
    }
#undef J_ISSUE
    epi_tiled<8>(acc,
        (char*)g_jo_h + ((size_t)bm * 8 + (N0 >> 6)) * 16384,
        (char*)g_jo_l + ((size_t)bm * 8 + (N0 >> 6)) * 16384,
        jb, N0, 0, 16384, wm, wn, false);
}

// ===================== k_vp =====================
#define VSTG 49152u
#define VP_SMEM 98880

__global__ void __launch_bounds__(512, 2) k_vp(
    const float* __restrict__ b1, const float* __restrict__ b2,
    const float* __restrict__ W3, const float* __restrict__ b3,
    float* __restrict__ out)
{
    extern __shared__ char sm[];
    uint sb = smem_u32(sm);
    int tid = threadIdx.x, wid = tid >> 5;
    int wm = (wid & 7) * 16, wn = (wid >> 3) * 64;
    int bx = blockIdx.x;
    size_t m0 = (size_t)bx * 128;
    float* sv = (float*)(sm + 98304);
    if (tid == 0) {
#pragma unroll
        for (int s = 0; s < 2; s++) {
            MBAR_INIT(sb + 98816 + s * 8, 1);
            MBAR_INIT(sb + 98832 + s * 8, 16);
        }
    }
    if (tid < 128) sv[tid] = 0.f;
    __syncthreads();

#define V_ISSUE(c, s) do { \
    uint d = sb + (uint)(s) * VSTG; uint m_ = sb + 98816 + (uint)(s) * 8; \
    MBAR_EXPECT(m_, 49152); \
    size_t t = ((size_t)bx * 8 + (c)) * 16384; \
    bulk_g2s(d,         (char*)g_pi_h + t, 16384, m_); \
    bulk_g2s(d + 16384, (char*)g_pi_l + t, 16384, m_); \
    bulk_g2s(d + 32768, (char*)g_vpW1T + (size_t)(c) * 16384, 16384, m_); \
} while (0)

    float acc[8][4];
    acc_zero(acc);
    if (tid == 0) { V_ISSUE(0, 0); V_ISSUE(1, 1); }
#pragma unroll
    for (int c = 0; c < 8; c++) {
        const int s = c & 1;
        MBAR_WAIT(sb + 98816 + s * 8, (c >> 1) & 1);
        gemm_swz<8>(acc, sb + s*VSTG, sb + s*VSTG + 16384, sb + s*VSTG + 32768, wm, wn);
        if ((tid & 31) == 0) MBAR_ARRIVE(sb + 98832 + s * 8);
        if (tid == 0 && c + 2 < 8) {
            MBAR_WAIT(sb + 98832 + s * 8, (c >> 1) & 1);
            V_ISSUE(c + 2, s);
        }
    }
#undef V_ISSUE
    __syncthreads();
    if (tid == 0) { MBAR_EXPECT(sb + 98816, 32768); bulk_g2s(sb + 65536, g_vpW2T, 32768, sb + 98816); }
    epi_tiled<8>(acc, sm, sm + 16384, b1, 0, 0, 32768, wm, wn, true);
    __syncthreads();
    MBAR_WAIT(sb + 98816, 0);

    acc_zero(acc);
    gemm_swz<8>(acc, sb + 0,     sb + 16384, sb + 65536,         wm, wn);
    gemm_swz<8>(acc, sb + 32768, sb + 49152, sb + 65536 + 16384, wm, wn);

    {
        int lane = tid & 31;
#pragma unroll
        for (int h = 0; h < 2; h++) {
            int r = wm + h * 8 + (lane >> 2);
            float s = 0.f;
#pragma unroll
            for (int nt = 0; nt < 8; nt++) {
                int c = wn + nt * 8 + (lane & 3) * 2;
                float v0 = fmaxf(acc[nt][h*2]   + __ldg(b2 + c),     0.f);
                float v1 = fmaxf(acc[nt][h*2+1] + __ldg(b2 + c + 1), 0.f);
                s += v0 * __ldg(W3 + c) + v1 * __ldg(W3 + c + 1);
            }
            s += __shfl_xor_sync(0xFFFFFFFF, s, 1);
            s += __shfl_xor_sync(0xFFFFFFFF, s, 2);
            if ((lane & 3) == 0) atomicAdd(&sv[r], s);
        }
    }
    __syncthreads();
    if (tid < 128) out[m0 + tid] = sv[tid] + __ldg(b3);
}

// ===================== k_ctrl =====================
#define CSTG 49152u
#define CTRL_SMEM 99392

__global__ void __launch_bounds__(512, 2) k_ctrl(
    const float* __restrict__ b1, const float* __restrict__ b2,
    const float* __restrict__ W3, const float* __restrict__ b3,
    float* __restrict__ out)
{
    int p0 = blockIdx.x * 64;
    int s1 = g_seg[1], s2 = g_seg[2], s3 = g_seg[3], s4 = g_seg[4];
    if (p0 >= s4) return;
    int e, segb;
    if (p0 < s1)      { e = 0; segb = 0; }
    else if (p0 < s2) { e = 1; segb = s1; }
    else if (p0 < s3) { e = 2; segb = s2; }
    else              { e = 3; segb = s3; }
    int cnt = g_cnt[e];

    extern __shared__ char sm[];
    uint sb = smem_u32(sm);
    int tid = threadIdx.x, wid = tid >> 5;
    int wm = (wid & 3) * 16, wn = (wid >> 2) * 64;
    int* ridx = (int*)(sm + 98304);
    float* sact = (float*)(sm + 98560);
    uint mb[2] = {sb + 99328, sb + 99336};
    uint me[2] = {sb + 99344, sb + 99352};
    if (tid == 0) {
        MBAR_INIT(mb[0], 1); MBAR_INIT(mb[1], 1);
        MBAR_INIT(me[0], 16); MBAR_INIT(me[1], 16);
    }
    if (tid < 64) {
        int local = p0 - segb + tid;
        ridx[tid] = (local < cnt) ? g_idx[p0 + tid] : -1;
    }
    if (tid < 192) sact[tid] = 0.f;
    __syncthreads();

    const float* b1e = b1 + e * 256;
    const float* b2e = b2 + e * 256;
    const float* w3e = W3 + e * 768;

#define C1_ISSUE(c, s) do { \
    uint d = sb + (uint)(s) * CSTG; \
    if (tid == 0) { \
        MBAR_EXPECT(mb[s], 32768); \
        bulk_g2s(d + 16384, (char*)g_cW1T + ((size_t)e * 8 + (c)) * 32768, 32768, mb[s]); \
    } \
    for (int u = tid; u < 1024; u += 512) { \
        int pl_ = u >> 9, rem = u & 511, rl = rem >> 3, un = rem & 7; \
        int src = ridx[rl]; if (src < 0) src = 0; \
        size_t so = ((size_t)(src >> 7) * 8 + (c)) * 16384 \
                  + (size_t)((src & 127) * 128 + ((un * 16) ^ ((src & 7) << 4))); \
        uint dd = d + (uint)pl_ * 8192u + swzoff(rl, un * 16); \
        cpa16(dd, (pl_ ? (char*)g_jo_l : (char*)g_jo_h) + so); \
    } \
    CPA_COMMIT(); \
} while (0)

    float acc[8][4];
    acc_zero(acc);
    C1_ISSUE(0, 0); C1_ISSUE(1, 1);
    int par[2] = {0, 0};
    for (int c = 0; c < 8; c++) {
        int s = c & 1;
        if (c < 7) CPA_WAIT1(); else CPA_WAIT0();
        MBAR_WAIT(mb[s], par[s]); par[s] ^= 1;
        __syncthreads();
        gemm_swz<8>(acc, sb + s*CSTG, sb + s*CSTG + 8192, sb + s*CSTG + 16384, wm, wn);
        __syncthreads();
        if (c + 2 < 8) C1_ISSUE(c + 2, s);
    }
#undef C1_ISSUE

    epi_tiled<8>(acc, sm, sm + 8192, b1e, 0, 0, 16384, wm, wn, true);
    __syncthreads();

#define C2_ISSUE(c, s) do { \
    MBAR_EXPECT(mb[s], 32768); \
    bulk_g2s(sb + 65536u, (char*)g_cW2T + ((size_t)e * 4 + (c)) * 32768, 32768, mb[s]); \
} while (0)
    acc_zero(acc);
    if (tid == 0) C2_ISSUE(0, 0);
#pragma unroll
    for (int c = 0; c < 4; c++) {
        const int s = c & 1;
        MBAR_WAIT(mb[s], par[s]); par[s] ^= 1;
        gemm_swz<8>(acc, sb + (uint)c * 16384u, sb + (uint)c * 16384u + 8192,
                    sb + 65536u, wm, wn);
        if ((tid & 31) == 0) MBAR_ARRIVE(me[0]);
        if (tid == 0 && c + 1 < 4) {
            MBAR_WAIT(me[0], c & 1);
            C2_ISSUE(c + 1, (c + 1) & 1);
        }
    }
#undef C2_ISSUE

    {
        int lane = tid & 31;
#pragma unroll
        for (int h = 0; h < 2; h++) {
            int r = wm + h * 8 + (lane >> 2);
            float a0 = 0.f, a1 = 0.f, a2 = 0.f;
#pragma unroll
            for (int nt = 0; nt < 8; nt++) {
                int c = wn + nt * 8 + (lane & 3) * 2;
                float v0 = fmaxf(acc[nt][h*2]   + __ldg(b2e + c),     0.f);
                float v1 = fmaxf(acc[nt][h*2+1] + __ldg(b2e + c + 1), 0.f);
                a0 += v0 * __ldg(w3e + c*3 + 0) + v1 * __ldg(w3e + (c+1)*3 + 0);
                a1 += v0 * __ldg(w3e + c*3 + 1) + v1 * __ldg(w3e + (c+1)*3 + 1);
                a2 += v0 * __ldg(w3e + c*3 + 2) + v1 * __ldg(w3e + (c+1)*3 + 2);
            }
            a0 += __shfl_xor_sync(0xFFFFFFFF, a0, 1);
            a0 += __shfl_xor_sync(0xFFFFFFFF, a0, 2);
            a1 += __shfl_xor_sync(0xFFFFFFFF, a1, 1);
            a1 += __shfl_xor_sync(0xFFFFFFFF, a1, 2);
            a2 += __shfl_xor_sync(0xFFFFFFFF, a2, 1);
            a2 += __shfl_xor_sync(0xFFFFFFFF, a2, 2);
            if ((lane & 3) == 0) {
                atomicAdd(&sact[r * 3 + 0], a0);
                atomicAdd(&sact[r * 3 + 1], a1);
                atomicAdd(&sact[r * 3 + 2], a2);
            }
        }
    }
    __syncthreads();
    if (tid < 64) {
        int src = ridx[tid];
        if (src >= 0) {
            out[(size_t)B_TOT + (size_t)src * 3 + 0] = sact[tid * 3 + 0] + __ldg(b3 + e * 3 + 0);
            out[(size_t)B_TOT + (size_t)src * 3 + 1] = sact[tid * 3 + 1] + __ldg(b3 + e * 3 + 1);
            out[(size_t)B_TOT + (size_t)src * 3 + 2] = sact[tid * 3 + 2] + __ldg(b3 + e * 3 + 2);
        }
    }
}

// ===================== launcher (multi-stream fork/join) =====================
extern "C" void kernel_launch(void* const* d_in, const int* in_sizes, int n_in,
                              void* d_out, int out_size)
{
    const float* p_i    = (const float*)d_in[0];
    const float* speed  = (const float*)d_in[1];
    const int*   cmd    = (const int*)d_in[2];
    const float* sp_W1  = (const float*)d_in[3];
    const float* sp_b1  = (const float*)d_in[4];
    const float* sp_W2  = (const float*)d_in[5];
    const float* sp_b2  = (const float*)d_in[6];
    const float* sp_W3  = (const float*)d_in[7];
    const float* sp_b3  = (const float*)d_in[8];
    const float* vp_W1  = (const float*)d_in[9];
    const float* vp_b1  = (const float*)d_in[10];
    const float* vp_W2  = (const float*)d_in[11];
    const float* vp_b2  = (const float*)d_in[12];
    const float* vp_W3  = (const float*)d_in[13];
    const float* vp_b3  = (const float*)d_in[14];
    const float* join_W = (const float*)d_in[15];
    const float* join_b = (const float*)d_in[16];
    const float* c_W1   = (const float*)d_in[17];
    const float* c_b1   = (const float*)d_in[18];
    const float* c_W2   = (const float*)d_in[19];
    const float* c_b2   = (const float*)d_in[20];
    const float* c_W3   = (const float*)d_in[21];
    const float* c_b3   = (const float*)d_in[22];
    float* out = (float*)d_out;

    cudaFuncSetAttribute(k_sp,   cudaFuncAttributeMaxDynamicSharedMemorySize, SP_SMEM);
    cudaFuncSetAttribute(k_join, cudaFuncAttributeMaxDynamicSharedMemorySize, JOIN_SMEM);
    cudaFuncSetAttribute(k_vp,   cudaFuncAttributeMaxDynamicSharedMemorySize, VP_SMEM);
    cudaFuncSetAttribute(k_ctrl, cudaFuncAttributeMaxDynamicSharedMemorySize, CTRL_SMEM);

    cudaStream_t s1;
    cudaStreamCreateWithFlags(&s1, cudaStreamNonBlocking);
    cudaEvent_t evFork, evPis, evPrep, evSide;
    cudaEventCreateWithFlags(&evFork, cudaEventDisableTiming);
    cudaEventCreateWithFlags(&evPis,  cudaEventDisableTiming);
    cudaEventCreateWithFlags(&evPrep, cudaEventDisableTiming);
    cudaEventCreateWithFlags(&evSide, cudaEventDisableTiming);

    // fork side stream from the capture stream
    cudaEventRecord(evFork, 0);
    cudaStreamWaitEvent(s1, evFork, 0);

    // ---- side stream (s1): p_i split -> routing -> vp
    k_pis<<<8192, 256, 0, s1>>>(p_i);
    cudaEventRecord(evPis, s1);
    k_reset<<<1, 32, 0, s1>>>();
    k_count<<<B_TOT / 256, 256, 0, s1>>>(cmd);
    k_seg<<<1, 32, 0, s1>>>();
    k_scatter<<<B_TOT / 256, 256, 0, s1>>>(cmd);

    // ---- main stream: weights -> speed MLP -> join
    k_prep<<<4800, 256>>>(sp_W2, sp_W3, vp_W1, vp_W2, join_W, c_W1, c_W2);
    cudaEventRecord(evPrep, 0);
    cudaStreamWaitEvent(s1, evPrep, 0);          // vp needs prepped weights
    k_vp<<<B_TOT / 128, 512, VP_SMEM, s1>>>(vp_b1, vp_b2, vp_W3, vp_b3, out);
    cudaEventRecord(evSide, s1);

    k_sp<<<B_TOT / 128, 512, SP_SMEM>>>(speed, sp_W1, sp_b1, sp_b2, sp_b3);
    cudaStreamWaitEvent(0, evPis, 0);            // join needs p_i split
    dim3 jg(4, B_TOT / 128);
    k_join<<<jg, 512, JOIN_SMEM>>>(join_b);

    cudaStreamWaitEvent(0, evSide, 0);           // ctrl needs routing + (vp done on s1)
    k_ctrl<<<B_TOT / 64 + 8, 512, CTRL_SMEM>>>(c_b1, c_b2, c_W3, c_b3, out);
}

// round 14
// speedup vs baseline: 2.5391x; 1.5275x over previous
#include <cuda_runtime.h>
#include <cuda_fp16.h>

#define B_TOT 32768
typedef unsigned int uint;

// ===================== device scratch (tiled+swizzled fp16 planes, single precision pass) =====================
__device__ __half g_spW2T[2*8192],  g_spW3T[2*8192];
__device__ __half g_vpW1T[8*8192],  g_vpW2T[2*8192];
__device__ __half g_joinT[(size_t)2*10*16384];
__device__ __half g_cW1T[(size_t)4*8*16384];
__device__ __half g_cW2T[(size_t)4*4*16384];
__device__ __half g_pi[(size_t)256*8*8192];   // [mb][ch][128x64 tile]
__device__ __half g_v [(size_t)256*2*8192];
__device__ __half g_jo[(size_t)256*8*8192];
__device__ int g_idx[B_TOT + 512];
__device__ int g_cnt[4], g_fill[4], g_seg[5];

// ===================== primitives =====================
__device__ __forceinline__ uint smem_u32(const void* p) {
    uint a;
    asm("{ .reg .u64 t; cvta.to.shared.u64 t, %1; cvt.u32.u64 %0, t; }" : "=r"(a) : "l"(p));
    return a;
}
__device__ __forceinline__ uint swzoff(int r, int cbyte) {
    return (uint)(r * 128 + (cbyte ^ ((r & 7) << 4)));
}
__device__ __forceinline__ void ldm4(uint f[4], uint a) {
    asm volatile("ldmatrix.sync.aligned.m8n8.x4.shared.b16 {%0,%1,%2,%3}, [%4];"
        : "=r"(f[0]), "=r"(f[1]), "=r"(f[2]), "=r"(f[3]) : "r"(a));
}
__device__ __forceinline__ void mma_fp16(float c[4], const uint a[4], const uint b[2]) {
    asm volatile(
        "mma.sync.aligned.m16n8k16.row.col.f32.f16.f16.f32 "
        "{%0,%1,%2,%3}, {%4,%5,%6,%7}, {%8,%9}, {%0,%1,%2,%3};"
        : "+f"(c[0]), "+f"(c[1]), "+f"(c[2]), "+f"(c[3])
        : "r"(a[0]), "r"(a[1]), "r"(a[2]), "r"(a[3]), "r"(b[0]), "r"(b[1]));
}
__device__ __forceinline__ uint pack2h(float a, float b) {
    __half h0 = __float2half_rn(a), h1 = __float2half_rn(b);
    return (uint)__half_as_ushort(h0) | ((uint)__half_as_ushort(h1) << 16);
}
__device__ __forceinline__ void cpa16(uint d, const void* s) {
    asm volatile("cp.async.cg.shared.global [%0], [%1], 16;" :: "r"(d), "l"(s));
}
#define CPA_COMMIT() asm volatile("cp.async.commit_group;" ::: "memory")
#define CPA_WAIT0()  asm volatile("cp.async.wait_group 0;" ::: "memory")
#define CPA_WAIT1()  asm volatile("cp.async.wait_group 1;" ::: "memory")

__device__ __forceinline__ void bulk_g2s(uint dst, const void* src, uint bytes, uint mbar) {
    asm volatile("cp.async.bulk.shared::cluster.global.mbarrier::complete_tx::bytes [%0], [%1], %2, [%3];"
        :: "r"(dst), "l"(src), "r"(bytes), "r"(mbar) : "memory");
}
#define MBAR_INIT(a, c) asm volatile("mbarrier.init.shared.b64 [%0], %1;" :: "r"(a), "r"(c) : "memory")
#define MBAR_EXPECT(a, tx) asm volatile("mbarrier.arrive.expect_tx.shared.b64 _, [%0], %1;" :: "r"(a), "r"(tx) : "memory")
#define MBAR_ARRIVE(a) asm volatile("mbarrier.arrive.shared.b64 _, [%0];" :: "r"(a) : "memory")
#define MBAR_WAIT(mbar_a, par) do { \
    uint _m = (mbar_a); uint _p = (uint)(par); uint _d; \
    asm volatile("{ .reg .pred p; mbarrier.try_wait.parity.acquire.cta.shared::cta.b64 p, [%1], %2; selp.b32 %0, 1, 0, p; }" \
        : "=r"(_d) : "r"(_m), "r"(_p) : "memory"); \
    if (!_d) { \
        asm volatile("{ .reg .pred P1;\nWL_%=:\n mbarrier.try_wait.parity.acquire.cta.shared::cta.b64 P1, [%0], %1, 0x989680;\n @P1 bra.uni WD_%=;\n bra.uni WL_%=;\nWD_%=:\n}" \
            :: "r"(_m), "r"(_p) : "memory"); \
    } \
} while (0)

// ===================== gemm: warp tile 16 x (NT*8), SINGLE fp16 pass =====================
template <int NT>
__device__ __forceinline__ void gemm1(float (&acc)[NT][4], uint As, uint Bs, int wm, int wn)
{
    const int lane = threadIdx.x & 31;
    const int ra = (lane & 15) + wm;
    const uint At = As + (uint)(ra & 127) * 128u;
    const uint ax = (uint)((ra & 7) << 4);
    const int ua = lane >> 4;
    const int rb = (lane & 7) + ((lane >> 4) << 3) + wn;
    const uint Bt = Bs + (uint)rb * 128u;
    const uint bx2 = (uint)((rb & 7) << 4);
    const int ub = (lane >> 3) & 1;
#pragma unroll
    for (int s = 0; s < 4; s++) {
        uint a4[4];
        ldm4(a4, At + (((uint)((s * 2 + ua) * 16)) ^ ax));
        uint cbb = ((uint)((s * 2 + ub) * 16)) ^ bx2;
#pragma unroll
        for (int p = 0; p < NT / 2; p++) {
            uint b4[4];
            ldm4(b4, Bt + (uint)(p * 2048) + cbb);
            mma_fp16(acc[2*p],   a4, b4);
            mma_fp16(acc[2*p+1], a4, b4 + 2);
        }
    }
}
template <int NT>
__device__ __forceinline__ void acc_zero(float (&acc)[NT][4]) {
#pragma unroll
    for (int n = 0; n < NT; n++)
#pragma unroll
    for (int q = 0; q < 4; q++) acc[n][q] = 0.f;
}

// ===================== epilogue: bias(+relu) -> fp16 -> swizzled tiles =====================
template <int NT>
__device__ __forceinline__ void epi1(const float (&acc)[NT][4],
    char* dst, const float* bias, int cb, size_t tsCh, int wm, int wn, bool relu)
{
    int lane = threadIdx.x & 31;
    int rr = wm + (lane >> 2), cc = wn + (lane & 3) * 2;
#pragma unroll
    for (int nt = 0; nt < NT; nt++)
#pragma unroll
    for (int h = 0; h < 2; h++) {
        int r = rr + h * 8, c = cc + nt * 8;
        float v0 = acc[nt][h*2]   + __ldg(bias + cb + c);
        float v1 = acc[nt][h*2+1] + __ldg(bias + cb + c + 1);
        if (relu) { v0 = fmaxf(v0, 0.f); v1 = fmaxf(v1, 0.f); }
        *(uint*)(dst + (size_t)(c >> 6) * tsCh + swzoff(r & 127, (c & 63) * 2)) = pack2h(v0, v1);
    }
}

// ===================== weight prep =====================
__global__ void k_prep(const float* spW2, const float* spW3, const float* vpW1, const float* vpW2,
                       const float* jW, const float* cW1, const float* cW2) {
    int i = blockIdx.x * 256 + threadIdx.x;
    float x; char* base; size_t off;
    if (i < 16384) {
        int l = i; int n = l >> 7, k = l & 127; x = spW2[k*128+n];
        base = (char*)g_spW2T; off = (size_t)(k >> 6) * 16384 + swzoff(n, (k & 63) * 2);
    } else if (i < 32768) {
        int l = i - 16384; int n = l >> 7, k = l & 127; x = spW3[k*128+n];
        base = (char*)g_spW3T; off = (size_t)(k >> 6) * 16384 + swzoff(n, (k & 63) * 2);
    } else if (i < 98304) {
        int l = i - 32768; int n = l >> 9, k = l & 511; x = vpW1[k*128+n];
        base = (char*)g_vpW1T; off = (size_t)(k >> 6) * 16384 + swzoff(n, (k & 63) * 2);
    } else if (i < 114688) {
        int l = i - 98304; int n = l >> 7, k = l & 127; x = vpW2[k*128+n];
        base = (char*)g_vpW2T; off = (size_t)(k >> 6) * 16384 + swzoff(n, (k & 63) * 2);
    } else if (i < 442368) {
        int l = i - 114688; int n = l / 640, k = l - n * 640; x = jW[(size_t)k*512+n];
        int nb = n >> 8, nl = n & 255;
        base = (char*)g_joinT; off = ((size_t)nb * 10 + (k >> 6)) * 32768 + swzoff(nl, (k & 63) * 2);
    } else if (i < 966656) {
        int l = i - 442368; int e = l >> 17, rm = l & 131071; int n = rm >> 9, k = rm & 511;
        x = cW1[(size_t)e*131072 + (size_t)k*256 + n];
        base = (char*)g_cW1T; off = ((size_t)e * 8 + (k >> 6)) * 32768 + swzoff(n, (k & 63) * 2);
    } else if (i < 1228800) {
        int l = i - 966656; int e = l >> 16, rm = l & 65535; int n = rm >> 8, k = rm & 255;
        x = cW2[(size_t)e*65536 + (size_t)k*256 + n];
        base = (char*)g_cW2T; off = ((size_t)e * 4 + (k >> 6)) * 32768 + swzoff(n, (k & 63) * 2);
    } else return;
    *(__half*)(base + off) = __float2half_rn(x);
}

__global__ void k_pis(const float* __restrict__ p) {
    int idx = blockIdx.x * 256 + threadIdx.x;
    int m = idx >> 6, u = idx & 63;
    int ch = u >> 3, ui = u & 7;
    const float* s = p + (size_t)m * 512 + u * 8;
    float4 f0 = *(const float4*)s;
    float4 f1 = *(const float4*)(s + 4);
    uint w0 = pack2h(f0.x, f0.y), w1 = pack2h(f0.z, f0.w);
    uint w2 = pack2h(f1.x, f1.y), w3 = pack2h(f1.z, f1.w);
    size_t off = ((size_t)(m >> 7) * 8 + ch) * 16384 + swzoff(m & 127, ui * 16);
    *(uint4*)((char*)g_pi + off) = make_uint4(w0, w1, w2, w3);
}

// ===================== routing =====================
__global__ void k_reset() { if (threadIdx.x < 4) { g_cnt[threadIdx.x] = 0; g_fill[threadIdx.x] = 0; } }
__global__ void k_count(const int* __restrict__ cmd) {
    __shared__ int h[4];
    int tid = threadIdx.x;
    if (tid < 4) h[tid] = 0;
    __syncthreads();
    int i = blockIdx.x * 256 + tid;
    if (i < B_TOT) atomicAdd(&h[cmd[i] & 3], 1);
    __syncthreads();
    if (tid < 4) atomicAdd(&g_cnt[tid], h[tid]);
}
__global__ void k_seg() {
    if (threadIdx.x == 0) {
        int off = 0;
        for (int e = 0; e < 4; e++) { g_seg[e] = off; off += (g_cnt[e] + 127) & ~127; }
        g_seg[4] = off;
    }
}
__global__ void k_scatter(const int* __restrict__ cmd) {
    __shared__ int h[4], base[4];
    int tid = threadIdx.x;
    if (tid < 4) h[tid] = 0;
    __syncthreads();
    int i = blockIdx.x * 256 + tid;
    int e = 0, loc = 0;
    if (i < B_TOT) { e = cmd[i] & 3; loc = atomicAdd(&h[e], 1); }
    __syncthreads();
    if (tid < 4) base[tid] = atomicAdd(&g_fill[tid], h[tid]);
    __syncthreads();
    if (i < B_TOT) g_idx[g_seg[e] + base[e] + loc] = i;
}

// ===================== k_sp: 1 -> 128 -> 128 -> 128 =====================
// A1 2ch @0 (32KB), A2 @32768 (32KB), W @65536 (32KB), ss @98304, mbar @98816
#define SP_SMEM 98848

__global__ void __launch_bounds__(512, 2) k_sp(
    const float* __restrict__ speed,
    const float* __restrict__ W1, const float* __restrict__ b1,
    const float* __restrict__ b2, const float* __restrict__ b3)
{
    extern __shared__ char sm[];
    uint sb = smem_u32(sm);
    int tid = threadIdx.x, wid = tid >> 5;
    int wm = (wid & 7) * 16, wn = (wid >> 3) * 64;
    size_t m0 = (size_t)blockIdx.x * 128;
    uint mbar = sb + 98816;
    float* ss = (float*)(sm + 98304);
    if (tid == 0) MBAR_INIT(mbar, 1);
    if (tid < 128) ss[tid] = speed[m0 + tid];
    __syncthreads();
    if (tid == 0) { MBAR_EXPECT(mbar, 32768); bulk_g2s(sb + 65536, g_spW2T, 32768, mbar); }

    for (int u = tid; u < 8192; u += 512) {
        int r = u >> 6, c = (u & 63) * 2;
        float sv = ss[r];
        float v0 = fmaxf(fmaf(sv, __ldg(W1 + c),     __ldg(b1 + c)),     0.f);
        float v1 = fmaxf(fmaf(sv, __ldg(W1 + c + 1), __ldg(b1 + c + 1)), 0.f);
        *(uint*)(sm + (uint)(c >> 6) * 16384 + swzoff(r, (c & 63) * 2)) = pack2h(v0, v1);
    }
    __syncthreads();
    MBAR_WAIT(mbar, 0);

    float acc[8][4];
    acc_zero(acc);
    gemm1<8>(acc, sb + 0,     sb + 65536,         wm, wn);
    gemm1<8>(acc, sb + 16384, sb + 65536 + 16384, wm, wn);
    __syncthreads();
    if (tid == 0) { MBAR_EXPECT(mbar, 32768); bulk_g2s(sb + 65536, g_spW3T, 32768, mbar); }
    epi1<8>(acc, sm + 32768, b2, 0, 16384, wm, wn, true);
    __syncthreads();
    MBAR_WAIT(mbar, 1);

    acc_zero(acc);
    gemm1<8>(acc, sb + 32768, sb + 65536,         wm, wn);
    gemm1<8>(acc, sb + 49152, sb + 65536 + 16384, wm, wn);
    epi1<8>(acc, (char*)g_v + (size_t)blockIdx.x * 2 * 16384, b3, 0, 16384, wm, wn, false);
}

// ===================== k_join: M=128, N=128, 3-stage 32KB pipeline, 2 CTAs/SM =====================
#define JSTG 32768u
#define JOIN_SMEM 98368

__global__ void __launch_bounds__(512, 2) k_join(const float* __restrict__ jb)
{
    extern __shared__ char sm[];
    uint sb = smem_u32(sm);
    int tid = threadIdx.x, wid = tid >> 5;
    int wm = (wid & 7) * 16, wn = (wid >> 3) * 64;
    int nb = blockIdx.x;
    int bm = blockIdx.y;
    int N0 = nb * 128;
    if (tid == 0) {
#pragma unroll
        for (int s = 0; s < 3; s++) {
            MBAR_INIT(sb + 98304 + s * 8, 1);
            MBAR_INIT(sb + 98328 + s * 8, 16);
        }
    }
    __syncthreads();

#define J_ISSUE(c, s) do { \
    uint d = sb + (uint)(s) * JSTG; uint m_ = sb + 98304 + (uint)(s) * 8; \
    MBAR_EXPECT(m_, 32768); \
    if ((c) < 8) bulk_g2s(d, (char*)g_pi + ((size_t)bm * 8 + (c)) * 16384, 16384, m_); \
    else         bulk_g2s(d, (char*)g_v  + ((size_t)bm * 2 + ((c)-8)) * 16384, 16384, m_); \
    bulk_g2s(d + 16384, \
             (char*)g_joinT + ((size_t)(N0 >> 8) * 10 + (c)) * 32768 + (size_t)(N0 & 255) * 128, \
             16384, m_); \
} while (0)

    float acc[8][4];
    acc_zero(acc);
    if (tid == 0) { J_ISSUE(0, 0); J_ISSUE(1, 1); J_ISSUE(2, 2); }
#pragma unroll
    for (int c = 0; c < 10; c++) {
        const int s = c % 3;
        MBAR_WAIT(sb + 98304 + s * 8, (c / 3) & 1);
        gemm1<8>(acc, sb + s*JSTG, sb + s*JSTG + 16384, wm, wn);
        if ((tid & 31) == 0) MBAR_ARRIVE(sb + 98328 + s * 8);
        if (tid == 0 && c + 3 < 10) {
            MBAR_WAIT(sb + 98328 + s * 8, (c / 3) & 1);
            J_ISSUE(c + 3, s);
        }
    }
#undef J_ISSUE
    epi1<8>(acc, (char*)g_jo + ((size_t)bm * 8 + (N0 >> 6)) * 16384,
            jb, N0, 16384, wm, wn, false);
}

// ===================== k_vp: 512 -> 128 -> 128 -> 1 (2-stage 32KB, 2 CTAs/SM) =====================
// stages @0,@32768. After L1: A2 @0 (32KB), W2 @32768 (32KB). sv @65536, full @66048, empty @66064
#define VSTG 32768u
#define VP_SMEM 66112

__global__ void __launch_bounds__(512, 2) k_vp(
    const float* __restrict__ b1, const float* __restrict__ b2,
    const float* __restrict__ W3, const float* __restrict__ b3,
    float* __restrict__ out)
{
    extern __shared__ char sm[];
    uint sb = smem_u32(sm);
    int tid = threadIdx.x, wid = tid >> 5;
    int wm = (wid & 7) * 16, wn = (wid >> 3) * 64;
    int bx = blockIdx.x;
    size_t m0 = (size_t)bx * 128;
    float* sv = (float*)(sm + 65536);
    if (tid == 0) {
#pragma unroll
        for (int s = 0; s < 2; s++) {
            MBAR_INIT(sb + 66048 + s * 8, 1);
            MBAR_INIT(sb + 66064 + s * 8, 16);
        }
    }
    if (tid < 128) sv[tid] = 0.f;
    __syncthreads();

#define V_ISSUE(c, s) do { \
    uint d = sb + (uint)(s) * VSTG; uint m_ = sb + 66048 + (uint)(s) * 8; \
    MBAR_EXPECT(m_, 32768); \
    bulk_g2s(d,         (char*)g_pi + ((size_t)bx * 8 + (c)) * 16384, 16384, m_); \
    bulk_g2s(d + 16384, (char*)g_vpW1T + (size_t)(c) * 16384, 16384, m_); \
} while (0)

    float acc[8][4];
    acc_zero(acc);
    if (tid == 0) { V_ISSUE(0, 0); V_ISSUE(1, 1); }
#pragma unroll
    for (int c = 0; c < 8; c++) {
        const int s = c & 1;
        MBAR_WAIT(sb + 66048 + s * 8, (c >> 1) & 1);
        gemm1<8>(acc, sb + s*VSTG, sb + s*VSTG + 16384, wm, wn);
        if ((tid & 31) == 0) MBAR_ARRIVE(sb + 66064 + s * 8);
        if (tid == 0 && c + 2 < 8) {
            MBAR_WAIT(sb + 66064 + s * 8, (c >> 1) & 1);
            V_ISSUE(c + 2, s);
        }
    }
#undef V_ISSUE
    __syncthreads();    // all warps done with both stages
    // full[0] completed 4x -> next parity 0
    if (tid == 0) { MBAR_EXPECT(sb + 66048, 32768); bulk_g2s(sb + 32768, g_vpW2T, 32768, sb + 66048); }
    epi1<8>(acc, sm, b1, 0, 16384, wm, wn, true);
    __syncthreads();
    MBAR_WAIT(sb + 66048, 0);

    acc_zero(acc);
    gemm1<8>(acc, sb + 0,     sb + 32768,         wm, wn);
    gemm1<8>(acc, sb + 16384, sb + 32768 + 16384, wm, wn);

    {
        int lane = tid & 31;
#pragma unroll
        for (int h = 0; h < 2; h++) {
            int r = wm + h * 8 + (lane >> 2);
            float s = 0.f;
#pragma unroll
            for (int nt = 0; nt < 8; nt++) {
                int c = wn + nt * 8 + (lane & 3) * 2;
                float v0 = fmaxf(acc[nt][h*2]   + __ldg(b2 + c),     0.f);
                float v1 = fmaxf(acc[nt][h*2+1] + __ldg(b2 + c + 1), 0.f);
                s += v0 * __ldg(W3 + c) + v1 * __ldg(W3 + c + 1);
            }
            s += __shfl_xor_sync(0xFFFFFFFF, s, 1);
            s += __shfl_xor_sync(0xFFFFFFFF, s, 2);
            if ((lane & 3) == 0) atomicAdd(&sv[r], s);
        }
    }
    __syncthreads();
    if (tid < 128) out[m0 + tid] = sv[tid] + __ldg(b3);
}

// ===================== k_ctrl: routed 512 -> 256 -> 256 -> 3 (M=64, N=256, 2 CTAs/SM) =====================
// L1 stages: s*40960: A gather 8KB @0, B 32KB @8192. A2 overlay @0 (4x8KB). L2 B @40960 (32KB).
// ridx @81920, sact @82176, mb @82944, me @82960
#define CSTG 40960u
#define CTRL_SMEM 82976

__global__ void __launch_bounds__(512, 2) k_ctrl(
    const float* __restrict__ b1, const float* __restrict__ b2,
    const float* __restrict__ W3, const float* __restrict__ b3,
    float* __restrict__ out)
{
    int p0 = blockIdx.x * 64;
    int s1 = g_seg[1], s2 = g_seg[2], s3 = g_seg[3], s4 = g_seg[4];
    if (p0 >= s4) return;
    int e, segb;
    if (p0 < s1)      { e = 0; segb = 0; }
    else if (p0 < s2) { e = 1; segb = s1; }
    else if (p0 < s3) { e = 2; segb = s2; }
    else              { e = 3; segb = s3; }
    int cnt = g_cnt[e];

    extern __shared__ char sm[];
    uint sb = smem_u32(sm);
    int tid = threadIdx.x, wid = tid >> 5;
    int wm = (wid & 3) * 16, wn = (wid >> 2) * 64;
    int* ridx = (int*)(sm + 81920);
    float* sact = (float*)(sm + 82176);
    uint mb[2] = {sb + 82944, sb + 82952};
    uint me0 = sb + 82960;
    if (tid == 0) {
        MBAR_INIT(mb[0], 1); MBAR_INIT(mb[1], 1);
        MBAR_INIT(me0, 16);
    }
    if (tid < 64) {
        int local = p0 - segb + tid;
        ridx[tid] = (local < cnt) ? g_idx[p0 + tid] : -1;
    }
    if (tid < 192) sact[tid] = 0.f;
    __syncthreads();

    const float* b1e = b1 + e * 256;
    const float* b2e = b2 + e * 256;
    const float* w3e = W3 + e * 768;

#define C1_ISSUE(c, s) do { \
    uint d = sb + (uint)(s) * CSTG; \
    if (tid == 0) { \
        MBAR_EXPECT(mb[s], 32768); \
        bulk_g2s(d + 8192, (char*)g_cW1T + ((size_t)e * 8 + (c)) * 32768, 32768, mb[s]); \
    } \
    { \
        int rl = tid >> 3, un = tid & 7; \
        int src = ridx[rl]; if (src < 0) src = 0; \
        size_t so = ((size_t)(src >> 7) * 8 + (c)) * 16384 \
                  + (size_t)((src & 127) * 128 + ((un * 16) ^ ((src & 7) << 4))); \
        cpa16(d + swzoff(rl, un * 16), (char*)g_jo + so); \
    } \
    CPA_COMMIT(); \
} while (0)

    float acc[8][4];
    acc_zero(acc);
    C1_ISSUE(0, 0); C1_ISSUE(1, 1);
    int par[2] = {0, 0};
    for (int c = 0; c < 8; c++) {
        int s = c & 1;
        if (c < 7) CPA_WAIT1(); else CPA_WAIT0();
        MBAR_WAIT(mb[s], par[s]); par[s] ^= 1;
        __syncthreads();
        gemm1<8>(acc, sb + s*CSTG, sb + s*CSTG + 8192, wm, wn);
        __syncthreads();
        if (c + 2 < 8) C1_ISSUE(c + 2, s);
    }
#undef C1_ISSUE

    // h1 -> A2 smem tiles (4 k-chunks x 8KB), overlaying drained stages
    epi1<8>(acc, sm, b1e, 0, 8192, wm, wn, true);
    __syncthreads();

    // L2: A2 smem, B single-buffered bulk @40960 (alternating full mbars, one empty)
#define C2_ISSUE(c, s) do { \
    MBAR_EXPECT(mb[s], 32768); \
    bulk_g2s(sb + 40960u, (char*)g_cW2T + ((size_t)e * 4 + (c)) * 32768, 32768, mb[s]); \
} while (0)
    acc_zero(acc);
    if (tid == 0) C2_ISSUE(0, 0);
#pragma unroll
    for (int c = 0; c < 4; c++) {
        const int s = c & 1;
        MBAR_WAIT(mb[s], par[s]); par[s] ^= 1;
        gemm1<8>(acc, sb + (uint)c * 8192u, sb + 40960u, wm, wn);
        if ((tid & 31) == 0) MBAR_ARRIVE(me0);
        if (tid == 0 && c + 1 < 4) {
            MBAR_WAIT(me0, c & 1);
            C2_ISSUE(c + 1, (c + 1) & 1);
        }
    }
#undef C2_ISSUE

    {
        int lane = tid & 31;
#pragma unroll
        for (int h = 0; h < 2; h++) {
            int r = wm + h * 8 + (lane >> 2);
            float a0 = 0.f, a1 = 0.f, a2 = 0.f;
#pragma unroll
            for (int nt = 0; nt < 8; nt++) {
                int c = wn + nt * 8 + (lane & 3) * 2;
                float v0 = fmaxf(acc[nt][h*2]   + __ldg(b2e + c),     0.f);
                float v1 = fmaxf(acc[nt][h*2+1] + __ldg(b2e + c + 1), 0.f);
                a0 += v0 * __ldg(w3e + c*3 + 0) + v1 * __ldg(w3e + (c+1)*3 + 0);
                a1 += v0 * __ldg(w3e + c*3 + 1) + v1 * __ldg(w3e + (c+1)*3 + 1);
                a2 += v0 * __ldg(w3e + c*3 + 2) + v1 * __ldg(w3e + (c+1)*3 + 2);
            }
            a0 += __shfl_xor_sync(0xFFFFFFFF, a0, 1);
            a0 += __shfl_xor_sync(0xFFFFFFFF, a0, 2);
            a1 += __shfl_xor_sync(0xFFFFFFFF, a1, 1);
            a1 += __shfl_xor_sync(0xFFFFFFFF, a1, 2);
            a2 += __shfl_xor_sync(0xFFFFFFFF, a2, 1);
            a2 += __shfl_xor_sync(0xFFFFFFFF, a2, 2);
            if ((lane & 3) == 0) {
                atomicAdd(&sact[r * 3 + 0], a0);
                atomicAdd(&sact[r * 3 + 1], a1);
                atomicAdd(&sact[r * 3 + 2], a2);
            }
        }
    }
    __syncthreads();
    if (tid < 64) {
        int src = ridx[tid];
        if (src >= 0) {
            out[(size_t)B_TOT + (size_t)src * 3 + 0] = sact[tid * 3 + 0] + __ldg(b3 + e * 3 + 0);
            out[(size_t)B_TOT + (size_t)src * 3 + 1] = sact[tid * 3 + 1] + __ldg(b3 + e * 3 + 1);
            out[(size_t)B_TOT + (size_t)src * 3 + 2] = sact[tid * 3 + 2] + __ldg(b3 + e * 3 + 2);
        }
    }
}

// ===================== launcher (multi-stream fork/join) =====================
extern "C" void kernel_launch(void* const* d_in, const int* in_sizes, int n_in,
                              void* d_out, int out_size)
{
    const float* p_i    = (const float*)d_in[0];
    const float* speed  = (const float*)d_in[1];
    const int*   cmd    = (const int*)d_in[2];
    const float* sp_W1  = (const float*)d_in[3];
    const float* sp_b1  = (const float*)d_in[4];
    const float* sp_W2  = (const float*)d_in[5];
    const float* sp_b2  = (const float*)d_in[6];
    const float* sp_W3  = (const float*)d_in[7];
    const float* sp_b3  = (const float*)d_in[8];
    const float* vp_W1  = (const float*)d_in[9];
    const float* vp_b1  = (const float*)d_in[10];
    const float* vp_W2  = (const float*)d_in[11];
    const float* vp_b2  = (const float*)d_in[12];
    const float* vp_W3  = (const float*)d_in[13];
    const float* vp_b3  = (const float*)d_in[14];
    const float* join_W = (const float*)d_in[15];
    const float* join_b = (const float*)d_in[16];
    const float* c_W1   = (const float*)d_in[17];
    const float* c_b1   = (const float*)d_in[18];
    const float* c_W2   = (const float*)d_in[19];
    const float* c_b2   = (const float*)d_in[20];
    const float* c_W3   = (const float*)d_in[21];
    const float* c_b3   = (const float*)d_in[22];
    float* out = (float*)d_out;

    cudaFuncSetAttribute(k_sp,   cudaFuncAttributeMaxDynamicSharedMemorySize, SP_SMEM);
    cudaFuncSetAttribute(k_join, cudaFuncAttributeMaxDynamicSharedMemorySize, JOIN_SMEM);
    cudaFuncSetAttribute(k_vp,   cudaFuncAttributeMaxDynamicSharedMemorySize, VP_SMEM);
    cudaFuncSetAttribute(k_ctrl, cudaFuncAttributeMaxDynamicSharedMemorySize, CTRL_SMEM);

    cudaStream_t s1;
    cudaStreamCreateWithFlags(&s1, cudaStreamNonBlocking);
    cudaEvent_t evFork, evPis, evPrep, evSide;
    cudaEventCreateWithFlags(&evFork, cudaEventDisableTiming);
    cudaEventCreateWithFlags(&evPis,  cudaEventDisableTiming);
    cudaEventCreateWithFlags(&evPrep, cudaEventDisableTiming);
    cudaEventCreateWithFlags(&evSide, cudaEventDisableTiming);

    cudaEventRecord(evFork, 0);
    cudaStreamWaitEvent(s1, evFork, 0);

    // side stream: p_i split -> routing -> vp
    k_pis<<<8192, 256, 0, s1>>>(p_i);
    cudaEventRecord(evPis, s1);
    k_reset<<<1, 32, 0, s1>>>();
    k_count<<<B_TOT / 256, 256, 0, s1>>>(cmd);
    k_seg<<<1, 32, 0, s1>>>();
    k_scatter<<<B_TOT / 256, 256, 0, s1>>>(cmd);

    // main stream: weights -> speed MLP -> join
    k_prep<<<4800, 256>>>(sp_W2, sp_W3, vp_W1, vp_W2, join_W, c_W1, c_W2);
    cudaEventRecord(evPrep, 0);
    cudaStreamWaitEvent(s1, evPrep, 0);
    k_vp<<<B_TOT / 128, 512, VP_SMEM, s1>>>(vp_b1, vp_b2, vp_W3, vp_b3, out);
    cudaEventRecord(evSide, s1);

    k_sp<<<B_TOT / 128, 512, SP_SMEM>>>(speed, sp_W1, sp_b1, sp_b2, sp_b3);
    cudaStreamWaitEvent(0, evPis, 0);
    dim3 jg(4, B_TOT / 128);
    k_join<<<jg, 512, JOIN_SMEM>>>(join_b);

    cudaStreamWaitEvent(0, evSide, 0);
    k_ctrl<<<B_TOT / 64 + 8, 512, CTRL_SMEM>>>(c_b1, c_b2, c_W3, c_b3, out);
}